// round 9
// baseline (speedup 1.0000x reference)
#include <cuda_runtime.h>
#include <cuda_bf16.h>
#include <cstdint>
#include <math.h>

// ---------------- problem constants ----------------
#define BN    16
#define CC    256
#define HIDN  512
#define NGRP  8
#define CGg   64
#define HWN   3136
#define CU    64
#define NTOT  (BN*HWN)
#define LRc   0.01f
#define SPLITK 49
#define PBZ   2           // (HWN/32)/SPLITK

typedef __nv_bfloat16 bft;

// ---------------- device scratch ----------------
__device__ float g_w1[HIDN*CC];
__device__ float g_w2[CC*HIDN];
__device__ float g_gamma[HIDN];
__device__ float g_beta[HIDN];

__device__ bft g_w1b [HIDN*CC];
__device__ bft g_w2b [CC*HIDN];
__device__ bft g_w2tb[HIDN*CC];
__device__ bft g_rw1b [CU*CC];
__device__ bft g_rw1tb[CC*CU];
__device__ bft g_rw2b [CC*CU];
__device__ bft g_rw2tb[CU*CC];

__device__ bft g_h1 [(size_t)BN*HIDN*HWN];
__device__ bft g_dg [(size_t)BN*HIDN*HWN];   // holds dgn after dg-GEMM
__device__ bft g_y  [(size_t)BN*CC*HWN];
__device__ bft g_drec[(size_t)BN*CC*HWN];
__device__ bft g_dy [(size_t)BN*CC*HWN];
__device__ bft g_pre [(size_t)BN*CU*HWN];
__device__ bft g_dpre[(size_t)BN*CU*HWN];
__device__ bft g_xb [(size_t)BN*CC*HWN];

__device__ float g_mu[BN*NGRP];
__device__ float g_rstd[BN*NGRP];
__device__ float2 g_gnp[BN*NGRP*49];
__device__ float2 g_rowp[(size_t)BN*HIDN*49];
__device__ float g_part[BN*HIDN*2];
__device__ float g_s1[BN*NGRP], g_s2[BN*NGRP];
__device__ float g_dgamma[HIDN], g_dbeta[HIDN];
__device__ float g_cm[CC], g_cA[CC], g_cB[CC];
__device__ float g_split[(size_t)SPLITK*HIDN*CC];
__device__ float g_dW1[HIDN*CC], g_dW2[CC*HIDN];
__device__ float g_maskf[2*NTOT];
__device__ float g_dscale[2];
__device__ float g_pooled[BN*CC];
__device__ float g_gate[BN];
__device__ int   g_flagF, g_flagW;

// ---------------- math helpers ----------------
__device__ __forceinline__ float geluf(float x){
    return 0.5f*x*(1.0f + erff(x*0.70710678118654752440f));
}
__device__ __forceinline__ float gelu_grad(float x){
    float cdf = 0.5f*(1.0f + erff(x*0.70710678118654752440f));
    float pdf = 0.3989422804014327f*__expf(-0.5f*x*x);
    return cdf + x*pdf;
}
__device__ __forceinline__ void block_reduce2(float& a, float& b){
    __shared__ float sa[256], sb[256];
    int t = threadIdx.x;
    sa[t]=a; sb[t]=b; __syncthreads();
    for (int s=128; s>0; s>>=1){
        if (t<s){ sa[t]+=sa[t+s]; sb[t]+=sb[t+s]; }
        __syncthreads();
    }
    a=sa[0]; b=sb[0];
}
__device__ __forceinline__ unsigned pack_bf2(float a, float b){
    __nv_bfloat162 p = __floats2bfloat162_rn(a, b);
    return *(unsigned*)&p;
}
__device__ __forceinline__ unsigned smem_u32(const void* p){
    return (unsigned)__cvta_generic_to_shared(p);
}
__device__ __forceinline__ void unpack8(uint4 u, float* v){
    __nv_bfloat162 p;
    p=*(__nv_bfloat162*)&u.x; v[0]=__low2float(p); v[1]=__high2float(p);
    p=*(__nv_bfloat162*)&u.y; v[2]=__low2float(p); v[3]=__high2float(p);
    p=*(__nv_bfloat162*)&u.z; v[4]=__low2float(p); v[5]=__high2float(p);
    p=*(__nv_bfloat162*)&u.w; v[6]=__low2float(p); v[7]=__high2float(p);
}
__device__ __forceinline__ uint4 pack8(const float* v){
    uint4 u;
    u.x=pack_bf2(v[0],v[1]); u.y=pack_bf2(v[2],v[3]);
    u.z=pack_bf2(v[4],v[5]); u.w=pack_bf2(v[6],v[7]);
    return u;
}
__device__ __forceinline__ float2 ldbf2(const bft* p){
    __nv_bfloat162 v = *(const __nv_bfloat162*)p;
    return make_float2(__low2float(v), __high2float(v));
}

// ---------------- init / mask handling ----------------
__global__ void reset_copy(const float* __restrict__ w1, const float* __restrict__ gam,
                           const float* __restrict__ bet, const float* __restrict__ w2,
                           const float* __restrict__ rw1, const float* __restrict__ rw2){
    int i = blockIdx.x*blockDim.x + threadIdx.x;
    if (i==0){ g_flagF=0; g_flagW=0; }
    if (i < HIDN*CC){ float v=w1[i]; g_w1[i]=v; g_w1b[i]=__float2bfloat16(v); }
    if (i < CC*HIDN){
        float v=w2[i]; g_w2[i]=v;
        bft bv=__float2bfloat16(v);
        g_w2b[i]=bv;
        int c=i/HIDN, o=i%HIDN;
        g_w2tb[o*CC+c]=bv;
    }
    if (i < CU*CC){
        bft bv=__float2bfloat16(rw1[i]);
        g_rw1b[i]=bv;
        int u=i/CC, c=i%CC;
        g_rw1tb[c*CU+u]=bv;
    }
    if (i < CC*CU){
        bft bv=__float2bfloat16(rw2[i]);
        g_rw2b[i]=bv;
        int c=i/CU, u=i%CU;
        g_rw2tb[u*CC+c]=bv;
    }
    if (i < HIDN){ g_gamma[i]=gam[i]; g_beta[i]=bet[i]; }
}

__global__ void mask_detect(const unsigned int* __restrict__ mw){
    int f=0, wd=0;
    for (int i = blockIdx.x*blockDim.x + threadIdx.x; i < 25088; i += gridDim.x*blockDim.x){
        unsigned v = mw[i];
        if (v == 0x3F800000u) f = 1;
        else if (v != 0u && v != 1u) wd = 1;
    }
    if (f)  atomicOr(&g_flagF, 1);
    if (wd) atomicOr(&g_flagW, 1);
}

__global__ void mask_convert(const void* __restrict__ mp){
    int mode = g_flagW ? 2 : (g_flagF ? 1 : 0);
    int n = 2*NTOT;
    for (int i = blockIdx.x*blockDim.x + threadIdx.x; i < n; i += gridDim.x*blockDim.x){
        bool v;
        if (mode==0)      v = ((const int*)mp)[i] != 0;
        else if (mode==1) v = ((const float*)mp)[i] != 0.0f;
        else              v = ((const unsigned char*)mp)[i] != 0;
        g_maskf[i] = v ? 1.0f : 0.0f;
    }
}

__global__ void inv_scale_kernel(){
    int s = blockIdx.x;
    float cnt = 0.f, d = 0.f;
    for (int i = threadIdx.x; i < NTOT; i += 256) cnt += 1.0f - g_maskf[s*NTOT + i];
    block_reduce2(cnt, d);
    if (threadIdx.x==0) g_dscale[s] = 2.0f/(cnt*256.0f + 1e-8f);
}

__global__ void convert_x(const float* __restrict__ x, bft* __restrict__ xb){
    size_t i8 = (size_t)blockIdx.x*blockDim.x + threadIdx.x;
    size_t i = i8*8;
    float4 a = *(const float4*)(x+i);
    float4 b = *(const float4*)(x+i+4);
    float v[8] = {a.x,a.y,a.z,a.w,b.x,b.y,b.z,b.w};
    *(uint4*)(xb+i) = pack8(v);
}

// ============================================================================
// gemm512: M=512, K=256, BP=64, 512 threads (16 warps, warp tile 64x32),
// cp.async double-buffered.
// STAT 1: GN group partials.  STAT 2: dgn epilogue (stores dgn, row partials).
// ============================================================================
template<int STAT>
__global__ __launch_bounds__(512) void gemm512(
    const bft* __restrict__ W, const bft* __restrict__ X, bft* __restrict__ out,
    const bft* __restrict__ aux)
{
    extern __shared__ char dsm[];
    const unsigned WsU = smem_u32(dsm);                  // [2][512][40]
    const unsigned XsU = WsU + 2*512*40*2;               // [2][32][72]
    float2* srowp = (float2*)(dsm + 2*512*40*2 + 2*32*72*2);   // [512][2]
    float2* sgn   = srowp;                                     // reuse (16 entries)
    int b  = blockIdx.z;
    int p0 = blockIdx.x*64;
    const bft* Xb = X + (size_t)b*256*HWN;
    int tid  = threadIdx.x;
    int lane = tid & 31, warp = tid >> 5;
    int wm = warp >> 1, wp = warp & 1;
    float acc[4][2][2][4] = {};

    auto issue = [&](int it){
        int k0 = it*32;
        unsigned wb = WsU + (unsigned)((it&1)*512*40*2);
        #pragma unroll
        for (int j=0;j<4;j++){
            int chunk = tid + j*512;
            int row = chunk>>2, q = chunk&3;
            unsigned dst = wb + (unsigned)((row*40 + q*8)*2);
            const bft* src = W + (size_t)row*256 + k0 + q*8;
            asm volatile("cp.async.cg.shared.global [%0], [%1], 16;" :: "r"(dst), "l"(src));
        }
        if (tid < 256){
            int row = tid>>3, c = (tid&7)*8;
            unsigned dst = XsU + (unsigned)(((it&1)*32*72 + row*72 + c)*2);
            const bft* src = Xb + (size_t)(k0+row)*HWN + p0 + c;
            asm volatile("cp.async.cg.shared.global [%0], [%1], 16;" :: "r"(dst), "l"(src));
        }
        asm volatile("cp.async.commit_group;");
    };

    issue(0);
    #pragma unroll 1
    for (int it = 0; it < 8; it++){
        if (it < 7){
            issue(it+1);
            asm volatile("cp.async.wait_group 1;");
        } else {
            asm volatile("cp.async.wait_group 0;");
        }
        __syncthreads();
        unsigned wb  = WsU + (unsigned)((it&1)*512*40*2);
        unsigned xb2 = XsU + (unsigned)((it&1)*32*72*2);
        #pragma unroll
        for (int h=0; h<2; h++){
            int kb = h*16;
            unsigned A[4][4];
            #pragma unroll
            for (int ii=0;ii<4;ii++){
                unsigned addr = wb + (unsigned)((((wm*64 + ii*16 + (lane&15))*40) + kb + (lane>>4)*8)*2);
                asm volatile("ldmatrix.sync.aligned.m8n8.x4.shared.b16 {%0,%1,%2,%3}, [%4];"
                    : "=r"(A[ii][0]),"=r"(A[ii][1]),"=r"(A[ii][2]),"=r"(A[ii][3]) : "r"(addr));
            }
            #pragma unroll
            for (int jj=0; jj<2; jj++){
                unsigned Bv[4];
                unsigned baddr = xb2 + (unsigned)((((kb + (lane&7) + 8*((lane>>3)&1))*72) + wp*32 + jj*16 + 8*(lane>>4))*2);
                asm volatile("ldmatrix.sync.aligned.m8n8.x4.trans.shared.b16 {%0,%1,%2,%3}, [%4];"
                    : "=r"(Bv[0]),"=r"(Bv[1]),"=r"(Bv[2]),"=r"(Bv[3]) : "r"(baddr));
                #pragma unroll
                for (int ii=0;ii<4;ii++)
                    #pragma unroll
                    for (int j=0;j<2;j++){
                        float* d = acc[ii][jj][j];
                        asm volatile("mma.sync.aligned.m16n8k16.row.col.f32.bf16.bf16.f32 "
                            "{%0,%1,%2,%3},{%4,%5,%6,%7},{%8,%9},{%0,%1,%2,%3};"
                            : "+f"(d[0]),"+f"(d[1]),"+f"(d[2]),"+f"(d[3])
                            : "r"(A[ii][0]),"r"(A[ii][1]),"r"(A[ii][2]),"r"(A[ii][3]),
                              "r"(Bv[j*2]),"r"(Bv[j*2+1]));
                    }
            }
        }
        __syncthreads();
    }

    if (STAT==1){
        float s=0.f, sq=0.f;
        #pragma unroll
        for (int ii=0;ii<4;ii++)
            #pragma unroll
            for (int jj=0;jj<2;jj++)
                #pragma unroll
                for (int j=0;j<2;j++)
                    #pragma unroll
                    for (int r=0;r<4;r++){
                        float v = acc[ii][jj][j][r];
                        s += v; sq += v*v;
                    }
        #pragma unroll
        for (int off=16; off; off>>=1){
            s  += __shfl_xor_sync(0xffffffffu, s, off);
            sq += __shfl_xor_sync(0xffffffffu, sq, off);
        }
        if (lane==0) sgn[warp] = make_float2(s, sq);
        __syncthreads();
        if (tid < 8){
            float2 v0 = sgn[tid*2], v1 = sgn[tid*2+1];
            g_gnp[((size_t)b*NGRP + tid)*49 + blockIdx.x] = make_float2(v0.x+v1.x, v0.y+v1.y);
        }
        __syncthreads();
    }

    // epilogue: warp-pair (wm) owns rows wm*64..+63 = GN group wm
    float bg_mu=0.f, bg_rs=0.f;
    if (STAT==2){ int bg=b*NGRP+wm; bg_mu=g_mu[bg]; bg_rs=g_rstd[bg]; }

    float st_s[4][2], st_t[4][2];
    #pragma unroll
    for (int i=0;i<4;i++){ st_s[i][0]=st_s[i][1]=0.f; st_t[i][0]=st_t[i][1]=0.f; }

    #pragma unroll
    for (int ii=0;ii<4;ii++){
        #pragma unroll
        for (int rr=0;rr<2;rr++){
            int m = wm*64 + ii*16 + rr*8 + (lane>>2);
            float ga=0.f, be=0.f;
            if (STAT==2){ ga=g_gamma[m]; be=g_beta[m]; }
            #pragma unroll
            for (int jj=0;jj<2;jj++){
                #pragma unroll
                for (int j=0;j<2;j++){
                    int c = p0 + wp*32 + jj*16 + j*8 + (lane&3)*2;
                    size_t idx = ((size_t)b*512 + m)*HWN + c;
                    float v0 = acc[ii][jj][j][rr*2+0], v1 = acc[ii][jj][j][rr*2+1];
                    if (STAT==2){
                        float2 hv = ldbf2(aux+idx);
                        float hat0=(hv.x-bg_mu)*bg_rs, hat1=(hv.y-bg_mu)*bg_rs;
                        v0 *= gelu_grad(hat0*ga+be);
                        v1 *= gelu_grad(hat1*ga+be);
                        st_s[ii][rr] += v0+v1;
                        st_t[ii][rr] += v0*hat0 + v1*hat1;
                    }
                    *(unsigned*)(out+idx) = pack_bf2(v0, v1);
                }
            }
        }
    }

    if (STAT==2){
        #pragma unroll
        for (int ii=0;ii<4;ii++)
            #pragma unroll
            for (int rr=0;rr<2;rr++){
                float s=st_s[ii][rr], t=st_t[ii][rr];
                s += __shfl_xor_sync(0xffffffffu, s, 1); t += __shfl_xor_sync(0xffffffffu, t, 1);
                s += __shfl_xor_sync(0xffffffffu, s, 2); t += __shfl_xor_sync(0xffffffffu, t, 2);
                if ((lane&3)==0){
                    int m = wm*64 + ii*16 + rr*8 + (lane>>2);
                    srowp[m*2 + wp] = make_float2(s, t);
                }
            }
        __syncthreads();
        if (tid < 512){
            float2 a = srowp[tid*2+0], b2 = srowp[tid*2+1];
            g_rowp[((size_t)b*512 + tid)*49 + blockIdx.x] = make_float2(a.x+b2.x, a.y+b2.y);
        }
    }
}

// ============================================================================
// bf16 tensor-core GEMM (register path) — M<=256 cases.
// XOP: 0 none, 1 X*=mask, 2 X=gelu(X), 3 X=gelu(GN(X))
// EPI: 0 store, 1 +aux, 2 drec, 3 *=gelu'(aux), 4 dy-combine, 5 final out
// STAT: 0 none, 3 chan row partials
// ============================================================================
template<int XOP, int EPI, int BM, int STAT, typename TO>
__global__ __launch_bounds__(256) void gemm_bf16(
    const bft* __restrict__ W, const bft* __restrict__ X, TO* __restrict__ out,
    int M, int K,
    const float* __restrict__ mask, const bft* __restrict__ aux,
    const bft* __restrict__ y, const float* __restrict__ scal)
{
    constexpr int WPp = (BM==64)?4:2;
    constexpr int NJc = (BM==64)?1:2;
    constexpr int WMT = (BM==256)?4:2;
    constexpr int NW  = (BM==256)?4:((BM==128)?2:1);
    __shared__ bft Ws[BM][40];
    __shared__ bft Xs[32][72];
    __shared__ float2 srow[BM][2];
    int b  = blockIdx.z;
    int m0 = blockIdx.y*BM, p0 = blockIdx.x*64;
    const bft* Xb = X + (size_t)b*K*HWN;
    int tid  = threadIdx.x;
    int lane = tid & 31, warp = tid >> 5;
    int wm = warp / WPp, wp = warp % WPp;
    float acc[WMT][NJc][2][4] = {};

    int xk = tid>>3, xc = (tid&7)*8;
    float mv[8];
    if (XOP==1){
        const float* mr = mask + (size_t)b*HWN + p0 + xc;
        float4 a=*(const float4*)mr, b2=*(const float4*)(mr+4);
        mv[0]=a.x;mv[1]=a.y;mv[2]=a.z;mv[3]=a.w;mv[4]=b2.x;mv[5]=b2.y;mv[6]=b2.z;mv[7]=b2.w;
    }

    uint4 wreg[NW];
    uint4 xreg;

    auto load_tile = [&](int k0){
        const bft* w;
        if (BM==256)      w = W + (size_t)(m0 + tid)*K + k0;
        else if (BM==128) w = W + (size_t)(m0 + (tid>>1))*K + k0 + (tid&1)*16;
        else              w = W + (size_t)(m0 + (tid>>2))*K + k0 + (tid&3)*8;
        #pragma unroll
        for (int q=0;q<NW;q++) wreg[q] = *(const uint4*)(w + q*8);
        xreg = *(const uint4*)(Xb + (size_t)(k0+xk)*HWN + p0 + xc);
    };

    auto store_tile = [&](int k0){
        if (BM==256){
            #pragma unroll
            for (int q=0;q<NW;q++) *(uint4*)&Ws[tid][q*8] = wreg[q];
        } else if (BM==128){
            int row=tid>>1, c=(tid&1)*16;
            *(uint4*)&Ws[row][c]   = wreg[0];
            *(uint4*)&Ws[row][c+8] = wreg[1];
        } else {
            int row=tid>>2, c=(tid&3)*8;
            *(uint4*)&Ws[row][c] = wreg[0];
        }
        if (XOP==0){
            *(uint4*)&Xs[xk][xc] = xreg;
        } else {
            float vv[8]; unpack8(xreg, vv);
            if (XOP==1){
                #pragma unroll
                for (int j=0;j<8;j++) vv[j] *= mv[j];
            } else if (XOP==2){
                #pragma unroll
                for (int j=0;j<8;j++) vv[j] = geluf(vv[j]);
            } else {
                int o = k0 + xk;
                int bg = b*NGRP + o/CGg;
                float mu=g_mu[bg], rs=g_rstd[bg], ga=g_gamma[o], be=g_beta[o];
                #pragma unroll
                for (int j=0;j<8;j++) vv[j] = geluf((vv[j]-mu)*rs*ga + be);
            }
            *(uint4*)&Xs[xk][xc] = pack8(vv);
        }
    };

    const int NK = K >> 5;
    load_tile(0);
    for (int i = 0; i < NK; i++){
        store_tile(i*32);
        __syncthreads();
        if (i+1 < NK) load_tile((i+1)*32);

        #pragma unroll
        for (int h=0; h<2; h++){
            int kb = h*16;
            unsigned A[WMT][4];
            #pragma unroll
            for (int ii=0;ii<WMT;ii++){
                unsigned addr = smem_u32(&Ws[wm*(WMT*16) + ii*16 + (lane&15)][kb + (lane>>4)*8]);
                asm volatile("ldmatrix.sync.aligned.m8n8.x4.shared.b16 {%0,%1,%2,%3}, [%4];"
                    : "=r"(A[ii][0]),"=r"(A[ii][1]),"=r"(A[ii][2]),"=r"(A[ii][3]) : "r"(addr));
            }
            #pragma unroll
            for (int jj=0; jj<NJc; jj++){
                unsigned Bv[4];
                unsigned baddr = smem_u32(&Xs[kb + (lane&7) + 8*((lane>>3)&1)][wp*(NJc*16) + jj*16 + 8*(lane>>4)]);
                asm volatile("ldmatrix.sync.aligned.m8n8.x4.trans.shared.b16 {%0,%1,%2,%3}, [%4];"
                    : "=r"(Bv[0]),"=r"(Bv[1]),"=r"(Bv[2]),"=r"(Bv[3]) : "r"(baddr));
                #pragma unroll
                for (int ii=0;ii<WMT;ii++)
                    #pragma unroll
                    for (int j=0;j<2;j++){
                        float* d = acc[ii][jj][j];
                        asm volatile("mma.sync.aligned.m16n8k16.row.col.f32.bf16.bf16.f32 "
                            "{%0,%1,%2,%3},{%4,%5,%6,%7},{%8,%9},{%0,%1,%2,%3};"
                            : "+f"(d[0]),"+f"(d[1]),"+f"(d[2]),"+f"(d[3])
                            : "r"(A[ii][0]),"r"(A[ii][1]),"r"(A[ii][2]),"r"(A[ii][3]),
                              "r"(Bv[j*2]),"r"(Bv[j*2+1]));
                    }
            }
        }
        __syncthreads();
    }

    float st_s[WMT][2];
    float st_t[WMT][2];
    #pragma unroll
    for (int i=0;i<WMT;i++){ st_s[i][0]=st_s[i][1]=0.f; st_t[i][0]=st_t[i][1]=0.f; }

    #pragma unroll
    for (int i=0;i<WMT;i++){
        int rbase = m0 + wm*(WMT*16) + i*16 + (lane>>2);
        #pragma unroll
        for (int jj=0;jj<NJc;jj++){
            #pragma unroll
            for (int j=0;j<2;j++){
                int c = p0 + wp*(NJc*16) + jj*16 + j*8 + (lane&3)*2;
                #pragma unroll
                for (int rr=0; rr<2; rr++){
                    int m = rbase + rr*8;
                    size_t idx = ((size_t)b*M + m)*HWN + c;
                    float v0 = acc[i][jj][j][rr*2+0], v1 = acc[i][jj][j][rr*2+1];
                    if (EPI==1){
                        float2 a = ldbf2(aux+idx);
                        v0 += a.x; v1 += a.y;
                    } else if (EPI==2){
                        float sc = scal[0];
                        size_t mi = (size_t)b*HWN + c;
                        float2 mk = *(const float2*)(mask+mi);
                        float2 yv = ldbf2(y+idx);
                        v0 = (v0 - yv.x)*(1.0f-mk.x)*sc;
                        v1 = (v1 - yv.y)*(1.0f-mk.y)*sc;
                    } else if (EPI==3){
                        float2 a = ldbf2(aux+idx);
                        v0 *= gelu_grad(a.x); v1 *= gelu_grad(a.y);
                    } else if (EPI==4){
                        size_t mi = (size_t)b*HWN + c;
                        float2 mk = *(const float2*)(mask+mi);
                        float2 a  = ldbf2(aux+idx);
                        float2 yv = ldbf2(y+idx);
                        float cA = g_cA[m], cB = g_cB[m], cm = g_cm[m];
                        v0 = v0*mk.x - a.x + cA + cB*(yv.x-cm);
                        v1 = v1*mk.y - a.y + cA + cB*(yv.y-cm);
                    } else if (EPI==5){
                        float sc = scal[0]*g_gate[b];
                        float2 xf = *(const float2*)(mask+idx);   // mask = x (fp32)
                        v0 = xf.x + sc*v0; v1 = xf.y + sc*v1;
                    }
                    if (STAT==3){
                        st_s[i][rr] += v0+v1;
                        st_t[i][rr] += v0*v0 + v1*v1;
                    }
                    if (sizeof(TO)==4)
                        *(float2*)((float*)out+idx) = make_float2(v0, v1);
                    else
                        *(unsigned*)((bft*)out+idx) = pack_bf2(v0, v1);
                }
            }
        }
    }

    if (STAT==3){
        #pragma unroll
        for (int i=0;i<WMT;i++)
            #pragma unroll
            for (int rr=0;rr<2;rr++){
                float s=st_s[i][rr], t=st_t[i][rr];
                s += __shfl_xor_sync(0xffffffffu, s, 1); t += __shfl_xor_sync(0xffffffffu, t, 1);
                s += __shfl_xor_sync(0xffffffffu, s, 2); t += __shfl_xor_sync(0xffffffffu, t, 2);
                if ((lane&3)==0) srow[wm*(WMT*16) + i*16 + rr*8 + (lane>>2)][wp] = make_float2(s, t);
            }
        __syncthreads();
        if (tid < BM){
            float2 a = srow[tid][0], b2 = srow[tid][1];
            g_rowp[((size_t)b*M + m0 + tid)*49 + blockIdx.x] = make_float2(a.x+b2.x, a.y+b2.y);
        }
    }
}

__global__ void gn_reduce(){
    int bg = threadIdx.x;  // 128
    float s=0.f, sq=0.f;
    for (int i=0;i<49;i++){
        float2 v = g_gnp[(size_t)bg*49 + i];
        s += v.x; sq += v.y;
    }
    float n = (float)(CGg*HWN);
    float mean = s/n;
    float var  = sq/n - mean*mean;
    g_mu[bg] = mean;
    g_rstd[bg] = rsqrtf(var + 1e-5f);
}

__global__ void dgn_rowreduce(){
    int idx = blockIdx.x*blockDim.x + threadIdx.x;
    float s=0.f, t=0.f;
    for (int x=0; x<49; x++){
        float2 v = g_rowp[(size_t)idx*49 + x];
        s += v.x; t += v.y;
    }
    g_part[idx*2+0] = s;
    g_part[idx*2+1] = t;
}

__global__ void chan_reduce(const float* __restrict__ rm, const float* __restrict__ rv){
    int c = blockIdx.x;
    float s=0.f, sq=0.f;
    for (int i=threadIdx.x; i<BN*49; i+=256){
        int b=i/49, x=i%49;
        float2 v = g_rowp[((size_t)b*CC + c)*49 + x];
        s += v.x; sq += v.y;
    }
    block_reduce2(s, sq);
    if (threadIdx.x==0){
        float n = (float)NTOT;
        float cm = s/n;
        float cv = (sq - n*cm*cm)/(n - 1.0f);
        float rve = rv[c] + 1e-8f;
        g_cm[c] = cm;
        g_cA[c] = 0.1f*2.0f*(cm - rm[c])/(256.0f*n);
        g_cB[c] = 0.1f*4.0f*(cv/rve - 1.0f)/(rve*256.0f*(n - 1.0f));
    }
}

// ============================================================================
// NT GEMM 128x128, double-buffered.
// XOPB: 0 none, 3 B'=gelu(GN(B));  XOPA: 0 none, 1 A'=dh1 from stored dgn
// ============================================================================
template<int XOPB, int XOPA>
__global__ __launch_bounds__(256) void gemm_nt_bf16(
    const bft* __restrict__ A, const bft* __restrict__ Bm, const bft* __restrict__ Hm,
    float* __restrict__ part, int Ma, int Nb)
{
    __shared__ bft As[2][128][40];
    __shared__ bft Bs[2][128][40];
    int z  = blockIdx.z;
    int m0 = blockIdx.y*128, n0 = blockIdx.x*128;
    int tid  = threadIdx.x;
    int lane = tid & 31, warp = tid >> 5;
    int wm = warp >> 1, wp = warp & 1;
    float acc[2][8][4] = {};

    int r  = tid >> 1, c0 = (tid & 1)*16;

    #define POFF(it) ((((it)%PBZ)*SPLITK + z)*32)
    #define AP(it) (A  + ((size_t)((it)/PBZ)*Ma + m0 + r)*HWN + POFF(it) + c0)
    #define BP(it) (Bm + ((size_t)((it)/PBZ)*Nb + n0 + r)*HWN + POFF(it) + c0)
    #define HP(it) (Hm + ((size_t)((it)/PBZ)*Ma + m0 + r)*HWN + POFF(it) + c0)

    uint4 a0, a1, b0, b1, h0, h1;
    auto load_it = [&](int it){
        a0 = *(const uint4*)AP(it); a1 = *(const uint4*)(AP(it)+8);
        b0 = *(const uint4*)BP(it); b1 = *(const uint4*)(BP(it)+8);
        if (XOPA==1){ h0 = *(const uint4*)HP(it); h1 = *(const uint4*)(HP(it)+8); }
    };
    auto store_it = [&](int buf, int it){
        if (XOPA==0){
            *(uint4*)&As[buf][r][c0]   = a0;
            *(uint4*)&As[buf][r][c0+8] = a1;
        } else {
            int b = it/PBZ;
            int o = m0 + r;
            int bg = b*NGRP + o/CGg;
            float mu=g_mu[bg], rs=g_rstd[bg], ga=g_gamma[o];
            float s1=g_s1[bg], s2=g_s2[bg];
            float av[8], hv[8];
            unpack8(a0, av); unpack8(h0, hv);
            #pragma unroll
            for (int j=0;j<8;j++){
                float hat=(hv[j]-mu)*rs;
                av[j] = rs*(av[j]*ga - s1 - hat*s2);
            }
            *(uint4*)&As[buf][r][c0] = pack8(av);
            unpack8(a1, av); unpack8(h1, hv);
            #pragma unroll
            for (int j=0;j<8;j++){
                float hat=(hv[j]-mu)*rs;
                av[j] = rs*(av[j]*ga - s1 - hat*s2);
            }
            *(uint4*)&As[buf][r][c0+8] = pack8(av);
        }
        if (XOPB==0){
            *(uint4*)&Bs[buf][r][c0]   = b0;
            *(uint4*)&Bs[buf][r][c0+8] = b1;
        } else {
            int b = it/PBZ;
            int o = n0 + r;
            int bg = b*NGRP + o/CGg;
            float mu=g_mu[bg], rs=g_rstd[bg], ga=g_gamma[o], be=g_beta[o];
            float v[8];
            unpack8(b0, v);
            #pragma unroll
            for (int j=0;j<8;j++) v[j] = geluf((v[j]-mu)*rs*ga + be);
            *(uint4*)&Bs[buf][r][c0] = pack8(v);
            unpack8(b1, v);
            #pragma unroll
            for (int j=0;j<8;j++) v[j] = geluf((v[j]-mu)*rs*ga + be);
            *(uint4*)&Bs[buf][r][c0+8] = pack8(v);
        }
    };

    load_it(0);
    store_it(0, 0);
    __syncthreads();

    const int ITERS = BN*PBZ;
    for (int it=0; it<ITERS; it++){
        int cur = it & 1;
        if (it+1 < ITERS) load_it(it+1);

        #pragma unroll
        for (int h=0; h<2; h++){
            int kb = h*16;
            unsigned Af[2][4];
            #pragma unroll
            for (int i=0;i<2;i++){
                unsigned addr = smem_u32(&As[cur][wm*32 + i*16 + (lane&15)][kb + (lane>>4)*8]);
                asm volatile("ldmatrix.sync.aligned.m8n8.x4.shared.b16 {%0,%1,%2,%3}, [%4];"
                    : "=r"(Af[i][0]),"=r"(Af[i][1]),"=r"(Af[i][2]),"=r"(Af[i][3]) : "r"(addr));
            }
            #pragma unroll
            for (int jj=0; jj<4; jj++){
                unsigned Bv[4];
                unsigned baddr = smem_u32(&Bs[cur][wp*64 + jj*16 + (lane&7) + 8*(lane>>4)][kb + 8*((lane>>3)&1)]);
                asm volatile("ldmatrix.sync.aligned.m8n8.x4.shared.b16 {%0,%1,%2,%3}, [%4];"
                    : "=r"(Bv[0]),"=r"(Bv[1]),"=r"(Bv[2]),"=r"(Bv[3]) : "r"(baddr));
                #pragma unroll
                for (int i=0;i<2;i++)
                    #pragma unroll
                    for (int j=0;j<2;j++){
                        float* d = acc[i][jj*2+j];
                        asm volatile("mma.sync.aligned.m16n8k16.row.col.f32.bf16.bf16.f32 "
                            "{%0,%1,%2,%3},{%4,%5,%6,%7},{%8,%9},{%0,%1,%2,%3};"
                            : "+f"(d[0]),"+f"(d[1]),"+f"(d[2]),"+f"(d[3])
                            : "r"(Af[i][0]),"r"(Af[i][1]),"r"(Af[i][2]),"r"(Af[i][3]),
                              "r"(Bv[j*2]),"r"(Bv[j*2+1]));
                    }
            }
        }
        if (it+1 < ITERS) store_it(cur^1, it+1);
        __syncthreads();
    }
    #undef AP
    #undef BP
    #undef HP
    #undef POFF

    #pragma unroll
    for (int i=0;i<2;i++){
        int rbase = m0 + wm*32 + i*16 + (lane>>2);
        #pragma unroll
        for (int jc=0;jc<8;jc++){
            int n = n0 + wp*64 + (jc>>1)*16 + (jc&1)*8 + (lane&3)*2;
            #pragma unroll
            for (int rr=0; rr<2; rr++){
                int m = rbase + rr*8;
                size_t idx = ((size_t)z*Ma + m)*Nb + n;
                *(float2*)(part+idx) = make_float2(acc[i][jc][rr*2], acc[i][jc][rr*2+1]);
            }
        }
    }
}

__global__ void reduce_split(const float* __restrict__ part, float* __restrict__ out, int n){
    int i = blockIdx.x*blockDim.x + threadIdx.x;
    if (i < n){
        float s = 0.f;
        for (int z=0; z<SPLITK; z++) s += part[(size_t)z*n + i];
        out[i] = s;
    }
}

__global__ void reduce_part(){
    int t = threadIdx.x;  // 512
    float db=0.f, dga=0.f;
    for (int b=0;b<BN;b++){
        db  += g_part[(b*HIDN+t)*2+0];
        dga += g_part[(b*HIDN+t)*2+1];
    }
    g_dbeta[t]=db; g_dgamma[t]=dga;
    if (t < BN*NGRP){
        int b=t/NGRP, g=t%NGRP;
        float s1=0.f, s2=0.f;
        for (int j=0;j<CGg;j++){
            int o=g*CGg+j;
            float ga=g_gamma[o];
            s1 += ga*g_part[(b*HIDN+o)*2+0];
            s2 += ga*g_part[(b*HIDN+o)*2+1];
        }
        float inv = 1.0f/(float)(CGg*HWN);
        g_s1[t]=s1*inv; g_s2[t]=s2*inv;
    }
}

__global__ void update_params(){
    int i = blockIdx.x*blockDim.x + threadIdx.x;
    if (i < HIDN*CC){
        float v = g_w1[i] - LRc*g_dW1[i];
        g_w1[i]=v; g_w1b[i]=__float2bfloat16(v);
    }
    if (i < CC*HIDN){
        float v = g_w2[i] - LRc*g_dW2[i];
        g_w2[i]=v;
        bft bv=__float2bfloat16(v);
        g_w2b[i]=bv;
        int c=i/HIDN, o=i%HIDN;
        g_w2tb[o*CC+c]=bv;
    }
    if (i < HIDN){ g_gamma[i] -= LRc*g_dgamma[i]; g_beta[i] -= LRc*g_dbeta[i]; }
}

// ---------------- gate path ----------------
__global__ void pooled_kernel(const float* __restrict__ x){
    int c = blockIdx.x, b = blockIdx.y;
    const float4* row = (const float4*)(x + ((size_t)b*CC + c)*HWN);
    float s=0.f, d=0.f;
    for (int i=threadIdx.x; i<HWN/4; i+=256){
        float4 v = row[i];
        s += v.x+v.y+v.z+v.w;
    }
    block_reduce2(s, d);
    if (threadIdx.x==0) g_pooled[b*CC+c] = s/(float)HWN;
}

__global__ void gate_kernel(const float* __restrict__ gw1, const float* __restrict__ gb1,
                            const float* __restrict__ gw2, const float* __restrict__ gb2){
    __shared__ float gh[BN*CU];
    int t = threadIdx.x;
    for (int j=t; j<BN*CU; j+=256){
        int b=j/CU, u=j%CU;
        float s = gb1[u];
        const float* pr = &g_pooled[b*CC];
        const float* wr = &gw1[u*CC];
        for (int c=0;c<CC;c++) s += pr[c]*wr[c];
        gh[j] = geluf(s);
    }
    __syncthreads();
    if (t < BN){
        float s = gb2[0];
        for (int u=0;u<CU;u++) s += gh[t*CU+u]*gw2[u];
        g_gate[t] = 1.0f/(1.0f + expf(-s));
    }
}

// ---------------- host orchestration ----------------
extern "C" void kernel_launch(void* const* d_in, const int* in_sizes, int n_in,
                              void* d_out, int out_size){
    const float* x        = (const float*)d_in[0];
    const float* conv1_w  = (const float*)d_in[1];
    const float* gn_gammaI= (const float*)d_in[2];
    const float* gn_betaI = (const float*)d_in[3];
    const float* conv2_w  = (const float*)d_in[4];
    const float* rw1      = (const float*)d_in[5];
    const float* rw2      = (const float*)d_in[6];
    const float* gw1      = (const float*)d_in[7];
    const float* gb1      = (const float*)d_in[8];
    const float* gw2      = (const float*)d_in[9];
    const float* gb2      = (const float*)d_in[10];
    const float* rscale   = (const float*)d_in[11];
    const float* rm       = (const float*)d_in[12];
    const float* rv       = (const float*)d_in[13];
    const void*  masks    = d_in[14];

    void* p;
    #define SYMF(sym) (cudaGetSymbolAddress(&p, sym), (float*)p)
    #define SYMB(sym) (cudaGetSymbolAddress(&p, sym), (bft*)p)
    bft*   pw1b   = SYMB(g_w1b);
    bft*   pw2b   = SYMB(g_w2b);
    bft*   pw2tb  = SYMB(g_w2tb);
    bft*   prw1b  = SYMB(g_rw1b);
    bft*   prw1tb = SYMB(g_rw1tb);
    bft*   prw2b  = SYMB(g_rw2b);
    bft*   prw2tb = SYMB(g_rw2tb);
    bft*   ph1    = SYMB(g_h1);
    bft*   pdg    = SYMB(g_dg);
    bft*   py     = SYMB(g_y);
    bft*   pdrec  = SYMB(g_drec);
    bft*   pdy    = SYMB(g_dy);
    bft*   ppre   = SYMB(g_pre);
    bft*   pdpre  = SYMB(g_dpre);
    bft*   pxb    = SYMB(g_xb);
    float* psplit = SYMF(g_split);
    float* pdW1   = SYMF(g_dW1);
    float* pdW2   = SYMF(g_dW2);
    float* pmaskf = SYMF(g_maskf);
    float* pdscale= SYMF(g_dscale);
    #undef SYMF
    #undef SYMB

    const int SMEM512 = 2*512*40*2 + 2*32*72*2 + 512*2*8;   // 99328
    cudaFuncSetAttribute(gemm512<1>, cudaFuncAttributeMaxDynamicSharedMemorySize, SMEM512);
    cudaFuncSetAttribute(gemm512<2>, cudaFuncAttributeMaxDynamicSharedMemorySize, SMEM512);

    // init
    reset_copy<<<512,256>>>(conv1_w, gn_gammaI, gn_betaI, conv2_w, rw1, rw2);
    mask_detect<<<32,256>>>((const unsigned int*)masks);
    convert_x<<<6272,256>>>(x, pxb);

    for (int s=0; s<2; s++){
        const float* mk = pmaskf + (size_t)s*NTOT;
        const float* sc = pdscale + s;

        // forward
        gemm512<1><<<dim3(49,1,BN),512,SMEM512>>>(pw1b, pxb, ph1, nullptr);
        gn_reduce<<<1,128>>>();
        if (s==0){
            mask_convert<<<98,1024>>>(masks);
            inv_scale_kernel<<<2,256>>>();
        }
        gemm_bf16<3,1,256,3,bft><<<dim3(49,1,BN),256>>>(pw2b, ph1,  py,   256,512, nullptr, pxb,   nullptr,nullptr);
        chan_reduce<<<256,256>>>(rm, rv);
        gemm_bf16<1,0, 64,0,bft><<<dim3(49,1,BN),256>>>(prw1b, py,   ppre,  64,256, mk,      nullptr,nullptr,nullptr);
        gemm_bf16<2,2,256,0,bft><<<dim3(49,1,BN),256>>>(prw2b, ppre, pdrec,256, 64, mk,      nullptr, py,    sc);

        // backward through surprise
        gemm_bf16<0,3, 64,0,bft><<<dim3(49,1,BN),256>>>(prw2tb, pdrec, pdpre, 64,256, nullptr, ppre,  nullptr,nullptr);
        gemm_bf16<0,4,256,0,bft><<<dim3(49,1,BN),256>>>(prw1tb, pdpre, pdy,  256, 64, mk,      pdrec, py,     nullptr);

        // backward through modifier (emits dgn + per-row partials)
        gemm512<2><<<dim3(49,1,BN),512,SMEM512>>>(pw2tb, pdy, pdg, ph1);
        dgn_rowreduce<<<32,256>>>();
        reduce_part<<<1,512>>>();

        gemm_nt_bf16<3,0><<<dim3(4,2,SPLITK),256>>>(pdy, ph1, nullptr, psplit, 256,512);
        reduce_split<<<512,256>>>(psplit, pdW2, HIDN*CC);
        gemm_nt_bf16<0,1><<<dim3(2,4,SPLITK),256>>>(pdg, pxb, ph1,     psplit, 512,256);
        reduce_split<<<512,256>>>(psplit, pdW1, HIDN*CC);

        update_params<<<512,256>>>();
    }

    // gate path
    pooled_kernel<<<dim3(CC,BN),256>>>(x);
    gate_kernel<<<1,256>>>(gw1, gb1, gw2, gb2);

    // final forward (fused output)
    gemm512<1><<<dim3(49,1,BN),512,SMEM512>>>(pw1b, pxb, ph1, nullptr);
    gn_reduce<<<1,128>>>();
    gemm_bf16<3,5,256,0,float><<<dim3(49,1,BN),256>>>(pw2b, ph1, (float*)d_out, 256,512, x, nullptr, nullptr, rscale);

    (void)in_sizes; (void)n_in; (void)out_size;
}

// round 10
// speedup vs baseline: 1.5079x; 1.5079x over previous
#include <cuda_runtime.h>
#include <cuda_bf16.h>
#include <cstdint>
#include <math.h>

// ---------------- problem constants ----------------
#define BN    16
#define CC    256
#define HIDN  512
#define NGRP  8
#define CGg   64
#define HWN   3136
#define CU    64
#define NTOT  (BN*HWN)
#define LRc   0.01f
#define SPLITK 49
#define PBZ   2           // (HWN/32)/SPLITK

typedef __nv_bfloat16 bft;

// ---------------- device scratch ----------------
__device__ float g_w1[HIDN*CC];
__device__ float g_w2[CC*HIDN];
__device__ float g_gamma[HIDN];
__device__ float g_beta[HIDN];

__device__ bft g_w1b [HIDN*CC];
__device__ bft g_w2b [CC*HIDN];
__device__ bft g_w2tb[HIDN*CC];
__device__ bft g_rw1b [CU*CC];
__device__ bft g_rw1tb[CC*CU];
__device__ bft g_rw2b [CC*CU];
__device__ bft g_rw2tb[CU*CC];

__device__ bft g_h1 [(size_t)BN*HIDN*HWN];
__device__ bft g_dg [(size_t)BN*HIDN*HWN];   // holds dgn after dg-GEMM
__device__ bft g_y  [(size_t)BN*CC*HWN];
__device__ bft g_drec[(size_t)BN*CC*HWN];
__device__ bft g_dy [(size_t)BN*CC*HWN];
__device__ bft g_pre [(size_t)BN*CU*HWN];
__device__ bft g_dpre[(size_t)BN*CU*HWN];
__device__ bft g_xb [(size_t)BN*CC*HWN];

__device__ float g_mu[BN*NGRP];
__device__ float g_rstd[BN*NGRP];
__device__ float2 g_gnp[BN*NGRP*49];
__device__ float2 g_rowp[(size_t)BN*HIDN*49];
__device__ float g_part[BN*HIDN*2];
__device__ float g_s1[BN*NGRP], g_s2[BN*NGRP];
__device__ float g_dgamma[HIDN], g_dbeta[HIDN];
__device__ float g_cm[CC], g_cA[CC], g_cB[CC];
__device__ float g_split[(size_t)SPLITK*HIDN*CC];
__device__ float g_dW1[HIDN*CC], g_dW2[CC*HIDN];
__device__ float g_maskf[2*NTOT];
__device__ float g_dscale[2];
__device__ float g_pooled[BN*CC];
__device__ float g_gate[BN];
__device__ int   g_flagF, g_flagW;

// ---------------- math helpers ----------------
__device__ __forceinline__ float geluf(float x){
    return 0.5f*x*(1.0f + erff(x*0.70710678118654752440f));
}
__device__ __forceinline__ float gelu_grad(float x){
    float cdf = 0.5f*(1.0f + erff(x*0.70710678118654752440f));
    float pdf = 0.3989422804014327f*__expf(-0.5f*x*x);
    return cdf + x*pdf;
}
__device__ __forceinline__ void block_reduce2(float& a, float& b){
    __shared__ float sa[256], sb[256];
    int t = threadIdx.x;
    sa[t]=a; sb[t]=b; __syncthreads();
    for (int s=128; s>0; s>>=1){
        if (t<s){ sa[t]+=sa[t+s]; sb[t]+=sb[t+s]; }
        __syncthreads();
    }
    a=sa[0]; b=sb[0];
}
__device__ __forceinline__ unsigned pack_bf2(float a, float b){
    __nv_bfloat162 p = __floats2bfloat162_rn(a, b);
    return *(unsigned*)&p;
}
__device__ __forceinline__ unsigned smem_u32(const void* p){
    return (unsigned)__cvta_generic_to_shared(p);
}
__device__ __forceinline__ void unpack8(uint4 u, float* v){
    __nv_bfloat162 p;
    p=*(__nv_bfloat162*)&u.x; v[0]=__low2float(p); v[1]=__high2float(p);
    p=*(__nv_bfloat162*)&u.y; v[2]=__low2float(p); v[3]=__high2float(p);
    p=*(__nv_bfloat162*)&u.z; v[4]=__low2float(p); v[5]=__high2float(p);
    p=*(__nv_bfloat162*)&u.w; v[6]=__low2float(p); v[7]=__high2float(p);
}
__device__ __forceinline__ uint4 pack8(const float* v){
    uint4 u;
    u.x=pack_bf2(v[0],v[1]); u.y=pack_bf2(v[2],v[3]);
    u.z=pack_bf2(v[4],v[5]); u.w=pack_bf2(v[6],v[7]);
    return u;
}
__device__ __forceinline__ float2 ldbf2(const bft* p){
    __nv_bfloat162 v = *(const __nv_bfloat162*)p;
    return make_float2(__low2float(v), __high2float(v));
}

// ---------------- init / mask handling ----------------
__global__ void reset_copy(const float* __restrict__ w1, const float* __restrict__ gam,
                           const float* __restrict__ bet, const float* __restrict__ w2,
                           const float* __restrict__ rw1, const float* __restrict__ rw2){
    int i = blockIdx.x*blockDim.x + threadIdx.x;
    if (i==0){ g_flagF=0; g_flagW=0; }
    if (i < HIDN*CC){ float v=w1[i]; g_w1[i]=v; g_w1b[i]=__float2bfloat16(v); }
    if (i < CC*HIDN){
        float v=w2[i]; g_w2[i]=v;
        bft bv=__float2bfloat16(v);
        g_w2b[i]=bv;
        int c=i/HIDN, o=i%HIDN;
        g_w2tb[o*CC+c]=bv;
    }
    if (i < CU*CC){
        bft bv=__float2bfloat16(rw1[i]);
        g_rw1b[i]=bv;
        int u=i/CC, c=i%CC;
        g_rw1tb[c*CU+u]=bv;
    }
    if (i < CC*CU){
        bft bv=__float2bfloat16(rw2[i]);
        g_rw2b[i]=bv;
        int c=i/CU, u=i%CU;
        g_rw2tb[u*CC+c]=bv;
    }
    if (i < HIDN){ g_gamma[i]=gam[i]; g_beta[i]=bet[i]; }
}

__global__ void mask_detect(const unsigned int* __restrict__ mw){
    int f=0, wd=0;
    for (int i = blockIdx.x*blockDim.x + threadIdx.x; i < 25088; i += gridDim.x*blockDim.x){
        unsigned v = mw[i];
        if (v == 0x3F800000u) f = 1;
        else if (v != 0u && v != 1u) wd = 1;
    }
    if (f)  atomicOr(&g_flagF, 1);
    if (wd) atomicOr(&g_flagW, 1);
}

__global__ void mask_convert(const void* __restrict__ mp){
    int mode = g_flagW ? 2 : (g_flagF ? 1 : 0);
    int n = 2*NTOT;
    for (int i = blockIdx.x*blockDim.x + threadIdx.x; i < n; i += gridDim.x*blockDim.x){
        bool v;
        if (mode==0)      v = ((const int*)mp)[i] != 0;
        else if (mode==1) v = ((const float*)mp)[i] != 0.0f;
        else              v = ((const unsigned char*)mp)[i] != 0;
        g_maskf[i] = v ? 1.0f : 0.0f;
    }
}

__global__ void inv_scale_kernel(){
    int s = blockIdx.x;
    float cnt = 0.f, d = 0.f;
    for (int i = threadIdx.x; i < NTOT; i += 256) cnt += 1.0f - g_maskf[s*NTOT + i];
    block_reduce2(cnt, d);
    if (threadIdx.x==0) g_dscale[s] = 2.0f/(cnt*256.0f + 1e-8f);
}

__global__ void convert_x(const float* __restrict__ x, bft* __restrict__ xb){
    size_t i8 = (size_t)blockIdx.x*blockDim.x + threadIdx.x;
    size_t i = i8*8;
    float4 a = *(const float4*)(x+i);
    float4 b = *(const float4*)(x+i+4);
    float v[8] = {a.x,a.y,a.z,a.w,b.x,b.y,b.z,b.w};
    *(uint4*)(xb+i) = pack8(v);
}

// ============================================================================
// gemm512: M=512, K=256, BP=64, 256 threads, warp tile 64x64,
// 3-stage cp.async pipeline.
// STAT 1: GN group partials.  STAT 2: dgn epilogue (stores dgn, row partials).
// ============================================================================
#define WSTG (512*40*2)
#define XSTG (32*72*2)
template<int STAT>
__global__ __launch_bounds__(256) void gemm512(
    const bft* __restrict__ W, const bft* __restrict__ X, bft* __restrict__ out,
    const bft* __restrict__ aux)
{
    extern __shared__ char dsm[];
    const unsigned WsU = smem_u32(dsm);                  // [3][512][40]
    const unsigned XsU = WsU + 3*WSTG;                   // [3][32][72]
    int b  = blockIdx.z;
    int p0 = blockIdx.x*64;
    const bft* Xb = X + (size_t)b*256*HWN;
    int tid  = threadIdx.x;
    int lane = tid & 31, wm = tid >> 5;
    float acc[4][4][2][4] = {};

    auto issue = [&](int it){
        int k0 = it*32;
        int st = it % 3;
        unsigned wb = WsU + (unsigned)(st*WSTG);
        #pragma unroll
        for (int j=0;j<8;j++){
            int chunk = tid + j*256;
            int row = chunk>>2, q = chunk&3;
            unsigned dst = wb + (unsigned)((row*40 + q*8)*2);
            const bft* src = W + (size_t)row*256 + k0 + q*8;
            asm volatile("cp.async.cg.shared.global [%0], [%1], 16;" :: "r"(dst), "l"(src));
        }
        {
            int row = tid>>3, c = (tid&7)*8;
            unsigned dst = XsU + (unsigned)((st*32*72 + row*72 + c)*2);
            const bft* src = Xb + (size_t)(k0+row)*HWN + p0 + c;
            asm volatile("cp.async.cg.shared.global [%0], [%1], 16;" :: "r"(dst), "l"(src));
        }
        asm volatile("cp.async.commit_group;");
    };

    issue(0);
    issue(1);
    #pragma unroll 1
    for (int it = 0; it < 8; it++){
        if (it + 2 < 8){
            issue(it+2);
            asm volatile("cp.async.wait_group 2;");
        } else if (it + 1 < 8){
            asm volatile("cp.async.wait_group 1;");
        } else {
            asm volatile("cp.async.wait_group 0;");
        }
        __syncthreads();
        int st = it % 3;
        unsigned wb  = WsU + (unsigned)(st*WSTG);
        unsigned xb2 = XsU + (unsigned)(st*32*72*2);
        #pragma unroll
        for (int h=0; h<2; h++){
            int kb = h*16;
            unsigned A[4][4];
            #pragma unroll
            for (int ii=0;ii<4;ii++){
                unsigned addr = wb + (unsigned)((((wm*64 + ii*16 + (lane&15))*40) + kb + (lane>>4)*8)*2);
                asm volatile("ldmatrix.sync.aligned.m8n8.x4.shared.b16 {%0,%1,%2,%3}, [%4];"
                    : "=r"(A[ii][0]),"=r"(A[ii][1]),"=r"(A[ii][2]),"=r"(A[ii][3]) : "r"(addr));
            }
            #pragma unroll
            for (int jj=0; jj<4; jj++){
                unsigned Bv[4];
                unsigned baddr = xb2 + (unsigned)((((kb + (lane&7) + 8*((lane>>3)&1))*72) + jj*16 + 8*(lane>>4))*2);
                asm volatile("ldmatrix.sync.aligned.m8n8.x4.trans.shared.b16 {%0,%1,%2,%3}, [%4];"
                    : "=r"(Bv[0]),"=r"(Bv[1]),"=r"(Bv[2]),"=r"(Bv[3]) : "r"(baddr));
                #pragma unroll
                for (int ii=0;ii<4;ii++)
                    #pragma unroll
                    for (int j=0;j<2;j++){
                        float* d = acc[ii][jj][j];
                        asm volatile("mma.sync.aligned.m16n8k16.row.col.f32.bf16.bf16.f32 "
                            "{%0,%1,%2,%3},{%4,%5,%6,%7},{%8,%9},{%0,%1,%2,%3};"
                            : "+f"(d[0]),"+f"(d[1]),"+f"(d[2]),"+f"(d[3])
                            : "r"(A[ii][0]),"r"(A[ii][1]),"r"(A[ii][2]),"r"(A[ii][3]),
                              "r"(Bv[j*2]),"r"(Bv[j*2+1]));
                    }
            }
        }
        __syncthreads();
    }

    if (STAT==1){
        __shared__ float2 sgn[8];
        float s=0.f, sq=0.f;
        #pragma unroll
        for (int ii=0;ii<4;ii++)
            #pragma unroll
            for (int jj=0;jj<4;jj++)
                #pragma unroll
                for (int j=0;j<2;j++)
                    #pragma unroll
                    for (int r=0;r<4;r++){
                        float v = acc[ii][jj][j][r];
                        s += v; sq += v*v;
                    }
        #pragma unroll
        for (int off=16; off; off>>=1){
            s  += __shfl_xor_sync(0xffffffffu, s, off);
            sq += __shfl_xor_sync(0xffffffffu, sq, off);
        }
        if (lane==0) sgn[wm] = make_float2(s, sq);
        __syncthreads();
        if (tid < 8){
            float2 v = sgn[tid];
            g_gnp[((size_t)b*NGRP + tid)*49 + blockIdx.x] = v;
        }
    }

    // epilogue: warp wm owns rows wm*64..wm*64+63 (= GN group wm)
    float bg_mu=0.f, bg_rs=0.f;
    if (STAT==2){ int bg=b*NGRP+wm; bg_mu=g_mu[bg]; bg_rs=g_rstd[bg]; }

    float st_s[4][2], st_t[4][2];
    #pragma unroll
    for (int i=0;i<4;i++){ st_s[i][0]=st_s[i][1]=0.f; st_t[i][0]=st_t[i][1]=0.f; }

    #pragma unroll
    for (int ii=0;ii<4;ii++){
        #pragma unroll
        for (int rr=0;rr<2;rr++){
            int m = wm*64 + ii*16 + rr*8 + (lane>>2);
            float ga=0.f, be=0.f;
            if (STAT==2){ ga=g_gamma[m]; be=g_beta[m]; }
            #pragma unroll
            for (int jj=0;jj<4;jj++){
                #pragma unroll
                for (int j=0;j<2;j++){
                    int c = p0 + jj*16 + j*8 + (lane&3)*2;
                    size_t idx = ((size_t)b*512 + m)*HWN + c;
                    float v0 = acc[ii][jj][j][rr*2+0], v1 = acc[ii][jj][j][rr*2+1];
                    if (STAT==2){
                        float2 hv = ldbf2(aux+idx);
                        float hat0=(hv.x-bg_mu)*bg_rs, hat1=(hv.y-bg_mu)*bg_rs;
                        v0 *= gelu_grad(hat0*ga+be);
                        v1 *= gelu_grad(hat1*ga+be);
                        st_s[ii][rr] += v0+v1;
                        st_t[ii][rr] += v0*hat0 + v1*hat1;
                    }
                    *(unsigned*)(out+idx) = pack_bf2(v0, v1);
                }
            }
        }
    }

    if (STAT==2){
        #pragma unroll
        for (int ii=0;ii<4;ii++)
            #pragma unroll
            for (int rr=0;rr<2;rr++){
                float s=st_s[ii][rr], t=st_t[ii][rr];
                s += __shfl_xor_sync(0xffffffffu, s, 1); t += __shfl_xor_sync(0xffffffffu, t, 1);
                s += __shfl_xor_sync(0xffffffffu, s, 2); t += __shfl_xor_sync(0xffffffffu, t, 2);
                if ((lane&3)==0){
                    int m = wm*64 + ii*16 + rr*8 + (lane>>2);
                    g_rowp[((size_t)b*512 + m)*49 + blockIdx.x] = make_float2(s, t);
                }
            }
    }
}

// ============================================================================
// bf16 tensor-core GEMM (register path) — M<=256 cases.
// XOP: 0 none, 1 X*=mask, 2 X=gelu(X), 3 X=gelu(GN(X))
// EPI: 0 store, 1 +aux, 2 drec, 3 *=gelu'(aux), 4 dy-combine, 5 final out
// STAT: 0 none, 3 chan row partials
// ============================================================================
template<int XOP, int EPI, int BM, int STAT, typename TO>
__global__ __launch_bounds__(256) void gemm_bf16(
    const bft* __restrict__ W, const bft* __restrict__ X, TO* __restrict__ out,
    int M, int K,
    const float* __restrict__ mask, const bft* __restrict__ aux,
    const bft* __restrict__ y, const float* __restrict__ scal)
{
    constexpr int WPp = (BM==64)?4:2;
    constexpr int NJc = (BM==64)?1:2;
    constexpr int WMT = (BM==256)?4:2;
    constexpr int NW  = (BM==256)?4:((BM==128)?2:1);
    __shared__ bft Ws[BM][40];
    __shared__ bft Xs[32][72];
    __shared__ float2 srow[BM][2];
    int b  = blockIdx.z;
    int m0 = blockIdx.y*BM, p0 = blockIdx.x*64;
    const bft* Xb = X + (size_t)b*K*HWN;
    int tid  = threadIdx.x;
    int lane = tid & 31, warp = tid >> 5;
    int wm = warp / WPp, wp = warp % WPp;
    float acc[WMT][NJc][2][4] = {};

    int xk = tid>>3, xc = (tid&7)*8;
    float mv[8];
    if (XOP==1){
        const float* mr = mask + (size_t)b*HWN + p0 + xc;
        float4 a=*(const float4*)mr, b2=*(const float4*)(mr+4);
        mv[0]=a.x;mv[1]=a.y;mv[2]=a.z;mv[3]=a.w;mv[4]=b2.x;mv[5]=b2.y;mv[6]=b2.z;mv[7]=b2.w;
    }

    uint4 wreg[NW];
    uint4 xreg;

    auto load_tile = [&](int k0){
        const bft* w;
        if (BM==256)      w = W + (size_t)(m0 + tid)*K + k0;
        else if (BM==128) w = W + (size_t)(m0 + (tid>>1))*K + k0 + (tid&1)*16;
        else              w = W + (size_t)(m0 + (tid>>2))*K + k0 + (tid&3)*8;
        #pragma unroll
        for (int q=0;q<NW;q++) wreg[q] = *(const uint4*)(w + q*8);
        xreg = *(const uint4*)(Xb + (size_t)(k0+xk)*HWN + p0 + xc);
    };

    auto store_tile = [&](int k0){
        if (BM==256){
            #pragma unroll
            for (int q=0;q<NW;q++) *(uint4*)&Ws[tid][q*8] = wreg[q];
        } else if (BM==128){
            int row=tid>>1, c=(tid&1)*16;
            *(uint4*)&Ws[row][c]   = wreg[0];
            *(uint4*)&Ws[row][c+8] = wreg[1];
        } else {
            int row=tid>>2, c=(tid&3)*8;
            *(uint4*)&Ws[row][c] = wreg[0];
        }
        if (XOP==0){
            *(uint4*)&Xs[xk][xc] = xreg;
        } else {
            float vv[8]; unpack8(xreg, vv);
            if (XOP==1){
                #pragma unroll
                for (int j=0;j<8;j++) vv[j] *= mv[j];
            } else if (XOP==2){
                #pragma unroll
                for (int j=0;j<8;j++) vv[j] = geluf(vv[j]);
            } else {
                int o = k0 + xk;
                int bg = b*NGRP + o/CGg;
                float mu=g_mu[bg], rs=g_rstd[bg], ga=g_gamma[o], be=g_beta[o];
                #pragma unroll
                for (int j=0;j<8;j++) vv[j] = geluf((vv[j]-mu)*rs*ga + be);
            }
            *(uint4*)&Xs[xk][xc] = pack8(vv);
        }
    };

    const int NK = K >> 5;
    load_tile(0);
    for (int i = 0; i < NK; i++){
        store_tile(i*32);
        __syncthreads();
        if (i+1 < NK) load_tile((i+1)*32);

        #pragma unroll
        for (int h=0; h<2; h++){
            int kb = h*16;
            unsigned A[WMT][4];
            #pragma unroll
            for (int ii=0;ii<WMT;ii++){
                unsigned addr = smem_u32(&Ws[wm*(WMT*16) + ii*16 + (lane&15)][kb + (lane>>4)*8]);
                asm volatile("ldmatrix.sync.aligned.m8n8.x4.shared.b16 {%0,%1,%2,%3}, [%4];"
                    : "=r"(A[ii][0]),"=r"(A[ii][1]),"=r"(A[ii][2]),"=r"(A[ii][3]) : "r"(addr));
            }
            #pragma unroll
            for (int jj=0; jj<NJc; jj++){
                unsigned Bv[4];
                unsigned baddr = smem_u32(&Xs[kb + (lane&7) + 8*((lane>>3)&1)][wp*(NJc*16) + jj*16 + 8*(lane>>4)]);
                asm volatile("ldmatrix.sync.aligned.m8n8.x4.trans.shared.b16 {%0,%1,%2,%3}, [%4];"
                    : "=r"(Bv[0]),"=r"(Bv[1]),"=r"(Bv[2]),"=r"(Bv[3]) : "r"(baddr));
                #pragma unroll
                for (int ii=0;ii<WMT;ii++)
                    #pragma unroll
                    for (int j=0;j<2;j++){
                        float* d = acc[ii][jj][j];
                        asm volatile("mma.sync.aligned.m16n8k16.row.col.f32.bf16.bf16.f32 "
                            "{%0,%1,%2,%3},{%4,%5,%6,%7},{%8,%9},{%0,%1,%2,%3};"
                            : "+f"(d[0]),"+f"(d[1]),"+f"(d[2]),"+f"(d[3])
                            : "r"(A[ii][0]),"r"(A[ii][1]),"r"(A[ii][2]),"r"(A[ii][3]),
                              "r"(Bv[j*2]),"r"(Bv[j*2+1]));
                    }
            }
        }
        __syncthreads();
    }

    float st_s[WMT][2];
    float st_t[WMT][2];
    #pragma unroll
    for (int i=0;i<WMT;i++){ st_s[i][0]=st_s[i][1]=0.f; st_t[i][0]=st_t[i][1]=0.f; }

    #pragma unroll
    for (int i=0;i<WMT;i++){
        int rbase = m0 + wm*(WMT*16) + i*16 + (lane>>2);
        #pragma unroll
        for (int jj=0;jj<NJc;jj++){
            #pragma unroll
            for (int j=0;j<2;j++){
                int c = p0 + wp*(NJc*16) + jj*16 + j*8 + (lane&3)*2;
                #pragma unroll
                for (int rr=0; rr<2; rr++){
                    int m = rbase + rr*8;
                    size_t idx = ((size_t)b*M + m)*HWN + c;
                    float v0 = acc[i][jj][j][rr*2+0], v1 = acc[i][jj][j][rr*2+1];
                    if (EPI==1){
                        float2 a = ldbf2(aux+idx);
                        v0 += a.x; v1 += a.y;
                    } else if (EPI==2){
                        float sc = scal[0];
                        size_t mi = (size_t)b*HWN + c;
                        float2 mk = *(const float2*)(mask+mi);
                        float2 yv = ldbf2(y+idx);
                        v0 = (v0 - yv.x)*(1.0f-mk.x)*sc;
                        v1 = (v1 - yv.y)*(1.0f-mk.y)*sc;
                    } else if (EPI==3){
                        float2 a = ldbf2(aux+idx);
                        v0 *= gelu_grad(a.x); v1 *= gelu_grad(a.y);
                    } else if (EPI==4){
                        size_t mi = (size_t)b*HWN + c;
                        float2 mk = *(const float2*)(mask+mi);
                        float2 a  = ldbf2(aux+idx);
                        float2 yv = ldbf2(y+idx);
                        float cA = g_cA[m], cB = g_cB[m], cm = g_cm[m];
                        v0 = v0*mk.x - a.x + cA + cB*(yv.x-cm);
                        v1 = v1*mk.y - a.y + cA + cB*(yv.y-cm);
                    } else if (EPI==5){
                        float sc = scal[0]*g_gate[b];
                        float2 xf = *(const float2*)(mask+idx);   // mask = x (fp32)
                        v0 = xf.x + sc*v0; v1 = xf.y + sc*v1;
                    }
                    if (STAT==3){
                        st_s[i][rr] += v0+v1;
                        st_t[i][rr] += v0*v0 + v1*v1;
                    }
                    if (sizeof(TO)==4)
                        *(float2*)((float*)out+idx) = make_float2(v0, v1);
                    else
                        *(unsigned*)((bft*)out+idx) = pack_bf2(v0, v1);
                }
            }
        }
    }

    if (STAT==3){
        #pragma unroll
        for (int i=0;i<WMT;i++)
            #pragma unroll
            for (int rr=0;rr<2;rr++){
                float s=st_s[i][rr], t=st_t[i][rr];
                s += __shfl_xor_sync(0xffffffffu, s, 1); t += __shfl_xor_sync(0xffffffffu, t, 1);
                s += __shfl_xor_sync(0xffffffffu, s, 2); t += __shfl_xor_sync(0xffffffffu, t, 2);
                if ((lane&3)==0) srow[wm*(WMT*16) + i*16 + rr*8 + (lane>>2)][wp] = make_float2(s, t);
            }
        __syncthreads();
        if (tid < BM){
            float2 a = srow[tid][0], b2 = srow[tid][1];
            g_rowp[((size_t)b*M + m0 + tid)*49 + blockIdx.x] = make_float2(a.x+b2.x, a.y+b2.y);
        }
    }
}

__global__ void gn_reduce(){
    int bg = threadIdx.x;  // 128
    float s=0.f, sq=0.f;
    for (int i=0;i<49;i++){
        float2 v = g_gnp[(size_t)bg*49 + i];
        s += v.x; sq += v.y;
    }
    float n = (float)(CGg*HWN);
    float mean = s/n;
    float var  = sq/n - mean*mean;
    g_mu[bg] = mean;
    g_rstd[bg] = rsqrtf(var + 1e-5f);
}

__global__ void dgn_rowreduce(){
    int idx = blockIdx.x*blockDim.x + threadIdx.x;
    float s=0.f, t=0.f;
    for (int x=0; x<49; x++){
        float2 v = g_rowp[(size_t)idx*49 + x];
        s += v.x; t += v.y;
    }
    g_part[idx*2+0] = s;
    g_part[idx*2+1] = t;
}

__global__ void chan_reduce(const float* __restrict__ rm, const float* __restrict__ rv){
    int c = blockIdx.x;
    float s=0.f, sq=0.f;
    for (int i=threadIdx.x; i<BN*49; i+=256){
        int b=i/49, x=i%49;
        float2 v = g_rowp[((size_t)b*CC + c)*49 + x];
        s += v.x; sq += v.y;
    }
    block_reduce2(s, sq);
    if (threadIdx.x==0){
        float n = (float)NTOT;
        float cm = s/n;
        float cv = (sq - n*cm*cm)/(n - 1.0f);
        float rve = rv[c] + 1e-8f;
        g_cm[c] = cm;
        g_cA[c] = 0.1f*2.0f*(cm - rm[c])/(256.0f*n);
        g_cB[c] = 0.1f*4.0f*(cv/rve - 1.0f)/(rve*256.0f*(n - 1.0f));
    }
}

// ============================================================================
// NT GEMM 128x128, double-buffered.
// XOPB: 0 none, 3 B'=gelu(GN(B));  XOPA: 0 none, 1 A'=dh1 from stored dgn
// ============================================================================
template<int XOPB, int XOPA>
__global__ __launch_bounds__(256) void gemm_nt_bf16(
    const bft* __restrict__ A, const bft* __restrict__ Bm, const bft* __restrict__ Hm,
    float* __restrict__ part, int Ma, int Nb)
{
    __shared__ bft As[2][128][40];
    __shared__ bft Bs[2][128][40];
    int z  = blockIdx.z;
    int m0 = blockIdx.y*128, n0 = blockIdx.x*128;
    int tid  = threadIdx.x;
    int lane = tid & 31, warp = tid >> 5;
    int wm = warp >> 1, wp = warp & 1;
    float acc[2][8][4] = {};

    int r  = tid >> 1, c0 = (tid & 1)*16;

    #define POFF(it) ((((it)%PBZ)*SPLITK + z)*32)
    #define AP(it) (A  + ((size_t)((it)/PBZ)*Ma + m0 + r)*HWN + POFF(it) + c0)
    #define BP(it) (Bm + ((size_t)((it)/PBZ)*Nb + n0 + r)*HWN + POFF(it) + c0)
    #define HP(it) (Hm + ((size_t)((it)/PBZ)*Ma + m0 + r)*HWN + POFF(it) + c0)

    uint4 a0, a1, b0, b1, h0, h1;
    auto load_it = [&](int it){
        a0 = *(const uint4*)AP(it); a1 = *(const uint4*)(AP(it)+8);
        b0 = *(const uint4*)BP(it); b1 = *(const uint4*)(BP(it)+8);
        if (XOPA==1){ h0 = *(const uint4*)HP(it); h1 = *(const uint4*)(HP(it)+8); }
    };
    auto store_it = [&](int buf, int it){
        if (XOPA==0){
            *(uint4*)&As[buf][r][c0]   = a0;
            *(uint4*)&As[buf][r][c0+8] = a1;
        } else {
            int b = it/PBZ;
            int o = m0 + r;
            int bg = b*NGRP + o/CGg;
            float mu=g_mu[bg], rs=g_rstd[bg], ga=g_gamma[o];
            float s1=g_s1[bg], s2=g_s2[bg];
            float av[8], hv[8];
            unpack8(a0, av); unpack8(h0, hv);
            #pragma unroll
            for (int j=0;j<8;j++){
                float hat=(hv[j]-mu)*rs;
                av[j] = rs*(av[j]*ga - s1 - hat*s2);
            }
            *(uint4*)&As[buf][r][c0] = pack8(av);
            unpack8(a1, av); unpack8(h1, hv);
            #pragma unroll
            for (int j=0;j<8;j++){
                float hat=(hv[j]-mu)*rs;
                av[j] = rs*(av[j]*ga - s1 - hat*s2);
            }
            *(uint4*)&As[buf][r][c0+8] = pack8(av);
        }
        if (XOPB==0){
            *(uint4*)&Bs[buf][r][c0]   = b0;
            *(uint4*)&Bs[buf][r][c0+8] = b1;
        } else {
            int b = it/PBZ;
            int o = n0 + r;
            int bg = b*NGRP + o/CGg;
            float mu=g_mu[bg], rs=g_rstd[bg], ga=g_gamma[o], be=g_beta[o];
            float v[8];
            unpack8(b0, v);
            #pragma unroll
            for (int j=0;j<8;j++) v[j] = geluf((v[j]-mu)*rs*ga + be);
            *(uint4*)&Bs[buf][r][c0] = pack8(v);
            unpack8(b1, v);
            #pragma unroll
            for (int j=0;j<8;j++) v[j] = geluf((v[j]-mu)*rs*ga + be);
            *(uint4*)&Bs[buf][r][c0+8] = pack8(v);
        }
    };

    load_it(0);
    store_it(0, 0);
    __syncthreads();

    const int ITERS = BN*PBZ;
    for (int it=0; it<ITERS; it++){
        int cur = it & 1;
        if (it+1 < ITERS) load_it(it+1);

        #pragma unroll
        for (int h=0; h<2; h++){
            int kb = h*16;
            unsigned Af[2][4];
            #pragma unroll
            for (int i=0;i<2;i++){
                unsigned addr = smem_u32(&As[cur][wm*32 + i*16 + (lane&15)][kb + (lane>>4)*8]);
                asm volatile("ldmatrix.sync.aligned.m8n8.x4.shared.b16 {%0,%1,%2,%3}, [%4];"
                    : "=r"(Af[i][0]),"=r"(Af[i][1]),"=r"(Af[i][2]),"=r"(Af[i][3]) : "r"(addr));
            }
            #pragma unroll
            for (int jj=0; jj<4; jj++){
                unsigned Bv[4];
                unsigned baddr = smem_u32(&Bs[cur][wp*64 + jj*16 + (lane&7) + 8*(lane>>4)][kb + 8*((lane>>3)&1)]);
                asm volatile("ldmatrix.sync.aligned.m8n8.x4.shared.b16 {%0,%1,%2,%3}, [%4];"
                    : "=r"(Bv[0]),"=r"(Bv[1]),"=r"(Bv[2]),"=r"(Bv[3]) : "r"(baddr));
                #pragma unroll
                for (int i=0;i<2;i++)
                    #pragma unroll
                    for (int j=0;j<2;j++){
                        float* d = acc[i][jj*2+j];
                        asm volatile("mma.sync.aligned.m16n8k16.row.col.f32.bf16.bf16.f32 "
                            "{%0,%1,%2,%3},{%4,%5,%6,%7},{%8,%9},{%0,%1,%2,%3};"
                            : "+f"(d[0]),"+f"(d[1]),"+f"(d[2]),"+f"(d[3])
                            : "r"(Af[i][0]),"r"(Af[i][1]),"r"(Af[i][2]),"r"(Af[i][3]),
                              "r"(Bv[j*2]),"r"(Bv[j*2+1]));
                    }
            }
        }
        if (it+1 < ITERS) store_it(cur^1, it+1);
        __syncthreads();
    }
    #undef AP
    #undef BP
    #undef HP
    #undef POFF

    #pragma unroll
    for (int i=0;i<2;i++){
        int rbase = m0 + wm*32 + i*16 + (lane>>2);
        #pragma unroll
        for (int jc=0;jc<8;jc++){
            int n = n0 + wp*64 + (jc>>1)*16 + (jc&1)*8 + (lane&3)*2;
            #pragma unroll
            for (int rr=0; rr<2; rr++){
                int m = rbase + rr*8;
                size_t idx = ((size_t)z*Ma + m)*Nb + n;
                *(float2*)(part+idx) = make_float2(acc[i][jc][rr*2], acc[i][jc][rr*2+1]);
            }
        }
    }
}

__global__ void reduce_split(const float* __restrict__ part, float* __restrict__ out, int n){
    int i = blockIdx.x*blockDim.x + threadIdx.x;
    if (i < n){
        float s = 0.f;
        for (int z=0; z<SPLITK; z++) s += part[(size_t)z*n + i];
        out[i] = s;
    }
}

__global__ void reduce_part(){
    int t = threadIdx.x;  // 512
    float db=0.f, dga=0.f;
    for (int b=0;b<BN;b++){
        db  += g_part[(b*HIDN+t)*2+0];
        dga += g_part[(b*HIDN+t)*2+1];
    }
    g_dbeta[t]=db; g_dgamma[t]=dga;
    if (t < BN*NGRP){
        int b=t/NGRP, g=t%NGRP;
        float s1=0.f, s2=0.f;
        for (int j=0;j<CGg;j++){
            int o=g*CGg+j;
            float ga=g_gamma[o];
            s1 += ga*g_part[(b*HIDN+o)*2+0];
            s2 += ga*g_part[(b*HIDN+o)*2+1];
        }
        float inv = 1.0f/(float)(CGg*HWN);
        g_s1[t]=s1*inv; g_s2[t]=s2*inv;
    }
}

__global__ void update_params(){
    int i = blockIdx.x*blockDim.x + threadIdx.x;
    if (i < HIDN*CC){
        float v = g_w1[i] - LRc*g_dW1[i];
        g_w1[i]=v; g_w1b[i]=__float2bfloat16(v);
    }
    if (i < CC*HIDN){
        float v = g_w2[i] - LRc*g_dW2[i];
        g_w2[i]=v;
        bft bv=__float2bfloat16(v);
        g_w2b[i]=bv;
        int c=i/HIDN, o=i%HIDN;
        g_w2tb[o*CC+c]=bv;
    }
    if (i < HIDN){ g_gamma[i] -= LRc*g_dgamma[i]; g_beta[i] -= LRc*g_dbeta[i]; }
}

// ---------------- gate path ----------------
__global__ void pooled_kernel(const float* __restrict__ x){
    int c = blockIdx.x, b = blockIdx.y;
    const float4* row = (const float4*)(x + ((size_t)b*CC + c)*HWN);
    float s=0.f, d=0.f;
    for (int i=threadIdx.x; i<HWN/4; i+=256){
        float4 v = row[i];
        s += v.x+v.y+v.z+v.w;
    }
    block_reduce2(s, d);
    if (threadIdx.x==0) g_pooled[b*CC+c] = s/(float)HWN;
}

__global__ void gate_kernel(const float* __restrict__ gw1, const float* __restrict__ gb1,
                            const float* __restrict__ gw2, const float* __restrict__ gb2){
    __shared__ float gh[BN*CU];
    int t = threadIdx.x;
    for (int j=t; j<BN*CU; j+=256){
        int b=j/CU, u=j%CU;
        float s = gb1[u];
        const float* pr = &g_pooled[b*CC];
        const float* wr = &gw1[u*CC];
        for (int c=0;c<CC;c++) s += pr[c]*wr[c];
        gh[j] = geluf(s);
    }
    __syncthreads();
    if (t < BN){
        float s = gb2[0];
        for (int u=0;u<CU;u++) s += gh[t*CU+u]*gw2[u];
        g_gate[t] = 1.0f/(1.0f + expf(-s));
    }
}

// ---------------- host orchestration ----------------
extern "C" void kernel_launch(void* const* d_in, const int* in_sizes, int n_in,
                              void* d_out, int out_size){
    const float* x        = (const float*)d_in[0];
    const float* conv1_w  = (const float*)d_in[1];
    const float* gn_gammaI= (const float*)d_in[2];
    const float* gn_betaI = (const float*)d_in[3];
    const float* conv2_w  = (const float*)d_in[4];
    const float* rw1      = (const float*)d_in[5];
    const float* rw2      = (const float*)d_in[6];
    const float* gw1      = (const float*)d_in[7];
    const float* gb1      = (const float*)d_in[8];
    const float* gw2      = (const float*)d_in[9];
    const float* gb2      = (const float*)d_in[10];
    const float* rscale   = (const float*)d_in[11];
    const float* rm       = (const float*)d_in[12];
    const float* rv       = (const float*)d_in[13];
    const void*  masks    = d_in[14];

    void* p;
    #define SYMF(sym) (cudaGetSymbolAddress(&p, sym), (float*)p)
    #define SYMB(sym) (cudaGetSymbolAddress(&p, sym), (bft*)p)
    bft*   pw1b   = SYMB(g_w1b);
    bft*   pw2b   = SYMB(g_w2b);
    bft*   pw2tb  = SYMB(g_w2tb);
    bft*   prw1b  = SYMB(g_rw1b);
    bft*   prw1tb = SYMB(g_rw1tb);
    bft*   prw2b  = SYMB(g_rw2b);
    bft*   prw2tb = SYMB(g_rw2tb);
    bft*   ph1    = SYMB(g_h1);
    bft*   pdg    = SYMB(g_dg);
    bft*   py     = SYMB(g_y);
    bft*   pdrec  = SYMB(g_drec);
    bft*   pdy    = SYMB(g_dy);
    bft*   ppre   = SYMB(g_pre);
    bft*   pdpre  = SYMB(g_dpre);
    bft*   pxb    = SYMB(g_xb);
    float* psplit = SYMF(g_split);
    float* pdW1   = SYMF(g_dW1);
    float* pdW2   = SYMF(g_dW2);
    float* pmaskf = SYMF(g_maskf);
    float* pdscale= SYMF(g_dscale);
    #undef SYMF
    #undef SYMB

    const int SMEM512 = 3*WSTG + 3*XSTG;   // 136704
    cudaFuncSetAttribute(gemm512<1>, cudaFuncAttributeMaxDynamicSharedMemorySize, SMEM512);
    cudaFuncSetAttribute(gemm512<2>, cudaFuncAttributeMaxDynamicSharedMemorySize, SMEM512);

    // init
    reset_copy<<<512,256>>>(conv1_w, gn_gammaI, gn_betaI, conv2_w, rw1, rw2);
    mask_detect<<<32,256>>>((const unsigned int*)masks);
    convert_x<<<6272,256>>>(x, pxb);

    for (int s=0; s<2; s++){
        const float* mk = pmaskf + (size_t)s*NTOT;
        const float* sc = pdscale + s;

        // forward
        gemm512<1><<<dim3(49,1,BN),256,SMEM512>>>(pw1b, pxb, ph1, nullptr);
        gn_reduce<<<1,128>>>();
        if (s==0){
            mask_convert<<<98,1024>>>(masks);
            inv_scale_kernel<<<2,256>>>();
        }
        gemm_bf16<3,1,256,3,bft><<<dim3(49,1,BN),256>>>(pw2b, ph1,  py,   256,512, nullptr, pxb,   nullptr,nullptr);
        chan_reduce<<<256,256>>>(rm, rv);
        gemm_bf16<1,0, 64,0,bft><<<dim3(49,1,BN),256>>>(prw1b, py,   ppre,  64,256, mk,      nullptr,nullptr,nullptr);
        gemm_bf16<2,2,256,0,bft><<<dim3(49,1,BN),256>>>(prw2b, ppre, pdrec,256, 64, mk,      nullptr, py,    sc);

        // backward through surprise
        gemm_bf16<0,3, 64,0,bft><<<dim3(49,1,BN),256>>>(prw2tb, pdrec, pdpre, 64,256, nullptr, ppre,  nullptr,nullptr);
        gemm_bf16<0,4,256,0,bft><<<dim3(49,1,BN),256>>>(prw1tb, pdpre, pdy,  256, 64, mk,      pdrec, py,     nullptr);

        // backward through modifier (emits dgn + per-row partials)
        gemm512<2><<<dim3(49,1,BN),256,SMEM512>>>(pw2tb, pdy, pdg, ph1);
        dgn_rowreduce<<<32,256>>>();
        reduce_part<<<1,512>>>();

        gemm_nt_bf16<3,0><<<dim3(4,2,SPLITK),256>>>(pdy, ph1, nullptr, psplit, 256,512);
        reduce_split<<<512,256>>>(psplit, pdW2, HIDN*CC);
        gemm_nt_bf16<0,1><<<dim3(2,4,SPLITK),256>>>(pdg, pxb, ph1,     psplit, 512,256);
        reduce_split<<<512,256>>>(psplit, pdW1, HIDN*CC);

        update_params<<<512,256>>>();
    }

    // gate path
    pooled_kernel<<<dim3(CC,BN),256>>>(x);
    gate_kernel<<<1,256>>>(gw1, gb1, gw2, gb2);

    // final forward (fused output)
    gemm512<1><<<dim3(49,1,BN),256,SMEM512>>>(pw1b, pxb, ph1, nullptr);
    gn_reduce<<<1,128>>>();
    gemm_bf16<3,5,256,0,float><<<dim3(49,1,BN),256>>>(pw2b, ph1, (float*)d_out, 256,512, x, nullptr, nullptr, rscale);

    (void)in_sizes; (void)n_in; (void)out_size;
}

// round 12
// speedup vs baseline: 1.5577x; 1.0330x over previous
#include <cuda_runtime.h>
#include <cuda_bf16.h>
#include <cstdint>
#include <math.h>

// ---------------- problem constants ----------------
#define BN    16
#define CC    256
#define HIDN  512
#define NGRP  8
#define CGg   64
#define HWN   3136
#define CU    64
#define NTOT  (BN*HWN)
#define LRc   0.01f
#define SPLITK 98
#define PBZ   1           // (HWN/32)/SPLITK

typedef __nv_bfloat16 bft;

// ---------------- device scratch ----------------
__device__ float g_w1[HIDN*CC];
__device__ float g_w2[CC*HIDN];
__device__ float g_gamma[HIDN];
__device__ float g_beta[HIDN];

__device__ bft g_w1b [HIDN*CC];
__device__ bft g_w2b [CC*HIDN];
__device__ bft g_w2tb[HIDN*CC];
__device__ bft g_rw1b [CU*CC];
__device__ bft g_rw1tb[CC*CU];
__device__ bft g_rw2b [CC*CU];
__device__ bft g_rw2tb[CU*CC];

__device__ bft g_h1 [(size_t)BN*HIDN*HWN];
__device__ bft g_dg [(size_t)BN*HIDN*HWN];   // holds dgn after dg-GEMM
__device__ bft g_y  [(size_t)BN*CC*HWN];
__device__ bft g_drec[(size_t)BN*CC*HWN];
__device__ bft g_dy [(size_t)BN*CC*HWN];
__device__ bft g_pre [(size_t)BN*CU*HWN];
__device__ bft g_dpre[(size_t)BN*CU*HWN];
__device__ bft g_xb [(size_t)BN*CC*HWN];

__device__ float g_mu[BN*NGRP];
__device__ float g_rstd[BN*NGRP];
__device__ float2 g_gnp[BN*NGRP*49];
__device__ float2 g_rowp[(size_t)BN*HIDN*49];
__device__ float g_part[BN*HIDN*2];
__device__ float g_s1[BN*NGRP], g_s2[BN*NGRP];
__device__ float g_dgamma[HIDN], g_dbeta[HIDN];
__device__ float g_cm[CC], g_cA[CC], g_cB[CC];
__device__ float g_split[(size_t)SPLITK*HIDN*CC];
__device__ float g_dW1[HIDN*CC], g_dW2[CC*HIDN];
__device__ float g_maskf[2*NTOT];
__device__ float g_dscale[2];
__device__ float g_pooled[BN*CC];
__device__ float g_gate[BN];
__device__ int   g_flagF, g_flagW;

// ---------------- math helpers ----------------
__device__ __forceinline__ float geluf(float x){
    return 0.5f*x*(1.0f + erff(x*0.70710678118654752440f));
}
__device__ __forceinline__ float gelu_grad(float x){
    float cdf = 0.5f*(1.0f + erff(x*0.70710678118654752440f));
    float pdf = 0.3989422804014327f*__expf(-0.5f*x*x);
    return cdf + x*pdf;
}
__device__ __forceinline__ void block_reduce2(float& a, float& b){
    __shared__ float sa[256], sb[256];
    int t = threadIdx.x;
    sa[t]=a; sb[t]=b; __syncthreads();
    for (int s=128; s>0; s>>=1){
        if (t<s){ sa[t]+=sa[t+s]; sb[t]+=sb[t+s]; }
        __syncthreads();
    }
    a=sa[0]; b=sb[0];
}
__device__ __forceinline__ unsigned pack_bf2(float a, float b){
    __nv_bfloat162 p = __floats2bfloat162_rn(a, b);
    return *(unsigned*)&p;
}
__device__ __forceinline__ unsigned smem_u32(const void* p){
    return (unsigned)__cvta_generic_to_shared(p);
}
__device__ __forceinline__ void unpack8(uint4 u, float* v){
    __nv_bfloat162 p;
    p=*(__nv_bfloat162*)&u.x; v[0]=__low2float(p); v[1]=__high2float(p);
    p=*(__nv_bfloat162*)&u.y; v[2]=__low2float(p); v[3]=__high2float(p);
    p=*(__nv_bfloat162*)&u.z; v[4]=__low2float(p); v[5]=__high2float(p);
    p=*(__nv_bfloat162*)&u.w; v[6]=__low2float(p); v[7]=__high2float(p);
}
__device__ __forceinline__ uint4 pack8(const float* v){
    uint4 u;
    u.x=pack_bf2(v[0],v[1]); u.y=pack_bf2(v[2],v[3]);
    u.z=pack_bf2(v[4],v[5]); u.w=pack_bf2(v[6],v[7]);
    return u;
}
__device__ __forceinline__ float2 ldbf2(const bft* p){
    __nv_bfloat162 v = *(const __nv_bfloat162*)p;
    return make_float2(__low2float(v), __high2float(v));
}

// ---------------- init / mask handling ----------------
__global__ void reset_copy(const float* __restrict__ w1, const float* __restrict__ gam,
                           const float* __restrict__ bet, const float* __restrict__ w2,
                           const float* __restrict__ rw1, const float* __restrict__ rw2){
    int i = blockIdx.x*blockDim.x + threadIdx.x;
    if (i==0){ g_flagF=0; g_flagW=0; }
    if (i < HIDN*CC){ float v=w1[i]; g_w1[i]=v; g_w1b[i]=__float2bfloat16(v); }
    if (i < CC*HIDN){
        float v=w2[i]; g_w2[i]=v;
        bft bv=__float2bfloat16(v);
        g_w2b[i]=bv;
        int c=i/HIDN, o=i%HIDN;
        g_w2tb[o*CC+c]=bv;
    }
    if (i < CU*CC){
        bft bv=__float2bfloat16(rw1[i]);
        g_rw1b[i]=bv;
        int u=i/CC, c=i%CC;
        g_rw1tb[c*CU+u]=bv;
    }
    if (i < CC*CU){
        bft bv=__float2bfloat16(rw2[i]);
        g_rw2b[i]=bv;
        int c=i/CU, u=i%CU;
        g_rw2tb[u*CC+c]=bv;
    }
    if (i < HIDN){ g_gamma[i]=gam[i]; g_beta[i]=bet[i]; }
}

__global__ void mask_detect(const unsigned int* __restrict__ mw){
    int f=0, wd=0;
    for (int i = blockIdx.x*blockDim.x + threadIdx.x; i < 25088; i += gridDim.x*blockDim.x){
        unsigned v = mw[i];
        if (v == 0x3F800000u) f = 1;
        else if (v != 0u && v != 1u) wd = 1;
    }
    if (f)  atomicOr(&g_flagF, 1);
    if (wd) atomicOr(&g_flagW, 1);
}

__global__ void mask_convert(const void* __restrict__ mp){
    int mode = g_flagW ? 2 : (g_flagF ? 1 : 0);
    int n = 2*NTOT;
    for (int i = blockIdx.x*blockDim.x + threadIdx.x; i < n; i += gridDim.x*blockDim.x){
        bool v;
        if (mode==0)      v = ((const int*)mp)[i] != 0;
        else if (mode==1) v = ((const float*)mp)[i] != 0.0f;
        else              v = ((const unsigned char*)mp)[i] != 0;
        g_maskf[i] = v ? 1.0f : 0.0f;
    }
}

__global__ void inv_scale_kernel(){
    int s = blockIdx.x;
    float cnt = 0.f, d = 0.f;
    for (int i = threadIdx.x; i < NTOT; i += 256) cnt += 1.0f - g_maskf[s*NTOT + i];
    block_reduce2(cnt, d);
    if (threadIdx.x==0) g_dscale[s] = 2.0f/(cnt*256.0f + 1e-8f);
}

__global__ void convert_x(const float* __restrict__ x, bft* __restrict__ xb){
    size_t i8 = (size_t)blockIdx.x*blockDim.x + threadIdx.x;
    size_t i = i8*8;
    float4 a = *(const float4*)(x+i);
    float4 b = *(const float4*)(x+i+4);
    float v[8] = {a.x,a.y,a.z,a.w,b.x,b.y,b.z,b.w};
    *(uint4*)(xb+i) = pack8(v);
}

// ============================================================================
// gemm512: M=512, K=256, BP=64, 256 threads, warp tile 64x64,
// 3-stage cp.async pipeline.  (R10-identical)
// STAT 1: GN group partials.  STAT 2: dgn epilogue (stores dgn, row partials).
// ============================================================================
#define WSTG (512*40*2)
#define XSTG (32*72*2)
template<int STAT>
__global__ __launch_bounds__(256) void gemm512(
    const bft* __restrict__ W, const bft* __restrict__ X, bft* __restrict__ out,
    const bft* __restrict__ aux)
{
    extern __shared__ char dsm[];
    const unsigned WsU = smem_u32(dsm);                  // [3][512][40]
    const unsigned XsU = WsU + 3*WSTG;                   // [3][32][72]
    int b  = blockIdx.z;
    int p0 = blockIdx.x*64;
    const bft* Xb = X + (size_t)b*256*HWN;
    int tid  = threadIdx.x;
    int lane = tid & 31, wm = tid >> 5;
    float acc[4][4][2][4] = {};

    auto issue = [&](int it){
        int k0 = it*32;
        int st = it % 3;
        unsigned wb = WsU + (unsigned)(st*WSTG);
        #pragma unroll
        for (int j=0;j<8;j++){
            int chunk = tid + j*256;
            int row = chunk>>2, q = chunk&3;
            unsigned dst = wb + (unsigned)((row*40 + q*8)*2);
            const bft* src = W + (size_t)row*256 + k0 + q*8;
            asm volatile("cp.async.cg.shared.global [%0], [%1], 16;" :: "r"(dst), "l"(src));
        }
        {
            int row = tid>>3, c = (tid&7)*8;
            unsigned dst = XsU + (unsigned)((st*32*72 + row*72 + c)*2);
            const bft* src = Xb + (size_t)(k0+row)*HWN + p0 + c;
            asm volatile("cp.async.cg.shared.global [%0], [%1], 16;" :: "r"(dst), "l"(src));
        }
        asm volatile("cp.async.commit_group;");
    };

    issue(0);
    issue(1);
    #pragma unroll 1
    for (int it = 0; it < 8; it++){
        if (it + 2 < 8){
            issue(it+2);
            asm volatile("cp.async.wait_group 2;");
        } else if (it + 1 < 8){
            asm volatile("cp.async.wait_group 1;");
        } else {
            asm volatile("cp.async.wait_group 0;");
        }
        __syncthreads();
        int st = it % 3;
        unsigned wb  = WsU + (unsigned)(st*WSTG);
        unsigned xb2 = XsU + (unsigned)(st*32*72*2);
        #pragma unroll
        for (int h=0; h<2; h++){
            int kb = h*16;
            unsigned A[4][4];
            #pragma unroll
            for (int ii=0;ii<4;ii++){
                unsigned addr = wb + (unsigned)((((wm*64 + ii*16 + (lane&15))*40) + kb + (lane>>4)*8)*2);
                asm volatile("ldmatrix.sync.aligned.m8n8.x4.shared.b16 {%0,%1,%2,%3}, [%4];"
                    : "=r"(A[ii][0]),"=r"(A[ii][1]),"=r"(A[ii][2]),"=r"(A[ii][3]) : "r"(addr));
            }
            #pragma unroll
            for (int jj=0; jj<4; jj++){
                unsigned Bv[4];
                unsigned baddr = xb2 + (unsigned)((((kb + (lane&7) + 8*((lane>>3)&1))*72) + jj*16 + 8*(lane>>4))*2);
                asm volatile("ldmatrix.sync.aligned.m8n8.x4.trans.shared.b16 {%0,%1,%2,%3}, [%4];"
                    : "=r"(Bv[0]),"=r"(Bv[1]),"=r"(Bv[2]),"=r"(Bv[3]) : "r"(baddr));
                #pragma unroll
                for (int ii=0;ii<4;ii++)
                    #pragma unroll
                    for (int j=0;j<2;j++){
                        float* d = acc[ii][jj][j];
                        asm volatile("mma.sync.aligned.m16n8k16.row.col.f32.bf16.bf16.f32 "
                            "{%0,%1,%2,%3},{%4,%5,%6,%7},{%8,%9},{%0,%1,%2,%3};"
                            : "+f"(d[0]),"+f"(d[1]),"+f"(d[2]),"+f"(d[3])
                            : "r"(A[ii][0]),"r"(A[ii][1]),"r"(A[ii][2]),"r"(A[ii][3]),
                              "r"(Bv[j*2]),"r"(Bv[j*2+1]));
                    }
            }
        }
        __syncthreads();
    }

    if (STAT==1){
        __shared__ float2 sgn[8];
        float s=0.f, sq=0.f;
        #pragma unroll
        for (int ii=0;ii<4;ii++)
            #pragma unroll
            for (int jj=0;jj<4;jj++)
                #pragma unroll
                for (int j=0;j<2;j++)
                    #pragma unroll
                    for (int r=0;r<4;r++){
                        float v = acc[ii][jj][j][r];
                        s += v; sq += v*v;
                    }
        #pragma unroll
        for (int off=16; off; off>>=1){
            s  += __shfl_xor_sync(0xffffffffu, s, off);
            sq += __shfl_xor_sync(0xffffffffu, sq, off);
        }
        if (lane==0) sgn[wm] = make_float2(s, sq);
        __syncthreads();
        if (tid < 8){
            float2 v = sgn[tid];
            g_gnp[((size_t)b*NGRP + tid)*49 + blockIdx.x] = v;
        }
    }

    // epilogue: warp wm owns rows wm*64..wm*64+63 (= GN group wm)
    float bg_mu=0.f, bg_rs=0.f;
    if (STAT==2){ int bg=b*NGRP+wm; bg_mu=g_mu[bg]; bg_rs=g_rstd[bg]; }

    float st_s[4][2], st_t[4][2];
    #pragma unroll
    for (int i=0;i<4;i++){ st_s[i][0]=st_s[i][1]=0.f; st_t[i][0]=st_t[i][1]=0.f; }

    #pragma unroll
    for (int ii=0;ii<4;ii++){
        #pragma unroll
        for (int rr=0;rr<2;rr++){
            int m = wm*64 + ii*16 + rr*8 + (lane>>2);
            float ga=0.f, be=0.f;
            if (STAT==2){ ga=g_gamma[m]; be=g_beta[m]; }
            #pragma unroll
            for (int jj=0;jj<4;jj++){
                #pragma unroll
                for (int j=0;j<2;j++){
                    int c = p0 + jj*16 + j*8 + (lane&3)*2;
                    size_t idx = ((size_t)b*512 + m)*HWN + c;
                    float v0 = acc[ii][jj][j][rr*2+0], v1 = acc[ii][jj][j][rr*2+1];
                    if (STAT==2){
                        float2 hv = ldbf2(aux+idx);
                        float hat0=(hv.x-bg_mu)*bg_rs, hat1=(hv.y-bg_mu)*bg_rs;
                        v0 *= gelu_grad(hat0*ga+be);
                        v1 *= gelu_grad(hat1*ga+be);
                        st_s[ii][rr] += v0+v1;
                        st_t[ii][rr] += v0*hat0 + v1*hat1;
                    }
                    *(unsigned*)(out+idx) = pack_bf2(v0, v1);
                }
            }
        }
    }

    if (STAT==2){
        #pragma unroll
        for (int ii=0;ii<4;ii++)
            #pragma unroll
            for (int rr=0;rr<2;rr++){
                float s=st_s[ii][rr], t=st_t[ii][rr];
                s += __shfl_xor_sync(0xffffffffu, s, 1); t += __shfl_xor_sync(0xffffffffu, t, 1);
                s += __shfl_xor_sync(0xffffffffu, s, 2); t += __shfl_xor_sync(0xffffffffu, t, 2);
                if ((lane&3)==0){
                    int m = wm*64 + ii*16 + rr*8 + (lane>>2);
                    g_rowp[((size_t)b*512 + m)*49 + blockIdx.x] = make_float2(s, t);
                }
            }
    }
}

// ============================================================================
// bf16 tensor-core GEMM (register path) — M<=256 cases.
// XOP: 0 none, 1 X*=mask, 2 X=gelu(X), 3 X=gelu(GN(X))
// EPI: 0 store, 1 +aux, 2 drec, 3 *=gelu'(aux), 4 dy-combine, 5 final out
// STAT: 0 none, 3 chan row partials
// ============================================================================
template<int XOP, int EPI, int BM, int STAT, typename TO>
__global__ __launch_bounds__(256,2) void gemm_bf16(
    const bft* __restrict__ W, const bft* __restrict__ X, TO* __restrict__ out,
    int M, int K,
    const float* __restrict__ mask, const bft* __restrict__ aux,
    const bft* __restrict__ y, const float* __restrict__ scal)
{
    constexpr int WPp = (BM==64)?4:2;
    constexpr int NJc = (BM==64)?1:2;
    constexpr int WMT = (BM==256)?4:2;
    constexpr int NW  = (BM==256)?4:((BM==128)?2:1);
    __shared__ bft Ws[BM][40];
    __shared__ bft Xs[32][72];
    __shared__ float2 srow[BM][2];
    int b  = blockIdx.z;
    int m0 = blockIdx.y*BM, p0 = blockIdx.x*64;
    const bft* Xb = X + (size_t)b*K*HWN;
    int tid  = threadIdx.x;
    int lane = tid & 31, warp = tid >> 5;
    int wm = warp / WPp, wp = warp % WPp;
    float acc[WMT][NJc][2][4] = {};

    int xk = tid>>3, xc = (tid&7)*8;
    float mv[8];
    if (XOP==1){
        const float* mr = mask + (size_t)b*HWN + p0 + xc;
        float4 a=*(const float4*)mr, b2=*(const float4*)(mr+4);
        mv[0]=a.x;mv[1]=a.y;mv[2]=a.z;mv[3]=a.w;mv[4]=b2.x;mv[5]=b2.y;mv[6]=b2.z;mv[7]=b2.w;
    }

    uint4 wreg[NW];
    uint4 xreg;

    auto load_tile = [&](int k0){
        const bft* w;
        if (BM==256)      w = W + (size_t)(m0 + tid)*K + k0;
        else if (BM==128) w = W + (size_t)(m0 + (tid>>1))*K + k0 + (tid&1)*16;
        else              w = W + (size_t)(m0 + (tid>>2))*K + k0 + (tid&3)*8;
        #pragma unroll
        for (int q=0;q<NW;q++) wreg[q] = *(const uint4*)(w + q*8);
        xreg = *(const uint4*)(Xb + (size_t)(k0+xk)*HWN + p0 + xc);
    };

    auto store_tile = [&](int k0){
        if (BM==256){
            #pragma unroll
            for (int q=0;q<NW;q++) *(uint4*)&Ws[tid][q*8] = wreg[q];
        } else if (BM==128){
            int row=tid>>1, c=(tid&1)*16;
            *(uint4*)&Ws[row][c]   = wreg[0];
            *(uint4*)&Ws[row][c+8] = wreg[1];
        } else {
            int row=tid>>2, c=(tid&3)*8;
            *(uint4*)&Ws[row][c] = wreg[0];
        }
        if (XOP==0){
            *(uint4*)&Xs[xk][xc] = xreg;
        } else {
            float vv[8]; unpack8(xreg, vv);
            if (XOP==1){
                #pragma unroll
                for (int j=0;j<8;j++) vv[j] *= mv[j];
            } else if (XOP==2){
                #pragma unroll
                for (int j=0;j<8;j++) vv[j] = geluf(vv[j]);
            } else {
                int o = k0 + xk;
                int bg = b*NGRP + o/CGg;
                float mu=g_mu[bg], rs=g_rstd[bg], ga=g_gamma[o], be=g_beta[o];
                #pragma unroll
                for (int j=0;j<8;j++) vv[j] = geluf((vv[j]-mu)*rs*ga + be);
            }
            *(uint4*)&Xs[xk][xc] = pack8(vv);
        }
    };

    const int NK = K >> 5;
    load_tile(0);
    for (int i = 0; i < NK; i++){
        store_tile(i*32);
        __syncthreads();
        if (i+1 < NK) load_tile((i+1)*32);

        #pragma unroll
        for (int h=0; h<2; h++){
            int kb = h*16;
            unsigned A[WMT][4];
            #pragma unroll
            for (int ii=0;ii<WMT;ii++){
                unsigned addr = smem_u32(&Ws[wm*(WMT*16) + ii*16 + (lane&15)][kb + (lane>>4)*8]);
                asm volatile("ldmatrix.sync.aligned.m8n8.x4.shared.b16 {%0,%1,%2,%3}, [%4];"
                    : "=r"(A[ii][0]),"=r"(A[ii][1]),"=r"(A[ii][2]),"=r"(A[ii][3]) : "r"(addr));
            }
            #pragma unroll
            for (int jj=0; jj<NJc; jj++){
                unsigned Bv[4];
                unsigned baddr = smem_u32(&Xs[kb + (lane&7) + 8*((lane>>3)&1)][wp*(NJc*16) + jj*16 + 8*(lane>>4)]);
                asm volatile("ldmatrix.sync.aligned.m8n8.x4.trans.shared.b16 {%0,%1,%2,%3}, [%4];"
                    : "=r"(Bv[0]),"=r"(Bv[1]),"=r"(Bv[2]),"=r"(Bv[3]) : "r"(baddr));
                #pragma unroll
                for (int ii=0;ii<WMT;ii++)
                    #pragma unroll
                    for (int j=0;j<2;j++){
                        float* d = acc[ii][jj][j];
                        asm volatile("mma.sync.aligned.m16n8k16.row.col.f32.bf16.bf16.f32 "
                            "{%0,%1,%2,%3},{%4,%5,%6,%7},{%8,%9},{%0,%1,%2,%3};"
                            : "+f"(d[0]),"+f"(d[1]),"+f"(d[2]),"+f"(d[3])
                            : "r"(A[ii][0]),"r"(A[ii][1]),"r"(A[ii][2]),"r"(A[ii][3]),
                              "r"(Bv[j*2]),"r"(Bv[j*2+1]));
                    }
            }
        }
        __syncthreads();
    }

    float st_s[WMT][2];
    float st_t[WMT][2];
    #pragma unroll
    for (int i=0;i<WMT;i++){ st_s[i][0]=st_s[i][1]=0.f; st_t[i][0]=st_t[i][1]=0.f; }

    #pragma unroll
    for (int i=0;i<WMT;i++){
        int rbase = m0 + wm*(WMT*16) + i*16 + (lane>>2);
        #pragma unroll
        for (int jj=0;jj<NJc;jj++){
            #pragma unroll
            for (int j=0;j<2;j++){
                int c = p0 + wp*(NJc*16) + jj*16 + j*8 + (lane&3)*2;
                #pragma unroll
                for (int rr=0; rr<2; rr++){
                    int m = rbase + rr*8;
                    size_t idx = ((size_t)b*M + m)*HWN + c;
                    float v0 = acc[i][jj][j][rr*2+0], v1 = acc[i][jj][j][rr*2+1];
                    if (EPI==1){
                        float2 a = ldbf2(aux+idx);
                        v0 += a.x; v1 += a.y;
                    } else if (EPI==2){
                        float sc = scal[0];
                        size_t mi = (size_t)b*HWN + c;
                        float2 mk = *(const float2*)(mask+mi);
                        float2 yv = ldbf2(y+idx);
                        v0 = (v0 - yv.x)*(1.0f-mk.x)*sc;
                        v1 = (v1 - yv.y)*(1.0f-mk.y)*sc;
                    } else if (EPI==3){
                        float2 a = ldbf2(aux+idx);
                        v0 *= gelu_grad(a.x); v1 *= gelu_grad(a.y);
                    } else if (EPI==4){
                        size_t mi = (size_t)b*HWN + c;
                        float2 mk = *(const float2*)(mask+mi);
                        float2 a  = ldbf2(aux+idx);
                        float2 yv = ldbf2(y+idx);
                        float cA = g_cA[m], cB = g_cB[m], cm = g_cm[m];
                        v0 = v0*mk.x - a.x + cA + cB*(yv.x-cm);
                        v1 = v1*mk.y - a.y + cA + cB*(yv.y-cm);
                    } else if (EPI==5){
                        float sc = scal[0]*g_gate[b];
                        float2 xf = *(const float2*)(mask+idx);   // mask = x (fp32)
                        v0 = xf.x + sc*v0; v1 = xf.y + sc*v1;
                    }
                    if (STAT==3){
                        st_s[i][rr] += v0+v1;
                        st_t[i][rr] += v0*v0 + v1*v1;
                    }
                    if (sizeof(TO)==4)
                        *(float2*)((float*)out+idx) = make_float2(v0, v1);
                    else
                        *(unsigned*)((bft*)out+idx) = pack_bf2(v0, v1);
                }
            }
        }
    }

    if (STAT==3){
        #pragma unroll
        for (int i=0;i<WMT;i++)
            #pragma unroll
            for (int rr=0;rr<2;rr++){
                float s=st_s[i][rr], t=st_t[i][rr];
                s += __shfl_xor_sync(0xffffffffu, s, 1); t += __shfl_xor_sync(0xffffffffu, t, 1);
                s += __shfl_xor_sync(0xffffffffu, s, 2); t += __shfl_xor_sync(0xffffffffu, t, 2);
                if ((lane&3)==0) srow[wm*(WMT*16) + i*16 + rr*8 + (lane>>2)][wp] = make_float2(s, t);
            }
        __syncthreads();
        if (tid < BM){
            float2 a = srow[tid][0], b2 = srow[tid][1];
            g_rowp[((size_t)b*M + m0 + tid)*49 + blockIdx.x] = make_float2(a.x+b2.x, a.y+b2.y);
        }
    }
}

__global__ void gn_reduce(){
    int bg = threadIdx.x;  // 128
    float s=0.f, sq=0.f;
    for (int i=0;i<49;i++){
        float2 v = g_gnp[(size_t)bg*49 + i];
        s += v.x; sq += v.y;
    }
    float n = (float)(CGg*HWN);
    float mean = s/n;
    float var  = sq/n - mean*mean;
    g_mu[bg] = mean;
    g_rstd[bg] = rsqrtf(var + 1e-5f);
}

__global__ void dgn_rowreduce(){
    int idx = blockIdx.x*blockDim.x + threadIdx.x;
    float s=0.f, t=0.f;
    for (int x=0; x<49; x++){
        float2 v = g_rowp[(size_t)idx*49 + x];
        s += v.x; t += v.y;
    }
    g_part[idx*2+0] = s;
    g_part[idx*2+1] = t;
}

__global__ void chan_reduce(const float* __restrict__ rm, const float* __restrict__ rv){
    int c = blockIdx.x;
    float s=0.f, sq=0.f;
    for (int i=threadIdx.x; i<BN*49; i+=256){
        int b=i/49, x=i%49;
        float2 v = g_rowp[((size_t)b*CC + c)*49 + x];
        s += v.x; sq += v.y;
    }
    block_reduce2(s, sq);
    if (threadIdx.x==0){
        float n = (float)NTOT;
        float cm = s/n;
        float cv = (sq - n*cm*cm)/(n - 1.0f);
        float rve = rv[c] + 1e-8f;
        g_cm[c] = cm;
        g_cA[c] = 0.1f*2.0f*(cm - rm[c])/(256.0f*n);
        g_cB[c] = 0.1f*4.0f*(cv/rve - 1.0f)/(rve*256.0f*(n - 1.0f));
    }
}

// ============================================================================
// NT GEMM 128x128, double-buffered.
// XOPB: 0 none, 3 B'=gelu(GN(B));  XOPA: 0 none, 1 A'=dh1 from stored dgn
// ============================================================================
template<int XOPB, int XOPA>
__global__ __launch_bounds__(256,2) void gemm_nt_bf16(
    const bft* __restrict__ A, const bft* __restrict__ Bm, const bft* __restrict__ Hm,
    float* __restrict__ part, int Ma, int Nb)
{
    __shared__ bft As[2][128][40];
    __shared__ bft Bs[2][128][40];
    int z  = blockIdx.z;
    int m0 = blockIdx.y*128, n0 = blockIdx.x*128;
    int tid  = threadIdx.x;
    int lane = tid & 31, warp = tid >> 5;
    int wm = warp >> 1, wp = warp & 1;
    float acc[2][8][4] = {};

    int r  = tid >> 1, c0 = (tid & 1)*16;

    #define POFF(it) ((((it)%PBZ)*SPLITK + z)*32)
    #define AP(it) (A  + ((size_t)((it)/PBZ)*Ma + m0 + r)*HWN + POFF(it) + c0)
    #define BP(it) (Bm + ((size_t)((it)/PBZ)*Nb + n0 + r)*HWN + POFF(it) + c0)
    #define HP(it) (Hm + ((size_t)((it)/PBZ)*Ma + m0 + r)*HWN + POFF(it) + c0)

    uint4 a0, a1, b0, b1, h0, h1;
    auto load_it = [&](int it){
        a0 = *(const uint4*)AP(it); a1 = *(const uint4*)(AP(it)+8);
        b0 = *(const uint4*)BP(it); b1 = *(const uint4*)(BP(it)+8);
        if (XOPA==1){ h0 = *(const uint4*)HP(it); h1 = *(const uint4*)(HP(it)+8); }
    };
    auto store_it = [&](int buf, int it){
        if (XOPA==0){
            *(uint4*)&As[buf][r][c0]   = a0;
            *(uint4*)&As[buf][r][c0+8] = a1;
        } else {
            int b = it/PBZ;
            int o = m0 + r;
            int bg = b*NGRP + o/CGg;
            float mu=g_mu[bg], rs=g_rstd[bg], ga=g_gamma[o];
            float s1=g_s1[bg], s2=g_s2[bg];
            float av[8], hv[8];
            unpack8(a0, av); unpack8(h0, hv);
            #pragma unroll
            for (int j=0;j<8;j++){
                float hat=(hv[j]-mu)*rs;
                av[j] = rs*(av[j]*ga - s1 - hat*s2);
            }
            *(uint4*)&As[buf][r][c0] = pack8(av);
            unpack8(a1, av); unpack8(h1, hv);
            #pragma unroll
            for (int j=0;j<8;j++){
                float hat=(hv[j]-mu)*rs;
                av[j] = rs*(av[j]*ga - s1 - hat*s2);
            }
            *(uint4*)&As[buf][r][c0+8] = pack8(av);
        }
        if (XOPB==0){
            *(uint4*)&Bs[buf][r][c0]   = b0;
            *(uint4*)&Bs[buf][r][c0+8] = b1;
        } else {
            int b = it/PBZ;
            int o = n0 + r;
            int bg = b*NGRP + o/CGg;
            float mu=g_mu[bg], rs=g_rstd[bg], ga=g_gamma[o], be=g_beta[o];
            float v[8];
            unpack8(b0, v);
            #pragma unroll
            for (int j=0;j<8;j++) v[j] = geluf((v[j]-mu)*rs*ga + be);
            *(uint4*)&Bs[buf][r][c0] = pack8(v);
            unpack8(b1, v);
            #pragma unroll
            for (int j=0;j<8;j++) v[j] = geluf((v[j]-mu)*rs*ga + be);
            *(uint4*)&Bs[buf][r][c0+8] = pack8(v);
        }
    };

    load_it(0);
    store_it(0, 0);
    __syncthreads();

    const int ITERS = BN*PBZ;
    for (int it=0; it<ITERS; it++){
        int cur = it & 1;
        if (it+1 < ITERS) load_it(it+1);

        #pragma unroll
        for (int h=0; h<2; h++){
            int kb = h*16;
            unsigned Af[2][4];
            #pragma unroll
            for (int i=0;i<2;i++){
                unsigned addr = smem_u32(&As[cur][wm*32 + i*16 + (lane&15)][kb + (lane>>4)*8]);
                asm volatile("ldmatrix.sync.aligned.m8n8.x4.shared.b16 {%0,%1,%2,%3}, [%4];"
                    : "=r"(Af[i][0]),"=r"(Af[i][1]),"=r"(Af[i][2]),"=r"(Af[i][3]) : "r"(addr));
            }
            #pragma unroll
            for (int jj=0; jj<4; jj++){
                unsigned Bv[4];
                unsigned baddr = smem_u32(&Bs[cur][wp*64 + jj*16 + (lane&7) + 8*(lane>>4)][kb + 8*((lane>>3)&1)]);
                asm volatile("ldmatrix.sync.aligned.m8n8.x4.shared.b16 {%0,%1,%2,%3}, [%4];"
                    : "=r"(Bv[0]),"=r"(Bv[1]),"=r"(Bv[2]),"=r"(Bv[3]) : "r"(baddr));
                #pragma unroll
                for (int i=0;i<2;i++)
                    #pragma unroll
                    for (int j=0;j<2;j++){
                        float* d = acc[i][jj*2+j];
                        asm volatile("mma.sync.aligned.m16n8k16.row.col.f32.bf16.bf16.f32 "
                            "{%0,%1,%2,%3},{%4,%5,%6,%7},{%8,%9},{%0,%1,%2,%3};"
                            : "+f"(d[0]),"+f"(d[1]),"+f"(d[2]),"+f"(d[3])
                            : "r"(Af[i][0]),"r"(Af[i][1]),"r"(Af[i][2]),"r"(Af[i][3]),
                              "r"(Bv[j*2]),"r"(Bv[j*2+1]));
                    }
            }
        }
        if (it+1 < ITERS) store_it(cur^1, it+1);
        __syncthreads();
    }
    #undef AP
    #undef BP
    #undef HP
    #undef POFF

    #pragma unroll
    for (int i=0;i<2;i++){
        int rbase = m0 + wm*32 + i*16 + (lane>>2);
        #pragma unroll
        for (int jc=0;jc<8;jc++){
            int n = n0 + wp*64 + (jc>>1)*16 + (jc&1)*8 + (lane&3)*2;
            #pragma unroll
            for (int rr=0; rr<2; rr++){
                int m = rbase + rr*8;
                size_t idx = ((size_t)z*Ma + m)*Nb + n;
                *(float2*)(part+idx) = make_float2(acc[i][jc][rr*2], acc[i][jc][rr*2+1]);
            }
        }
    }
}

__global__ void reduce_split(const float* __restrict__ part, float* __restrict__ out, int n){
    int i = blockIdx.x*blockDim.x + threadIdx.x;
    if (i < n){
        float s = 0.f;
        for (int z=0; z<SPLITK; z++) s += part[(size_t)z*n + i];
        out[i] = s;
    }
}

__global__ void reduce_part(){
    int t = threadIdx.x;  // 512
    float db=0.f, dga=0.f;
    for (int b=0;b<BN;b++){
        db  += g_part[(b*HIDN+t)*2+0];
        dga += g_part[(b*HIDN+t)*2+1];
    }
    g_dbeta[t]=db; g_dgamma[t]=dga;
    if (t < BN*NGRP){
        int b=t/NGRP, g=t%NGRP;
        float s1=0.f, s2=0.f;
        for (int j=0;j<CGg;j++){
            int o=g*CGg+j;
            float ga=g_gamma[o];
            s1 += ga*g_part[(b*HIDN+o)*2+0];
            s2 += ga*g_part[(b*HIDN+o)*2+1];
        }
        float inv = 1.0f/(float)(CGg*HWN);
        g_s1[t]=s1*inv; g_s2[t]=s2*inv;
    }
}

__global__ void update_params(){
    int i = blockIdx.x*blockDim.x + threadIdx.x;
    if (i < HIDN*CC){
        float v = g_w1[i] - LRc*g_dW1[i];
        g_w1[i]=v; g_w1b[i]=__float2bfloat16(v);
    }
    if (i < CC*HIDN){
        float v = g_w2[i] - LRc*g_dW2[i];
        g_w2[i]=v;
        bft bv=__float2bfloat16(v);
        g_w2b[i]=bv;
        int c=i/HIDN, o=i%HIDN;
        g_w2tb[o*CC+c]=bv;
    }
    if (i < HIDN){ g_gamma[i] -= LRc*g_dgamma[i]; g_beta[i] -= LRc*g_dbeta[i]; }
}

// ---------------- gate path ----------------
__global__ void pooled_kernel(const float* __restrict__ x){
    int c = blockIdx.x, b = blockIdx.y;
    const float4* row = (const float4*)(x + ((size_t)b*CC + c)*HWN);
    float s=0.f, d=0.f;
    for (int i=threadIdx.x; i<HWN/4; i+=256){
        float4 v = row[i];
        s += v.x+v.y+v.z+v.w;
    }
    block_reduce2(s, d);
    if (threadIdx.x==0) g_pooled[b*CC+c] = s/(float)HWN;
}

__global__ void gate_kernel(const float* __restrict__ gw1, const float* __restrict__ gb1,
                            const float* __restrict__ gw2, const float* __restrict__ gb2){
    __shared__ float gh[BN*CU];
    int t = threadIdx.x;
    for (int j=t; j<BN*CU; j+=256){
        int b=j/CU, u=j%CU;
        float s = gb1[u];
        const float* pr = &g_pooled[b*CC];
        const float* wr = &gw1[u*CC];
        for (int c=0;c<CC;c++) s += pr[c]*wr[c];
        gh[j] = geluf(s);
    }
    __syncthreads();
    if (t < BN){
        float s = gb2[0];
        for (int u=0;u<CU;u++) s += gh[t*CU+u]*gw2[u];
        g_gate[t] = 1.0f/(1.0f + expf(-s));
    }
}

// ---------------- host orchestration ----------------
extern "C" void kernel_launch(void* const* d_in, const int* in_sizes, int n_in,
                              void* d_out, int out_size){
    const float* x        = (const float*)d_in[0];
    const float* conv1_w  = (const float*)d_in[1];
    const float* gn_gammaI= (const float*)d_in[2];
    const float* gn_betaI = (const float*)d_in[3];
    const float* conv2_w  = (const float*)d_in[4];
    const float* rw1      = (const float*)d_in[5];
    const float* rw2      = (const float*)d_in[6];
    const float* gw1      = (const float*)d_in[7];
    const float* gb1      = (const float*)d_in[8];
    const float* gw2      = (const float*)d_in[9];
    const float* gb2      = (const float*)d_in[10];
    const float* rscale   = (const float*)d_in[11];
    const float* rm       = (const float*)d_in[12];
    const float* rv       = (const float*)d_in[13];
    const void*  masks    = d_in[14];

    void* p;
    #define SYMF(sym) (cudaGetSymbolAddress(&p, sym), (float*)p)
    #define SYMB(sym) (cudaGetSymbolAddress(&p, sym), (bft*)p)
    bft*   pw1b   = SYMB(g_w1b);
    bft*   pw2b   = SYMB(g_w2b);
    bft*   pw2tb  = SYMB(g_w2tb);
    bft*   prw1b  = SYMB(g_rw1b);
    bft*   prw1tb = SYMB(g_rw1tb);
    bft*   prw2b  = SYMB(g_rw2b);
    bft*   prw2tb = SYMB(g_rw2tb);
    bft*   ph1    = SYMB(g_h1);
    bft*   pdg    = SYMB(g_dg);
    bft*   py     = SYMB(g_y);
    bft*   pdrec  = SYMB(g_drec);
    bft*   pdy    = SYMB(g_dy);
    bft*   ppre   = SYMB(g_pre);
    bft*   pdpre  = SYMB(g_dpre);
    bft*   pxb    = SYMB(g_xb);
    float* psplit = SYMF(g_split);
    float* pdW1   = SYMF(g_dW1);
    float* pdW2   = SYMF(g_dW2);
    float* pmaskf = SYMF(g_maskf);
    float* pdscale= SYMF(g_dscale);
    #undef SYMF
    #undef SYMB

    const int SMEM512 = 3*WSTG + 3*XSTG;   // 136704
    cudaFuncSetAttribute(gemm512<1>, cudaFuncAttributeMaxDynamicSharedMemorySize, SMEM512);
    cudaFuncSetAttribute(gemm512<2>, cudaFuncAttributeMaxDynamicSharedMemorySize, SMEM512);

    // init
    reset_copy<<<512,256>>>(conv1_w, gn_gammaI, gn_betaI, conv2_w, rw1, rw2);
    mask_detect<<<32,256>>>((const unsigned int*)masks);
    convert_x<<<6272,256>>>(x, pxb);

    for (int s=0; s<2; s++){
        const float* mk = pmaskf + (size_t)s*NTOT;
        const float* sc = pdscale + s;

        // forward
        gemm512<1><<<dim3(49,1,BN),256,SMEM512>>>(pw1b, pxb, ph1, nullptr);
        gn_reduce<<<1,128>>>();
        if (s==0){
            mask_convert<<<98,1024>>>(masks);
            inv_scale_kernel<<<2,256>>>();
        }
        gemm_bf16<3,1,256,3,bft><<<dim3(49,1,BN),256>>>(pw2b, ph1,  py,   256,512, nullptr, pxb,   nullptr,nullptr);
        chan_reduce<<<256,256>>>(rm, rv);
        gemm_bf16<1,0, 64,0,bft><<<dim3(49,1,BN),256>>>(prw1b, py,   ppre,  64,256, mk,      nullptr,nullptr,nullptr);
        gemm_bf16<2,2,256,0,bft><<<dim3(49,1,BN),256>>>(prw2b, ppre, pdrec,256, 64, mk,      nullptr, py,    sc);

        // backward through surprise
        gemm_bf16<0,3, 64,0,bft><<<dim3(49,1,BN),256>>>(prw2tb, pdrec, pdpre, 64,256, nullptr, ppre,  nullptr,nullptr);
        gemm_bf16<0,4,256,0,bft><<<dim3(49,1,BN),256>>>(prw1tb, pdpre, pdy,  256, 64, mk,      pdrec, py,     nullptr);

        // backward through modifier (emits dgn + per-row partials)
        gemm512<2><<<dim3(49,1,BN),256,SMEM512>>>(pw2tb, pdy, pdg, ph1);
        dgn_rowreduce<<<32,256>>>();
        reduce_part<<<1,512>>>();

        gemm_nt_bf16<3,0><<<dim3(4,2,SPLITK),256>>>(pdy, ph1, nullptr, psplit, 256,512);
        reduce_split<<<512,256>>>(psplit, pdW2, HIDN*CC);
        gemm_nt_bf16<0,1><<<dim3(2,4,SPLITK),256>>>(pdg, pxb, ph1,     psplit, 512,256);
        reduce_split<<<512,256>>>(psplit, pdW1, HIDN*CC);

        update_params<<<512,256>>>();
    }

    // gate path
    pooled_kernel<<<dim3(CC,BN),256>>>(x);
    gate_kernel<<<1,256>>>(gw1, gb1, gw2, gb2);

    // final forward (fused output)
    gemm512<1><<<dim3(49,1,BN),256,SMEM512>>>(pw1b, pxb, ph1, nullptr);
    gn_reduce<<<1,128>>>();
    gemm_bf16<3,5,256,0,float><<<dim3(49,1,BN),256>>>(pw2b, ph1, (float*)d_out, 256,512, x, nullptr, nullptr, rscale);

    (void)in_sizes; (void)n_in; (void)out_size;
}

// round 13
// speedup vs baseline: 1.5844x; 1.0172x over previous
#include <cuda_runtime.h>
#include <cuda_bf16.h>
#include <cstdint>
#include <math.h>

// ---------------- problem constants ----------------
#define BN    16
#define CC    256
#define HIDN  512
#define NGRP  8
#define CGg   64
#define HWN   3136
#define CU    64
#define NTOT  (BN*HWN)
#define LRc   0.01f
#define SPLITK 98
#define PBZ   1           // (HWN/32)/SPLITK

typedef __nv_bfloat16 bft;

// ---------------- device scratch ----------------
__device__ float g_w1[HIDN*CC];
__device__ float g_w2[CC*HIDN];
__device__ float g_gamma[HIDN];
__device__ float g_beta[HIDN];

__device__ bft g_w1b [HIDN*CC];
__device__ bft g_w2b [CC*HIDN];
__device__ bft g_w2tb[HIDN*CC];
__device__ bft g_rw1b [CU*CC];
__device__ bft g_rw1tb[CC*CU];
__device__ bft g_rw2b [CC*CU];
__device__ bft g_rw2tb[CU*CC];

__device__ bft g_h1 [(size_t)BN*HIDN*HWN];
__device__ bft g_dg [(size_t)BN*HIDN*HWN];   // holds dgn after dg-GEMM
__device__ bft g_y  [(size_t)BN*CC*HWN];
__device__ bft g_drec[(size_t)BN*CC*HWN];
__device__ bft g_dy [(size_t)BN*CC*HWN];
__device__ bft g_pre [(size_t)BN*CU*HWN];
__device__ bft g_dpre[(size_t)BN*CU*HWN];
__device__ bft g_xb [(size_t)BN*CC*HWN];

__device__ float g_mu[BN*NGRP];
__device__ float g_rstd[BN*NGRP];
__device__ float2 g_gnp[BN*NGRP*49];
__device__ float2 g_rowp[(size_t)BN*HIDN*49];
__device__ float g_part[BN*HIDN*2];
__device__ float g_s1[BN*NGRP], g_s2[BN*NGRP];
__device__ float g_dgamma[HIDN], g_dbeta[HIDN];
__device__ float g_cm[CC], g_cA[CC], g_cB[CC];
__device__ bft g_split1[(size_t)SPLITK*HIDN*CC];   // dW2 partials (bf16)
__device__ bft g_split2[(size_t)SPLITK*HIDN*CC];   // dW1 partials (bf16)
__device__ float g_maskf[2*NTOT];
__device__ float g_dscale[2];
__device__ float g_pooled[BN*CC];
__device__ float g_gate[BN];
__device__ int   g_flagF, g_flagW;

// ---------------- math helpers ----------------
__device__ __forceinline__ float geluf(float x){
    return 0.5f*x*(1.0f + erff(x*0.70710678118654752440f));
}
__device__ __forceinline__ float gelu_grad(float x){
    float cdf = 0.5f*(1.0f + erff(x*0.70710678118654752440f));
    float pdf = 0.3989422804014327f*__expf(-0.5f*x*x);
    return cdf + x*pdf;
}
__device__ __forceinline__ void block_reduce2(float& a, float& b){
    __shared__ float sa[256], sb[256];
    int t = threadIdx.x;
    sa[t]=a; sb[t]=b; __syncthreads();
    for (int s=128; s>0; s>>=1){
        if (t<s){ sa[t]+=sa[t+s]; sb[t]+=sb[t+s]; }
        __syncthreads();
    }
    a=sa[0]; b=sb[0];
}
__device__ __forceinline__ unsigned pack_bf2(float a, float b){
    __nv_bfloat162 p = __floats2bfloat162_rn(a, b);
    return *(unsigned*)&p;
}
__device__ __forceinline__ unsigned smem_u32(const void* p){
    return (unsigned)__cvta_generic_to_shared(p);
}
__device__ __forceinline__ void unpack8(uint4 u, float* v){
    __nv_bfloat162 p;
    p=*(__nv_bfloat162*)&u.x; v[0]=__low2float(p); v[1]=__high2float(p);
    p=*(__nv_bfloat162*)&u.y; v[2]=__low2float(p); v[3]=__high2float(p);
    p=*(__nv_bfloat162*)&u.z; v[4]=__low2float(p); v[5]=__high2float(p);
    p=*(__nv_bfloat162*)&u.w; v[6]=__low2float(p); v[7]=__high2float(p);
}
__device__ __forceinline__ uint4 pack8(const float* v){
    uint4 u;
    u.x=pack_bf2(v[0],v[1]); u.y=pack_bf2(v[2],v[3]);
    u.z=pack_bf2(v[4],v[5]); u.w=pack_bf2(v[6],v[7]);
    return u;
}
__device__ __forceinline__ float2 ldbf2(const bft* p){
    __nv_bfloat162 v = *(const __nv_bfloat162*)p;
    return make_float2(__low2float(v), __high2float(v));
}

// ---------------- init / mask handling ----------------
__global__ void reset_copy(const float* __restrict__ w1, const float* __restrict__ gam,
                           const float* __restrict__ bet, const float* __restrict__ w2,
                           const float* __restrict__ rw1, const float* __restrict__ rw2){
    int i = blockIdx.x*blockDim.x + threadIdx.x;
    if (i==0){ g_flagF=0; g_flagW=0; }
    if (i < HIDN*CC){ float v=w1[i]; g_w1[i]=v; g_w1b[i]=__float2bfloat16(v); }
    if (i < CC*HIDN){
        float v=w2[i]; g_w2[i]=v;
        bft bv=__float2bfloat16(v);
        g_w2b[i]=bv;
        int c=i/HIDN, o=i%HIDN;
        g_w2tb[o*CC+c]=bv;
    }
    if (i < CU*CC){
        bft bv=__float2bfloat16(rw1[i]);
        g_rw1b[i]=bv;
        int u=i/CC, c=i%CC;
        g_rw1tb[c*CU+u]=bv;
    }
    if (i < CC*CU){
        bft bv=__float2bfloat16(rw2[i]);
        g_rw2b[i]=bv;
        int c=i/CU, u=i%CU;
        g_rw2tb[u*CC+c]=bv;
    }
    if (i < HIDN){ g_gamma[i]=gam[i]; g_beta[i]=bet[i]; }
}

__global__ void mask_detect(const unsigned int* __restrict__ mw){
    int f=0, wd=0;
    for (int i = blockIdx.x*blockDim.x + threadIdx.x; i < 25088; i += gridDim.x*blockDim.x){
        unsigned v = mw[i];
        if (v == 0x3F800000u) f = 1;
        else if (v != 0u && v != 1u) wd = 1;
    }
    if (f)  atomicOr(&g_flagF, 1);
    if (wd) atomicOr(&g_flagW, 1);
}

__global__ void mask_convert(const void* __restrict__ mp){
    int mode = g_flagW ? 2 : (g_flagF ? 1 : 0);
    int n = 2*NTOT;
    for (int i = blockIdx.x*blockDim.x + threadIdx.x; i < n; i += gridDim.x*blockDim.x){
        bool v;
        if (mode==0)      v = ((const int*)mp)[i] != 0;
        else if (mode==1) v = ((const float*)mp)[i] != 0.0f;
        else              v = ((const unsigned char*)mp)[i] != 0;
        g_maskf[i] = v ? 1.0f : 0.0f;
    }
}

__global__ void inv_scale_kernel(){
    int s = blockIdx.x;
    float cnt = 0.f, d = 0.f;
    for (int i = threadIdx.x; i < NTOT; i += 256) cnt += 1.0f - g_maskf[s*NTOT + i];
    block_reduce2(cnt, d);
    if (threadIdx.x==0) g_dscale[s] = 2.0f/(cnt*256.0f + 1e-8f);
}

__global__ void convert_x(const float* __restrict__ x, bft* __restrict__ xb){
    size_t i8 = (size_t)blockIdx.x*blockDim.x + threadIdx.x;
    size_t i = i8*8;
    float4 a = *(const float4*)(x+i);
    float4 b = *(const float4*)(x+i+4);
    float v[8] = {a.x,a.y,a.z,a.w,b.x,b.y,b.z,b.w};
    *(uint4*)(xb+i) = pack8(v);
}

// ============================================================================
// gemm512: M=512, K=256, BP=64, 256 threads, warp tile 64x64,
// 3-stage cp.async pipeline.
// STAT 1: GN group partials.  STAT 2: dgn epilogue (stores dgn, row partials).
// ============================================================================
#define WSTG (512*40*2)
#define XSTG (32*72*2)
template<int STAT>
__global__ __launch_bounds__(256) void gemm512(
    const bft* __restrict__ W, const bft* __restrict__ X, bft* __restrict__ out,
    const bft* __restrict__ aux)
{
    extern __shared__ char dsm[];
    const unsigned WsU = smem_u32(dsm);                  // [3][512][40]
    const unsigned XsU = WsU + 3*WSTG;                   // [3][32][72]
    int b  = blockIdx.z;
    int p0 = blockIdx.x*64;
    const bft* Xb = X + (size_t)b*256*HWN;
    int tid  = threadIdx.x;
    int lane = tid & 31, wm = tid >> 5;
    float acc[4][4][2][4] = {};

    auto issue = [&](int it){
        int k0 = it*32;
        int st = it % 3;
        unsigned wb = WsU + (unsigned)(st*WSTG);
        #pragma unroll
        for (int j=0;j<8;j++){
            int chunk = tid + j*256;
            int row = chunk>>2, q = chunk&3;
            unsigned dst = wb + (unsigned)((row*40 + q*8)*2);
            const bft* src = W + (size_t)row*256 + k0 + q*8;
            asm volatile("cp.async.cg.shared.global [%0], [%1], 16;" :: "r"(dst), "l"(src));
        }
        {
            int row = tid>>3, c = (tid&7)*8;
            unsigned dst = XsU + (unsigned)((st*32*72 + row*72 + c)*2);
            const bft* src = Xb + (size_t)(k0+row)*HWN + p0 + c;
            asm volatile("cp.async.cg.shared.global [%0], [%1], 16;" :: "r"(dst), "l"(src));
        }
        asm volatile("cp.async.commit_group;");
    };

    issue(0);
    issue(1);
    #pragma unroll 1
    for (int it = 0; it < 8; it++){
        if (it + 2 < 8){
            issue(it+2);
            asm volatile("cp.async.wait_group 2;");
        } else if (it + 1 < 8){
            asm volatile("cp.async.wait_group 1;");
        } else {
            asm volatile("cp.async.wait_group 0;");
        }
        __syncthreads();
        int st = it % 3;
        unsigned wb  = WsU + (unsigned)(st*WSTG);
        unsigned xb2 = XsU + (unsigned)(st*32*72*2);
        #pragma unroll
        for (int h=0; h<2; h++){
            int kb = h*16;
            unsigned A[4][4];
            #pragma unroll
            for (int ii=0;ii<4;ii++){
                unsigned addr = wb + (unsigned)((((wm*64 + ii*16 + (lane&15))*40) + kb + (lane>>4)*8)*2);
                asm volatile("ldmatrix.sync.aligned.m8n8.x4.shared.b16 {%0,%1,%2,%3}, [%4];"
                    : "=r"(A[ii][0]),"=r"(A[ii][1]),"=r"(A[ii][2]),"=r"(A[ii][3]) : "r"(addr));
            }
            #pragma unroll
            for (int jj=0; jj<4; jj++){
                unsigned Bv[4];
                unsigned baddr = xb2 + (unsigned)((((kb + (lane&7) + 8*((lane>>3)&1))*72) + jj*16 + 8*(lane>>4))*2);
                asm volatile("ldmatrix.sync.aligned.m8n8.x4.trans.shared.b16 {%0,%1,%2,%3}, [%4];"
                    : "=r"(Bv[0]),"=r"(Bv[1]),"=r"(Bv[2]),"=r"(Bv[3]) : "r"(baddr));
                #pragma unroll
                for (int ii=0;ii<4;ii++)
                    #pragma unroll
                    for (int j=0;j<2;j++){
                        float* d = acc[ii][jj][j];
                        asm volatile("mma.sync.aligned.m16n8k16.row.col.f32.bf16.bf16.f32 "
                            "{%0,%1,%2,%3},{%4,%5,%6,%7},{%8,%9},{%0,%1,%2,%3};"
                            : "+f"(d[0]),"+f"(d[1]),"+f"(d[2]),"+f"(d[3])
                            : "r"(A[ii][0]),"r"(A[ii][1]),"r"(A[ii][2]),"r"(A[ii][3]),
                              "r"(Bv[j*2]),"r"(Bv[j*2+1]));
                    }
            }
        }
        __syncthreads();
    }

    if (STAT==1){
        __shared__ float2 sgn[8];
        float s=0.f, sq=0.f;
        #pragma unroll
        for (int ii=0;ii<4;ii++)
            #pragma unroll
            for (int jj=0;jj<4;jj++)
                #pragma unroll
                for (int j=0;j<2;j++)
                    #pragma unroll
                    for (int r=0;r<4;r++){
                        float v = acc[ii][jj][j][r];
                        s += v; sq += v*v;
                    }
        #pragma unroll
        for (int off=16; off; off>>=1){
            s  += __shfl_xor_sync(0xffffffffu, s, off);
            sq += __shfl_xor_sync(0xffffffffu, sq, off);
        }
        if (lane==0) sgn[wm] = make_float2(s, sq);
        __syncthreads();
        if (tid < 8){
            float2 v = sgn[tid];
            g_gnp[((size_t)b*NGRP + tid)*49 + blockIdx.x] = v;
        }
    }

    // epilogue: warp wm owns rows wm*64..wm*64+63 (= GN group wm)
    float bg_mu=0.f, bg_rs=0.f;
    if (STAT==2){ int bg=b*NGRP+wm; bg_mu=g_mu[bg]; bg_rs=g_rstd[bg]; }

    float st_s[4][2], st_t[4][2];
    #pragma unroll
    for (int i=0;i<4;i++){ st_s[i][0]=st_s[i][1]=0.f; st_t[i][0]=st_t[i][1]=0.f; }

    #pragma unroll
    for (int ii=0;ii<4;ii++){
        #pragma unroll
        for (int rr=0;rr<2;rr++){
            int m = wm*64 + ii*16 + rr*8 + (lane>>2);
            float ga=0.f, be=0.f;
            if (STAT==2){ ga=g_gamma[m]; be=g_beta[m]; }
            #pragma unroll
            for (int jj=0;jj<4;jj++){
                #pragma unroll
                for (int j=0;j<2;j++){
                    int c = p0 + jj*16 + j*8 + (lane&3)*2;
                    size_t idx = ((size_t)b*512 + m)*HWN + c;
                    float v0 = acc[ii][jj][j][rr*2+0], v1 = acc[ii][jj][j][rr*2+1];
                    if (STAT==2){
                        float2 hv = ldbf2(aux+idx);
                        float hat0=(hv.x-bg_mu)*bg_rs, hat1=(hv.y-bg_mu)*bg_rs;
                        v0 *= gelu_grad(hat0*ga+be);
                        v1 *= gelu_grad(hat1*ga+be);
                        st_s[ii][rr] += v0+v1;
                        st_t[ii][rr] += v0*hat0 + v1*hat1;
                    }
                    *(unsigned*)(out+idx) = pack_bf2(v0, v1);
                }
            }
        }
    }

    if (STAT==2){
        #pragma unroll
        for (int ii=0;ii<4;ii++)
            #pragma unroll
            for (int rr=0;rr<2;rr++){
                float s=st_s[ii][rr], t=st_t[ii][rr];
                s += __shfl_xor_sync(0xffffffffu, s, 1); t += __shfl_xor_sync(0xffffffffu, t, 1);
                s += __shfl_xor_sync(0xffffffffu, s, 2); t += __shfl_xor_sync(0xffffffffu, t, 2);
                if ((lane&3)==0){
                    int m = wm*64 + ii*16 + rr*8 + (lane>>2);
                    g_rowp[((size_t)b*512 + m)*49 + blockIdx.x] = make_float2(s, t);
                }
            }
    }
}

// ============================================================================
// bf16 tensor-core GEMM (register path) — M<=256 cases.
// XOP: 0 none, 1 X*=mask, 2 X=gelu(X), 3 X=gelu(GN(X))
// EPI: 0 store, 1 +aux, 2 drec, 3 *=gelu'(aux), 4 dy-combine, 5 final out
// STAT: 0 none, 3 chan row partials
// ============================================================================
template<int XOP, int EPI, int BM, int STAT, typename TO>
__global__ __launch_bounds__(256,2) void gemm_bf16(
    const bft* __restrict__ W, const bft* __restrict__ X, TO* __restrict__ out,
    int M, int K,
    const float* __restrict__ mask, const bft* __restrict__ aux,
    const bft* __restrict__ y, const float* __restrict__ scal)
{
    constexpr int WPp = (BM==64)?4:2;
    constexpr int NJc = (BM==64)?1:2;
    constexpr int WMT = (BM==256)?4:2;
    constexpr int NW  = (BM==256)?4:((BM==128)?2:1);
    __shared__ bft Ws[BM][40];
    __shared__ bft Xs[32][72];
    __shared__ float2 srow[BM][2];
    int b  = blockIdx.z;
    int m0 = blockIdx.y*BM, p0 = blockIdx.x*64;
    const bft* Xb = X + (size_t)b*K*HWN;
    int tid  = threadIdx.x;
    int lane = tid & 31, warp = tid >> 5;
    int wm = warp / WPp, wp = warp % WPp;
    float acc[WMT][NJc][2][4] = {};

    int xk = tid>>3, xc = (tid&7)*8;
    float mv[8];
    if (XOP==1){
        const float* mr = mask + (size_t)b*HWN + p0 + xc;
        float4 a=*(const float4*)mr, b2=*(const float4*)(mr+4);
        mv[0]=a.x;mv[1]=a.y;mv[2]=a.z;mv[3]=a.w;mv[4]=b2.x;mv[5]=b2.y;mv[6]=b2.z;mv[7]=b2.w;
    }

    uint4 wreg[NW];
    uint4 xreg;

    auto load_tile = [&](int k0){
        const bft* w;
        if (BM==256)      w = W + (size_t)(m0 + tid)*K + k0;
        else if (BM==128) w = W + (size_t)(m0 + (tid>>1))*K + k0 + (tid&1)*16;
        else              w = W + (size_t)(m0 + (tid>>2))*K + k0 + (tid&3)*8;
        #pragma unroll
        for (int q=0;q<NW;q++) wreg[q] = *(const uint4*)(w + q*8);
        xreg = *(const uint4*)(Xb + (size_t)(k0+xk)*HWN + p0 + xc);
    };

    auto store_tile = [&](int k0){
        if (BM==256){
            #pragma unroll
            for (int q=0;q<NW;q++) *(uint4*)&Ws[tid][q*8] = wreg[q];
        } else if (BM==128){
            int row=tid>>1, c=(tid&1)*16;
            *(uint4*)&Ws[row][c]   = wreg[0];
            *(uint4*)&Ws[row][c+8] = wreg[1];
        } else {
            int row=tid>>2, c=(tid&3)*8;
            *(uint4*)&Ws[row][c] = wreg[0];
        }
        if (XOP==0){
            *(uint4*)&Xs[xk][xc] = xreg;
        } else {
            float vv[8]; unpack8(xreg, vv);
            if (XOP==1){
                #pragma unroll
                for (int j=0;j<8;j++) vv[j] *= mv[j];
            } else if (XOP==2){
                #pragma unroll
                for (int j=0;j<8;j++) vv[j] = geluf(vv[j]);
            } else {
                int o = k0 + xk;
                int bg = b*NGRP + o/CGg;
                float mu=g_mu[bg], rs=g_rstd[bg], ga=g_gamma[o], be=g_beta[o];
                #pragma unroll
                for (int j=0;j<8;j++) vv[j] = geluf((vv[j]-mu)*rs*ga + be);
            }
            *(uint4*)&Xs[xk][xc] = pack8(vv);
        }
    };

    const int NK = K >> 5;
    load_tile(0);
    for (int i = 0; i < NK; i++){
        store_tile(i*32);
        __syncthreads();
        if (i+1 < NK) load_tile((i+1)*32);

        #pragma unroll
        for (int h=0; h<2; h++){
            int kb = h*16;
            unsigned A[WMT][4];
            #pragma unroll
            for (int ii=0;ii<WMT;ii++){
                unsigned addr = smem_u32(&Ws[wm*(WMT*16) + ii*16 + (lane&15)][kb + (lane>>4)*8]);
                asm volatile("ldmatrix.sync.aligned.m8n8.x4.shared.b16 {%0,%1,%2,%3}, [%4];"
                    : "=r"(A[ii][0]),"=r"(A[ii][1]),"=r"(A[ii][2]),"=r"(A[ii][3]) : "r"(addr));
            }
            #pragma unroll
            for (int jj=0; jj<NJc; jj++){
                unsigned Bv[4];
                unsigned baddr = smem_u32(&Xs[kb + (lane&7) + 8*((lane>>3)&1)][wp*(NJc*16) + jj*16 + 8*(lane>>4)]);
                asm volatile("ldmatrix.sync.aligned.m8n8.x4.trans.shared.b16 {%0,%1,%2,%3}, [%4];"
                    : "=r"(Bv[0]),"=r"(Bv[1]),"=r"(Bv[2]),"=r"(Bv[3]) : "r"(baddr));
                #pragma unroll
                for (int ii=0;ii<WMT;ii++)
                    #pragma unroll
                    for (int j=0;j<2;j++){
                        float* d = acc[ii][jj][j];
                        asm volatile("mma.sync.aligned.m16n8k16.row.col.f32.bf16.bf16.f32 "
                            "{%0,%1,%2,%3},{%4,%5,%6,%7},{%8,%9},{%0,%1,%2,%3};"
                            : "+f"(d[0]),"+f"(d[1]),"+f"(d[2]),"+f"(d[3])
                            : "r"(A[ii][0]),"r"(A[ii][1]),"r"(A[ii][2]),"r"(A[ii][3]),
                              "r"(Bv[j*2]),"r"(Bv[j*2+1]));
                    }
            }
        }
        __syncthreads();
    }

    float st_s[WMT][2];
    float st_t[WMT][2];
    #pragma unroll
    for (int i=0;i<WMT;i++){ st_s[i][0]=st_s[i][1]=0.f; st_t[i][0]=st_t[i][1]=0.f; }

    #pragma unroll
    for (int i=0;i<WMT;i++){
        int rbase = m0 + wm*(WMT*16) + i*16 + (lane>>2);
        #pragma unroll
        for (int jj=0;jj<NJc;jj++){
            #pragma unroll
            for (int j=0;j<2;j++){
                int c = p0 + wp*(NJc*16) + jj*16 + j*8 + (lane&3)*2;
                #pragma unroll
                for (int rr=0; rr<2; rr++){
                    int m = rbase + rr*8;
                    size_t idx = ((size_t)b*M + m)*HWN + c;
                    float v0 = acc[i][jj][j][rr*2+0], v1 = acc[i][jj][j][rr*2+1];
                    if (EPI==1){
                        float2 a = ldbf2(aux+idx);
                        v0 += a.x; v1 += a.y;
                    } else if (EPI==2){
                        float sc = scal[0];
                        size_t mi = (size_t)b*HWN + c;
                        float2 mk = *(const float2*)(mask+mi);
                        float2 yv = ldbf2(y+idx);
                        v0 = (v0 - yv.x)*(1.0f-mk.x)*sc;
                        v1 = (v1 - yv.y)*(1.0f-mk.y)*sc;
                    } else if (EPI==3){
                        float2 a = ldbf2(aux+idx);
                        v0 *= gelu_grad(a.x); v1 *= gelu_grad(a.y);
                    } else if (EPI==4){
                        size_t mi = (size_t)b*HWN + c;
                        float2 mk = *(const float2*)(mask+mi);
                        float2 a  = ldbf2(aux+idx);
                        float2 yv = ldbf2(y+idx);
                        float cA = g_cA[m], cB = g_cB[m], cm = g_cm[m];
                        v0 = v0*mk.x - a.x + cA + cB*(yv.x-cm);
                        v1 = v1*mk.y - a.y + cA + cB*(yv.y-cm);
                    } else if (EPI==5){
                        float sc = scal[0]*g_gate[b];
                        float2 xf = *(const float2*)(mask+idx);   // mask = x (fp32)
                        v0 = xf.x + sc*v0; v1 = xf.y + sc*v1;
                    }
                    if (STAT==3){
                        st_s[i][rr] += v0+v1;
                        st_t[i][rr] += v0*v0 + v1*v1;
                    }
                    if (sizeof(TO)==4)
                        *(float2*)((float*)out+idx) = make_float2(v0, v1);
                    else
                        *(unsigned*)((bft*)out+idx) = pack_bf2(v0, v1);
                }
            }
        }
    }

    if (STAT==3){
        #pragma unroll
        for (int i=0;i<WMT;i++)
            #pragma unroll
            for (int rr=0;rr<2;rr++){
                float s=st_s[i][rr], t=st_t[i][rr];
                s += __shfl_xor_sync(0xffffffffu, s, 1); t += __shfl_xor_sync(0xffffffffu, t, 1);
                s += __shfl_xor_sync(0xffffffffu, s, 2); t += __shfl_xor_sync(0xffffffffu, t, 2);
                if ((lane&3)==0) srow[wm*(WMT*16) + i*16 + rr*8 + (lane>>2)][wp] = make_float2(s, t);
            }
        __syncthreads();
        if (tid < BM){
            float2 a = srow[tid][0], b2 = srow[tid][1];
            g_rowp[((size_t)b*M + m0 + tid)*49 + blockIdx.x] = make_float2(a.x+b2.x, a.y+b2.y);
        }
    }
}

__global__ void gn_reduce(){
    int bg = threadIdx.x;  // 128
    float s=0.f, sq=0.f;
    for (int i=0;i<49;i++){
        float2 v = g_gnp[(size_t)bg*49 + i];
        s += v.x; sq += v.y;
    }
    float n = (float)(CGg*HWN);
    float mean = s/n;
    float var  = sq/n - mean*mean;
    g_mu[bg] = mean;
    g_rstd[bg] = rsqrtf(var + 1e-5f);
}

__global__ void dgn_rowreduce(){
    int idx = blockIdx.x*blockDim.x + threadIdx.x;
    float s=0.f, t=0.f;
    for (int x=0; x<49; x++){
        float2 v = g_rowp[(size_t)idx*49 + x];
        s += v.x; t += v.y;
    }
    g_part[idx*2+0] = s;
    g_part[idx*2+1] = t;
}

__global__ void chan_reduce(const float* __restrict__ rm, const float* __restrict__ rv){
    int c = blockIdx.x;
    float s=0.f, sq=0.f;
    for (int i=threadIdx.x; i<BN*49; i+=256){
        int b=i/49, x=i%49;
        float2 v = g_rowp[((size_t)b*CC + c)*49 + x];
        s += v.x; sq += v.y;
    }
    block_reduce2(s, sq);
    if (threadIdx.x==0){
        float n = (float)NTOT;
        float cm = s/n;
        float cv = (sq - n*cm*cm)/(n - 1.0f);
        float rve = rv[c] + 1e-8f;
        g_cm[c] = cm;
        g_cA[c] = 0.1f*2.0f*(cm - rm[c])/(256.0f*n);
        g_cB[c] = 0.1f*4.0f*(cv/rve - 1.0f)/(rve*256.0f*(n - 1.0f));
    }
}

// ============================================================================
// NT GEMM 128x128, double-buffered, bf16 partial output.
// XOPB: 0 none, 3 B'=gelu(GN(B));  XOPA: 0 none, 1 A'=dh1 from stored dgn
// ============================================================================
template<int XOPB, int XOPA>
__global__ __launch_bounds__(256,2) void gemm_nt_bf16(
    const bft* __restrict__ A, const bft* __restrict__ Bm, const bft* __restrict__ Hm,
    bft* __restrict__ part, int Ma, int Nb)
{
    __shared__ bft As[2][128][40];
    __shared__ bft Bs[2][128][40];
    int z  = blockIdx.z;
    int m0 = blockIdx.y*128, n0 = blockIdx.x*128;
    int tid  = threadIdx.x;
    int lane = tid & 31, warp = tid >> 5;
    int wm = warp >> 1, wp = warp & 1;
    float acc[2][8][4] = {};

    int r  = tid >> 1, c0 = (tid & 1)*16;

    #define POFF(it) ((((it)%PBZ)*SPLITK + z)*32)
    #define AP(it) (A  + ((size_t)((it)/PBZ)*Ma + m0 + r)*HWN + POFF(it) + c0)
    #define BP(it) (Bm + ((size_t)((it)/PBZ)*Nb + n0 + r)*HWN + POFF(it) + c0)
    #define HP(it) (Hm + ((size_t)((it)/PBZ)*Ma + m0 + r)*HWN + POFF(it) + c0)

    uint4 a0, a1, b0, b1, h0, h1;
    auto load_it = [&](int it){
        a0 = *(const uint4*)AP(it); a1 = *(const uint4*)(AP(it)+8);
        b0 = *(const uint4*)BP(it); b1 = *(const uint4*)(BP(it)+8);
        if (XOPA==1){ h0 = *(const uint4*)HP(it); h1 = *(const uint4*)(HP(it)+8); }
    };
    auto store_it = [&](int buf, int it){
        if (XOPA==0){
            *(uint4*)&As[buf][r][c0]   = a0;
            *(uint4*)&As[buf][r][c0+8] = a1;
        } else {
            int b = it/PBZ;
            int o = m0 + r;
            int bg = b*NGRP + o/CGg;
            float mu=g_mu[bg], rs=g_rstd[bg], ga=g_gamma[o];
            float s1=g_s1[bg], s2=g_s2[bg];
            float av[8], hv[8];
            unpack8(a0, av); unpack8(h0, hv);
            #pragma unroll
            for (int j=0;j<8;j++){
                float hat=(hv[j]-mu)*rs;
                av[j] = rs*(av[j]*ga - s1 - hat*s2);
            }
            *(uint4*)&As[buf][r][c0] = pack8(av);
            unpack8(a1, av); unpack8(h1, hv);
            #pragma unroll
            for (int j=0;j<8;j++){
                float hat=(hv[j]-mu)*rs;
                av[j] = rs*(av[j]*ga - s1 - hat*s2);
            }
            *(uint4*)&As[buf][r][c0+8] = pack8(av);
        }
        if (XOPB==0){
            *(uint4*)&Bs[buf][r][c0]   = b0;
            *(uint4*)&Bs[buf][r][c0+8] = b1;
        } else {
            int b = it/PBZ;
            int o = n0 + r;
            int bg = b*NGRP + o/CGg;
            float mu=g_mu[bg], rs=g_rstd[bg], ga=g_gamma[o], be=g_beta[o];
            float v[8];
            unpack8(b0, v);
            #pragma unroll
            for (int j=0;j<8;j++) v[j] = geluf((v[j]-mu)*rs*ga + be);
            *(uint4*)&Bs[buf][r][c0] = pack8(v);
            unpack8(b1, v);
            #pragma unroll
            for (int j=0;j<8;j++) v[j] = geluf((v[j]-mu)*rs*ga + be);
            *(uint4*)&Bs[buf][r][c0+8] = pack8(v);
        }
    };

    load_it(0);
    store_it(0, 0);
    __syncthreads();

    const int ITERS = BN*PBZ;
    for (int it=0; it<ITERS; it++){
        int cur = it & 1;
        if (it+1 < ITERS) load_it(it+1);

        #pragma unroll
        for (int h=0; h<2; h++){
            int kb = h*16;
            unsigned Af[2][4];
            #pragma unroll
            for (int i=0;i<2;i++){
                unsigned addr = smem_u32(&As[cur][wm*32 + i*16 + (lane&15)][kb + (lane>>4)*8]);
                asm volatile("ldmatrix.sync.aligned.m8n8.x4.shared.b16 {%0,%1,%2,%3}, [%4];"
                    : "=r"(Af[i][0]),"=r"(Af[i][1]),"=r"(Af[i][2]),"=r"(Af[i][3]) : "r"(addr));
            }
            #pragma unroll
            for (int jj=0; jj<4; jj++){
                unsigned Bv[4];
                unsigned baddr = smem_u32(&Bs[cur][wp*64 + jj*16 + (lane&7) + 8*(lane>>4)][kb + 8*((lane>>3)&1)]);
                asm volatile("ldmatrix.sync.aligned.m8n8.x4.shared.b16 {%0,%1,%2,%3}, [%4];"
                    : "=r"(Bv[0]),"=r"(Bv[1]),"=r"(Bv[2]),"=r"(Bv[3]) : "r"(baddr));
                #pragma unroll
                for (int i=0;i<2;i++)
                    #pragma unroll
                    for (int j=0;j<2;j++){
                        float* d = acc[i][jj*2+j];
                        asm volatile("mma.sync.aligned.m16n8k16.row.col.f32.bf16.bf16.f32 "
                            "{%0,%1,%2,%3},{%4,%5,%6,%7},{%8,%9},{%0,%1,%2,%3};"
                            : "+f"(d[0]),"+f"(d[1]),"+f"(d[2]),"+f"(d[3])
                            : "r"(Af[i][0]),"r"(Af[i][1]),"r"(Af[i][2]),"r"(Af[i][3]),
                              "r"(Bv[j*2]),"r"(Bv[j*2+1]));
                    }
            }
        }
        if (it+1 < ITERS) store_it(cur^1, it+1);
        __syncthreads();
    }
    #undef AP
    #undef BP
    #undef HP
    #undef POFF

    #pragma unroll
    for (int i=0;i<2;i++){
        int rbase = m0 + wm*32 + i*16 + (lane>>2);
        #pragma unroll
        for (int jc=0;jc<8;jc++){
            int n = n0 + wp*64 + (jc>>1)*16 + (jc&1)*8 + (lane&3)*2;
            #pragma unroll
            for (int rr=0; rr<2; rr++){
                int m = rbase + rr*8;
                size_t idx = ((size_t)z*Ma + m)*Nb + n;
                *(unsigned*)(part+idx) = pack_bf2(acc[i][jc][rr*2], acc[i][jc][rr*2+1]);
            }
        }
    }
}

__global__ void reduce_part(){
    int t = threadIdx.x;  // 512
    float db=0.f, dga=0.f;
    for (int b=0;b<BN;b++){
        db  += g_part[(b*HIDN+t)*2+0];
        dga += g_part[(b*HIDN+t)*2+1];
    }
    g_dbeta[t]=db; g_dgamma[t]=dga;
    if (t < BN*NGRP){
        int b=t/NGRP, g=t%NGRP;
        float s1=0.f, s2=0.f;
        for (int j=0;j<CGg;j++){
            int o=g*CGg+j;
            float ga=g_gamma[o];
            s1 += ga*g_part[(b*HIDN+o)*2+0];
            s2 += ga*g_part[(b*HIDN+o)*2+1];
        }
        float inv = 1.0f/(float)(CGg*HWN);
        g_s1[t]=s1*inv; g_s2[t]=s2*inv;
    }
}

// fused: reduce both split buffers + SGD update + refresh bf16 copies
__global__ void update_fused(){
    int i2 = blockIdx.x*blockDim.x + threadIdx.x;   // 65536 (pairs)
    int i = i2*2;
    {   // W2 (g_split1, layout [z][c*HIDN+o])
        float s0=0.f, s1=0.f;
        const bft* p = g_split1 + i;
        for (int z=0; z<SPLITK; z++){
            float2 v = ldbf2(p + (size_t)z*HIDN*CC);
            s0 += v.x; s1 += v.y;
        }
        int c = i/HIDN, o = i%HIDN;
        float v0 = g_w2[i]   - LRc*s0;
        float v1 = g_w2[i+1] - LRc*s1;
        g_w2[i]=v0; g_w2[i+1]=v1;
        bft b0=__float2bfloat16(v0), b1=__float2bfloat16(v1);
        g_w2b[i]=b0; g_w2b[i+1]=b1;
        g_w2tb[o*CC+c]=b0; g_w2tb[(o+1)*CC+c]=b1;
    }
    {   // W1 (g_split2, layout [z][o*CC+c])
        float s0=0.f, s1=0.f;
        const bft* p = g_split2 + i;
        for (int z=0; z<SPLITK; z++){
            float2 v = ldbf2(p + (size_t)z*HIDN*CC);
            s0 += v.x; s1 += v.y;
        }
        float v0 = g_w1[i]   - LRc*s0;
        float v1 = g_w1[i+1] - LRc*s1;
        g_w1[i]=v0; g_w1[i+1]=v1;
        g_w1b[i]=__float2bfloat16(v0); g_w1b[i+1]=__float2bfloat16(v1);
    }
    if (i2 < HIDN){
        g_gamma[i2] -= LRc*g_dgamma[i2];
        g_beta[i2]  -= LRc*g_dbeta[i2];
    }
}

// ---------------- gate path ----------------
__global__ void pooled_kernel(const float* __restrict__ x){
    int c = blockIdx.x, b = blockIdx.y;
    const float4* row = (const float4*)(x + ((size_t)b*CC + c)*HWN);
    float s=0.f, d=0.f;
    for (int i=threadIdx.x; i<HWN/4; i+=256){
        float4 v = row[i];
        s += v.x+v.y+v.z+v.w;
    }
    block_reduce2(s, d);
    if (threadIdx.x==0) g_pooled[b*CC+c] = s/(float)HWN;
}

__global__ void gate_kernel(const float* __restrict__ gw1, const float* __restrict__ gb1,
                            const float* __restrict__ gw2, const float* __restrict__ gb2){
    __shared__ float gh[BN*CU];
    int t = threadIdx.x;
    for (int j=t; j<BN*CU; j+=256){
        int b=j/CU, u=j%CU;
        float s = gb1[u];
        const float* pr = &g_pooled[b*CC];
        const float* wr = &gw1[u*CC];
        for (int c=0;c<CC;c++) s += pr[c]*wr[c];
        gh[j] = geluf(s);
    }
    __syncthreads();
    if (t < BN){
        float s = gb2[0];
        for (int u=0;u<CU;u++) s += gh[t*CU+u]*gw2[u];
        g_gate[t] = 1.0f/(1.0f + expf(-s));
    }
}

// ---------------- host orchestration ----------------
extern "C" void kernel_launch(void* const* d_in, const int* in_sizes, int n_in,
                              void* d_out, int out_size){
    const float* x        = (const float*)d_in[0];
    const float* conv1_w  = (const float*)d_in[1];
    const float* gn_gammaI= (const float*)d_in[2];
    const float* gn_betaI = (const float*)d_in[3];
    const float* conv2_w  = (const float*)d_in[4];
    const float* rw1      = (const float*)d_in[5];
    const float* rw2      = (const float*)d_in[6];
    const float* gw1      = (const float*)d_in[7];
    const float* gb1      = (const float*)d_in[8];
    const float* gw2      = (const float*)d_in[9];
    const float* gb2      = (const float*)d_in[10];
    const float* rscale   = (const float*)d_in[11];
    const float* rm       = (const float*)d_in[12];
    const float* rv       = (const float*)d_in[13];
    const void*  masks    = d_in[14];

    void* p;
    #define SYMF(sym) (cudaGetSymbolAddress(&p, sym), (float*)p)
    #define SYMB(sym) (cudaGetSymbolAddress(&p, sym), (bft*)p)
    bft*   pw1b   = SYMB(g_w1b);
    bft*   pw2b   = SYMB(g_w2b);
    bft*   pw2tb  = SYMB(g_w2tb);
    bft*   prw1b  = SYMB(g_rw1b);
    bft*   prw1tb = SYMB(g_rw1tb);
    bft*   prw2b  = SYMB(g_rw2b);
    bft*   prw2tb = SYMB(g_rw2tb);
    bft*   ph1    = SYMB(g_h1);
    bft*   pdg    = SYMB(g_dg);
    bft*   py     = SYMB(g_y);
    bft*   pdrec  = SYMB(g_drec);
    bft*   pdy    = SYMB(g_dy);
    bft*   ppre   = SYMB(g_pre);
    bft*   pdpre  = SYMB(g_dpre);
    bft*   pxb    = SYMB(g_xb);
    bft*   psplit1= SYMB(g_split1);
    bft*   psplit2= SYMB(g_split2);
    float* pmaskf = SYMF(g_maskf);
    float* pdscale= SYMF(g_dscale);
    #undef SYMF
    #undef SYMB

    const int SMEM512 = 3*WSTG + 3*XSTG;   // 136704
    cudaFuncSetAttribute(gemm512<1>, cudaFuncAttributeMaxDynamicSharedMemorySize, SMEM512);
    cudaFuncSetAttribute(gemm512<2>, cudaFuncAttributeMaxDynamicSharedMemorySize, SMEM512);

    // init
    reset_copy<<<512,256>>>(conv1_w, gn_gammaI, gn_betaI, conv2_w, rw1, rw2);
    mask_detect<<<32,256>>>((const unsigned int*)masks);
    convert_x<<<6272,256>>>(x, pxb);

    for (int s=0; s<2; s++){
        const float* mk = pmaskf + (size_t)s*NTOT;
        const float* sc = pdscale + s;

        // forward
        gemm512<1><<<dim3(49,1,BN),256,SMEM512>>>(pw1b, pxb, ph1, nullptr);
        gn_reduce<<<1,128>>>();
        if (s==0){
            mask_convert<<<98,1024>>>(masks);
            inv_scale_kernel<<<2,256>>>();
        }
        gemm_bf16<3,1,256,3,bft><<<dim3(49,1,BN),256>>>(pw2b, ph1,  py,   256,512, nullptr, pxb,   nullptr,nullptr);
        chan_reduce<<<256,256>>>(rm, rv);
        gemm_bf16<1,0, 64,0,bft><<<dim3(49,1,BN),256>>>(prw1b, py,   ppre,  64,256, mk,      nullptr,nullptr,nullptr);
        gemm_bf16<2,2,256,0,bft><<<dim3(49,1,BN),256>>>(prw2b, ppre, pdrec,256, 64, mk,      nullptr, py,    sc);

        // backward through surprise
        gemm_bf16<0,3, 64,0,bft><<<dim3(49,1,BN),256>>>(prw2tb, pdrec, pdpre, 64,256, nullptr, ppre,  nullptr,nullptr);
        gemm_bf16<0,4,256,0,bft><<<dim3(49,1,BN),256>>>(prw1tb, pdpre, pdy,  256, 64, mk,      pdrec, py,     nullptr);

        // backward through modifier (emits dgn + per-row partials)
        gemm512<2><<<dim3(49,1,BN),256,SMEM512>>>(pw2tb, pdy, pdg, ph1);
        dgn_rowreduce<<<32,256>>>();
        reduce_part<<<1,512>>>();

        gemm_nt_bf16<3,0><<<dim3(4,2,SPLITK),256>>>(pdy, ph1, nullptr, psplit1, 256,512);   // dW2
        gemm_nt_bf16<0,1><<<dim3(2,4,SPLITK),256>>>(pdg, pxb, ph1,     psplit2, 512,256);   // dW1
        update_fused<<<256,256>>>();
    }

    // gate path
    pooled_kernel<<<dim3(CC,BN),256>>>(x);
    gate_kernel<<<1,256>>>(gw1, gb1, gw2, gb2);

    // final forward (fused output)
    gemm512<1><<<dim3(49,1,BN),256,SMEM512>>>(pw1b, pxb, ph1, nullptr);
    gn_reduce<<<1,128>>>();
    gemm_bf16<3,5,256,0,float><<<dim3(49,1,BN),256>>>(pw2b, ph1, (float*)d_out, 256,512, x, nullptr, nullptr, rscale);

    (void)in_sizes; (void)n_in; (void)out_size;
}

// round 14
// speedup vs baseline: 1.5968x; 1.0078x over previous
#include <cuda_runtime.h>
#include <cuda_bf16.h>
#include <cstdint>
#include <math.h>

// ---------------- problem constants ----------------
#define BN    16
#define CC    256
#define HIDN  512
#define NGRP  8
#define CGg   64
#define HWN   3136
#define CU    64
#define NTOT  (BN*HWN)
#define LRc   0.01f
#define SPLITK 98
#define PBZ   1           // (HWN/32)/SPLITK

typedef __nv_bfloat16 bft;

// ---------------- device scratch ----------------
__device__ float g_w1[HIDN*CC];
__device__ float g_w2[CC*HIDN];
__device__ float g_gamma[HIDN];
__device__ float g_beta[HIDN];

__device__ bft g_w1b [HIDN*CC];
__device__ bft g_w2b [CC*HIDN];
__device__ bft g_w2tb[HIDN*CC];
__device__ bft g_rw1b [CU*CC];
__device__ bft g_rw1tb[CC*CU];
__device__ bft g_rw2b [CC*CU];
__device__ bft g_rw2tb[CU*CC];

__device__ bft g_h1 [(size_t)BN*HIDN*HWN];
__device__ bft g_dg [(size_t)BN*HIDN*HWN];   // holds dgn after dg-GEMM
__device__ bft g_y  [(size_t)BN*CC*HWN];
__device__ bft g_drec[(size_t)BN*CC*HWN];
__device__ bft g_dy [(size_t)BN*CC*HWN];
__device__ bft g_pre [(size_t)BN*CU*HWN];
__device__ bft g_dpre[(size_t)BN*CU*HWN];
__device__ bft g_xb [(size_t)BN*CC*HWN];

__device__ float g_mu[BN*NGRP];
__device__ float g_rstd[BN*NGRP];
__device__ float2 g_gnp[BN*NGRP*49];
__device__ float2 g_rowp[(size_t)BN*HIDN*49];
__device__ float g_part[BN*HIDN*2];
__device__ float g_s1[BN*NGRP], g_s2[BN*NGRP];
__device__ float g_dgamma[HIDN], g_dbeta[HIDN];
__device__ float g_cm[CC], g_cA[CC], g_cB[CC];
__device__ bft g_split1[(size_t)SPLITK*HIDN*CC];   // dW2 partials (bf16)
__device__ bft g_split2[(size_t)SPLITK*HIDN*CC];   // dW1 partials (bf16)
__device__ float g_maskf[2*NTOT];
__device__ float2 g_mpart[98];
__device__ float g_dscale[2];
__device__ float g_pooled[BN*CC];
__device__ float g_gate[BN];
__device__ int   g_flagF, g_flagW;

// ---------------- math helpers ----------------
__device__ __forceinline__ float geluf(float x){
    return 0.5f*x*(1.0f + erff(x*0.70710678118654752440f));
}
__device__ __forceinline__ float gelu_grad(float x){
    float cdf = 0.5f*(1.0f + erff(x*0.70710678118654752440f));
    float pdf = 0.3989422804014327f*__expf(-0.5f*x*x);
    return cdf + x*pdf;
}
__device__ __forceinline__ void block_reduce2(float& a, float& b){
    __shared__ float sa[256], sb[256];
    int t = threadIdx.x;
    sa[t]=a; sb[t]=b; __syncthreads();
    for (int s=128; s>0; s>>=1){
        if (t<s){ sa[t]+=sa[t+s]; sb[t]+=sb[t+s]; }
        __syncthreads();
    }
    a=sa[0]; b=sb[0];
}
__device__ __forceinline__ unsigned pack_bf2(float a, float b){
    __nv_bfloat162 p = __floats2bfloat162_rn(a, b);
    return *(unsigned*)&p;
}
__device__ __forceinline__ unsigned smem_u32(const void* p){
    return (unsigned)__cvta_generic_to_shared(p);
}
__device__ __forceinline__ void unpack8(uint4 u, float* v){
    __nv_bfloat162 p;
    p=*(__nv_bfloat162*)&u.x; v[0]=__low2float(p); v[1]=__high2float(p);
    p=*(__nv_bfloat162*)&u.y; v[2]=__low2float(p); v[3]=__high2float(p);
    p=*(__nv_bfloat162*)&u.z; v[4]=__low2float(p); v[5]=__high2float(p);
    p=*(__nv_bfloat162*)&u.w; v[6]=__low2float(p); v[7]=__high2float(p);
}
__device__ __forceinline__ uint4 pack8(const float* v){
    uint4 u;
    u.x=pack_bf2(v[0],v[1]); u.y=pack_bf2(v[2],v[3]);
    u.z=pack_bf2(v[4],v[5]); u.w=pack_bf2(v[6],v[7]);
    return u;
}
__device__ __forceinline__ float2 ldbf2(const bft* p){
    __nv_bfloat162 v = *(const __nv_bfloat162*)p;
    return make_float2(__low2float(v), __high2float(v));
}

// ---------------- init / mask handling ----------------
__global__ void reset_copy(const float* __restrict__ w1, const float* __restrict__ gam,
                           const float* __restrict__ bet, const float* __restrict__ w2,
                           const float* __restrict__ rw1, const float* __restrict__ rw2){
    int i = blockIdx.x*blockDim.x + threadIdx.x;
    if (i==0){ g_flagF=0; g_flagW=0; }
    if (i < HIDN*CC){ float v=w1[i]; g_w1[i]=v; g_w1b[i]=__float2bfloat16(v); }
    if (i < CC*HIDN){
        float v=w2[i]; g_w2[i]=v;
        bft bv=__float2bfloat16(v);
        g_w2b[i]=bv;
        int c=i/HIDN, o=i%HIDN;
        g_w2tb[o*CC+c]=bv;
    }
    if (i < CU*CC){
        bft bv=__float2bfloat16(rw1[i]);
        g_rw1b[i]=bv;
        int u=i/CC, c=i%CC;
        g_rw1tb[c*CU+u]=bv;
    }
    if (i < CC*CU){
        bft bv=__float2bfloat16(rw2[i]);
        g_rw2b[i]=bv;
        int c=i/CU, u=i%CU;
        g_rw2tb[u*CC+c]=bv;
    }
    if (i < HIDN){ g_gamma[i]=gam[i]; g_beta[i]=bet[i]; }
}

__global__ void mask_detect(const unsigned int* __restrict__ mw){
    int f=0, wd=0;
    for (int i = blockIdx.x*blockDim.x + threadIdx.x; i < 25088; i += gridDim.x*blockDim.x){
        unsigned v = mw[i];
        if (v == 0x3F800000u) f = 1;
        else if (v != 0u && v != 1u) wd = 1;
    }
    if (f)  atomicOr(&g_flagF, 1);
    if (wd) atomicOr(&g_flagW, 1);
}

// convert masks to float AND emit per-block zero-counts (for both steps)
__global__ void mask_convert(const void* __restrict__ mp){
    int mode = g_flagW ? 2 : (g_flagF ? 1 : 0);
    int n = 2*NTOT;
    float c0 = 0.f, c1 = 0.f;
    for (int i = blockIdx.x*blockDim.x + threadIdx.x; i < n; i += gridDim.x*blockDim.x){
        bool v;
        if (mode==0)      v = ((const int*)mp)[i] != 0;
        else if (mode==1) v = ((const float*)mp)[i] != 0.0f;
        else              v = ((const unsigned char*)mp)[i] != 0;
        g_maskf[i] = v ? 1.0f : 0.0f;
        if (!v){ if (i < NTOT) c0 += 1.0f; else c1 += 1.0f; }
    }
    // reduce within the 1024-thread block (use two 256-level passes via shfl+smem)
    __shared__ float sa[32], sb[32];
    int lane = threadIdx.x & 31, w = threadIdx.x >> 5;
    #pragma unroll
    for (int off=16; off; off>>=1){
        c0 += __shfl_xor_sync(0xffffffffu, c0, off);
        c1 += __shfl_xor_sync(0xffffffffu, c1, off);
    }
    if (lane==0){ sa[w]=c0; sb[w]=c1; }
    __syncthreads();
    if (threadIdx.x==0){
        float a=0.f, b=0.f;
        for (int j=0;j<32;j++){ a+=sa[j]; b+=sb[j]; }
        g_mpart[blockIdx.x] = make_float2(a, b);
    }
}

__global__ void inv_scale_kernel(){
    int t = threadIdx.x;  // 128
    float a = 0.f, b = 0.f;
    if (t < 98){ float2 v = g_mpart[t]; a=v.x; b=v.y; }
    __shared__ float sa[128], sb[128];
    sa[t]=a; sb[t]=b; __syncthreads();
    for (int s=64; s>0; s>>=1){
        if (t<s){ sa[t]+=sa[t+s]; sb[t]+=sb[t+s]; }
        __syncthreads();
    }
    if (t==0){
        g_dscale[0] = 2.0f/(sa[0]*256.0f + 1e-8f);
        g_dscale[1] = 2.0f/(sb[0]*256.0f + 1e-8f);
    }
}

// fused: x -> bf16 copy + channel mean (pooled)
__global__ void convert_pool(const float* __restrict__ x, bft* __restrict__ xb){
    int c = blockIdx.x, b = blockIdx.y;
    size_t base = ((size_t)b*CC + c)*HWN;
    float s = 0.f, d = 0.f;
    for (int i = threadIdx.x; i < HWN/8; i += 256){
        size_t off = base + (size_t)i*8;
        float4 a0 = *(const float4*)(x+off);
        float4 a1 = *(const float4*)(x+off+4);
        float v[8] = {a0.x,a0.y,a0.z,a0.w,a1.x,a1.y,a1.z,a1.w};
        *(uint4*)(xb+off) = pack8(v);
        #pragma unroll
        for (int j=0;j<8;j++) s += v[j];
    }
    block_reduce2(s, d);
    if (threadIdx.x==0) g_pooled[b*CC+c] = s/(float)HWN;
}

// ============================================================================
// gemm512: M=512, K=256, BP=64, 256 threads, warp tile 64x64,
// 3-stage cp.async pipeline.
// STAT 1: GN group partials.  STAT 2: dgn epilogue (stores dgn, row partials).
// ============================================================================
#define WSTG (512*40*2)
#define XSTG (32*72*2)
template<int STAT>
__global__ __launch_bounds__(256) void gemm512(
    const bft* __restrict__ W, const bft* __restrict__ X, bft* __restrict__ out,
    const bft* __restrict__ aux)
{
    extern __shared__ char dsm[];
    const unsigned WsU = smem_u32(dsm);                  // [3][512][40]
    const unsigned XsU = WsU + 3*WSTG;                   // [3][32][72]
    int b  = blockIdx.z;
    int p0 = blockIdx.x*64;
    const bft* Xb = X + (size_t)b*256*HWN;
    int tid  = threadIdx.x;
    int lane = tid & 31, wm = tid >> 5;
    float acc[4][4][2][4] = {};

    auto issue = [&](int it){
        int k0 = it*32;
        int st = it % 3;
        unsigned wb = WsU + (unsigned)(st*WSTG);
        #pragma unroll
        for (int j=0;j<8;j++){
            int chunk = tid + j*256;
            int row = chunk>>2, q = chunk&3;
            unsigned dst = wb + (unsigned)((row*40 + q*8)*2);
            const bft* src = W + (size_t)row*256 + k0 + q*8;
            asm volatile("cp.async.cg.shared.global [%0], [%1], 16;" :: "r"(dst), "l"(src));
        }
        {
            int row = tid>>3, c = (tid&7)*8;
            unsigned dst = XsU + (unsigned)((st*32*72 + row*72 + c)*2);
            const bft* src = Xb + (size_t)(k0+row)*HWN + p0 + c;
            asm volatile("cp.async.cg.shared.global [%0], [%1], 16;" :: "r"(dst), "l"(src));
        }
        asm volatile("cp.async.commit_group;");
    };

    issue(0);
    issue(1);
    #pragma unroll 1
    for (int it = 0; it < 8; it++){
        if (it + 2 < 8){
            issue(it+2);
            asm volatile("cp.async.wait_group 2;");
        } else if (it + 1 < 8){
            asm volatile("cp.async.wait_group 1;");
        } else {
            asm volatile("cp.async.wait_group 0;");
        }
        __syncthreads();
        int st = it % 3;
        unsigned wb  = WsU + (unsigned)(st*WSTG);
        unsigned xb2 = XsU + (unsigned)(st*32*72*2);
        #pragma unroll
        for (int h=0; h<2; h++){
            int kb = h*16;
            unsigned A[4][4];
            #pragma unroll
            for (int ii=0;ii<4;ii++){
                unsigned addr = wb + (unsigned)((((wm*64 + ii*16 + (lane&15))*40) + kb + (lane>>4)*8)*2);
                asm volatile("ldmatrix.sync.aligned.m8n8.x4.shared.b16 {%0,%1,%2,%3}, [%4];"
                    : "=r"(A[ii][0]),"=r"(A[ii][1]),"=r"(A[ii][2]),"=r"(A[ii][3]) : "r"(addr));
            }
            #pragma unroll
            for (int jj=0; jj<4; jj++){
                unsigned Bv[4];
                unsigned baddr = xb2 + (unsigned)((((kb + (lane&7) + 8*((lane>>3)&1))*72) + jj*16 + 8*(lane>>4))*2);
                asm volatile("ldmatrix.sync.aligned.m8n8.x4.trans.shared.b16 {%0,%1,%2,%3}, [%4];"
                    : "=r"(Bv[0]),"=r"(Bv[1]),"=r"(Bv[2]),"=r"(Bv[3]) : "r"(baddr));
                #pragma unroll
                for (int ii=0;ii<4;ii++)
                    #pragma unroll
                    for (int j=0;j<2;j++){
                        float* d = acc[ii][jj][j];
                        asm volatile("mma.sync.aligned.m16n8k16.row.col.f32.bf16.bf16.f32 "
                            "{%0,%1,%2,%3},{%4,%5,%6,%7},{%8,%9},{%0,%1,%2,%3};"
                            : "+f"(d[0]),"+f"(d[1]),"+f"(d[2]),"+f"(d[3])
                            : "r"(A[ii][0]),"r"(A[ii][1]),"r"(A[ii][2]),"r"(A[ii][3]),
                              "r"(Bv[j*2]),"r"(Bv[j*2+1]));
                    }
            }
        }
        __syncthreads();
    }

    if (STAT==1){
        __shared__ float2 sgn[8];
        float s=0.f, sq=0.f;
        #pragma unroll
        for (int ii=0;ii<4;ii++)
            #pragma unroll
            for (int jj=0;jj<4;jj++)
                #pragma unroll
                for (int j=0;j<2;j++)
                    #pragma unroll
                    for (int r=0;r<4;r++){
                        float v = acc[ii][jj][j][r];
                        s += v; sq += v*v;
                    }
        #pragma unroll
        for (int off=16; off; off>>=1){
            s  += __shfl_xor_sync(0xffffffffu, s, off);
            sq += __shfl_xor_sync(0xffffffffu, sq, off);
        }
        if (lane==0) sgn[wm] = make_float2(s, sq);
        __syncthreads();
        if (tid < 8){
            float2 v = sgn[tid];
            g_gnp[((size_t)b*NGRP + tid)*49 + blockIdx.x] = v;
        }
    }

    // epilogue: warp wm owns rows wm*64..wm*64+63 (= GN group wm)
    float bg_mu=0.f, bg_rs=0.f;
    if (STAT==2){ int bg=b*NGRP+wm; bg_mu=g_mu[bg]; bg_rs=g_rstd[bg]; }

    float st_s[4][2], st_t[4][2];
    #pragma unroll
    for (int i=0;i<4;i++){ st_s[i][0]=st_s[i][1]=0.f; st_t[i][0]=st_t[i][1]=0.f; }

    #pragma unroll
    for (int ii=0;ii<4;ii++){
        #pragma unroll
        for (int rr=0;rr<2;rr++){
            int m = wm*64 + ii*16 + rr*8 + (lane>>2);
            float ga=0.f, be=0.f;
            if (STAT==2){ ga=g_gamma[m]; be=g_beta[m]; }
            #pragma unroll
            for (int jj=0;jj<4;jj++){
                #pragma unroll
                for (int j=0;j<2;j++){
                    int c = p0 + jj*16 + j*8 + (lane&3)*2;
                    size_t idx = ((size_t)b*512 + m)*HWN + c;
                    float v0 = acc[ii][jj][j][rr*2+0], v1 = acc[ii][jj][j][rr*2+1];
                    if (STAT==2){
                        float2 hv = ldbf2(aux+idx);
                        float hat0=(hv.x-bg_mu)*bg_rs, hat1=(hv.y-bg_mu)*bg_rs;
                        v0 *= gelu_grad(hat0*ga+be);
                        v1 *= gelu_grad(hat1*ga+be);
                        st_s[ii][rr] += v0+v1;
                        st_t[ii][rr] += v0*hat0 + v1*hat1;
                    }
                    *(unsigned*)(out+idx) = pack_bf2(v0, v1);
                }
            }
        }
    }

    if (STAT==2){
        #pragma unroll
        for (int ii=0;ii<4;ii++)
            #pragma unroll
            for (int rr=0;rr<2;rr++){
                float s=st_s[ii][rr], t=st_t[ii][rr];
                s += __shfl_xor_sync(0xffffffffu, s, 1); t += __shfl_xor_sync(0xffffffffu, t, 1);
                s += __shfl_xor_sync(0xffffffffu, s, 2); t += __shfl_xor_sync(0xffffffffu, t, 2);
                if ((lane&3)==0){
                    int m = wm*64 + ii*16 + rr*8 + (lane>>2);
                    g_rowp[((size_t)b*512 + m)*49 + blockIdx.x] = make_float2(s, t);
                }
            }
    }
}

// ============================================================================
// bf16 tensor-core GEMM (register path) — M<=256 cases.
// XOP: 0 none, 1 X*=mask, 2 X=gelu(X), 3 X=gelu(GN(X))
// EPI: 0 store, 1 +aux, 2 drec, 3 *=gelu'(aux), 4 dy-combine, 5 final out
// STAT: 0 none, 3 chan row partials
// ============================================================================
template<int XOP, int EPI, int BM, int STAT, typename TO>
__global__ __launch_bounds__(256,2) void gemm_bf16(
    const bft* __restrict__ W, const bft* __restrict__ X, TO* __restrict__ out,
    int M, int K,
    const float* __restrict__ mask, const bft* __restrict__ aux,
    const bft* __restrict__ y, const float* __restrict__ scal)
{
    constexpr int WPp = (BM==64)?4:2;
    constexpr int NJc = (BM==64)?1:2;
    constexpr int WMT = (BM==256)?4:2;
    constexpr int NW  = (BM==256)?4:((BM==128)?2:1);
    __shared__ bft Ws[BM][40];
    __shared__ bft Xs[32][72];
    __shared__ float2 srow[BM][2];
    int b  = blockIdx.z;
    int m0 = blockIdx.y*BM, p0 = blockIdx.x*64;
    const bft* Xb = X + (size_t)b*K*HWN;
    int tid  = threadIdx.x;
    int lane = tid & 31, warp = tid >> 5;
    int wm = warp / WPp, wp = warp % WPp;
    float acc[WMT][NJc][2][4] = {};

    int xk = tid>>3, xc = (tid&7)*8;
    float mv[8];
    if (XOP==1){
        const float* mr = mask + (size_t)b*HWN + p0 + xc;
        float4 a=*(const float4*)mr, b2=*(const float4*)(mr+4);
        mv[0]=a.x;mv[1]=a.y;mv[2]=a.z;mv[3]=a.w;mv[4]=b2.x;mv[5]=b2.y;mv[6]=b2.z;mv[7]=b2.w;
    }

    uint4 wreg[NW];
    uint4 xreg;

    auto load_tile = [&](int k0){
        const bft* w;
        if (BM==256)      w = W + (size_t)(m0 + tid)*K + k0;
        else if (BM==128) w = W + (size_t)(m0 + (tid>>1))*K + k0 + (tid&1)*16;
        else              w = W + (size_t)(m0 + (tid>>2))*K + k0 + (tid&3)*8;
        #pragma unroll
        for (int q=0;q<NW;q++) wreg[q] = *(const uint4*)(w + q*8);
        xreg = *(const uint4*)(Xb + (size_t)(k0+xk)*HWN + p0 + xc);
    };

    auto store_tile = [&](int k0){
        if (BM==256){
            #pragma unroll
            for (int q=0;q<NW;q++) *(uint4*)&Ws[tid][q*8] = wreg[q];
        } else if (BM==128){
            int row=tid>>1, c=(tid&1)*16;
            *(uint4*)&Ws[row][c]   = wreg[0];
            *(uint4*)&Ws[row][c+8] = wreg[1];
        } else {
            int row=tid>>2, c=(tid&3)*8;
            *(uint4*)&Ws[row][c] = wreg[0];
        }
        if (XOP==0){
            *(uint4*)&Xs[xk][xc] = xreg;
        } else {
            float vv[8]; unpack8(xreg, vv);
            if (XOP==1){
                #pragma unroll
                for (int j=0;j<8;j++) vv[j] *= mv[j];
            } else if (XOP==2){
                #pragma unroll
                for (int j=0;j<8;j++) vv[j] = geluf(vv[j]);
            } else {
                int o = k0 + xk;
                int bg = b*NGRP + o/CGg;
                float mu=g_mu[bg], rs=g_rstd[bg], ga=g_gamma[o], be=g_beta[o];
                #pragma unroll
                for (int j=0;j<8;j++) vv[j] = geluf((vv[j]-mu)*rs*ga + be);
            }
            *(uint4*)&Xs[xk][xc] = pack8(vv);
        }
    };

    const int NK = K >> 5;
    load_tile(0);
    for (int i = 0; i < NK; i++){
        store_tile(i*32);
        __syncthreads();
        if (i+1 < NK) load_tile((i+1)*32);

        #pragma unroll
        for (int h=0; h<2; h++){
            int kb = h*16;
            unsigned A[WMT][4];
            #pragma unroll
            for (int ii=0;ii<WMT;ii++){
                unsigned addr = smem_u32(&Ws[wm*(WMT*16) + ii*16 + (lane&15)][kb + (lane>>4)*8]);
                asm volatile("ldmatrix.sync.aligned.m8n8.x4.shared.b16 {%0,%1,%2,%3}, [%4];"
                    : "=r"(A[ii][0]),"=r"(A[ii][1]),"=r"(A[ii][2]),"=r"(A[ii][3]) : "r"(addr));
            }
            #pragma unroll
            for (int jj=0; jj<NJc; jj++){
                unsigned Bv[4];
                unsigned baddr = smem_u32(&Xs[kb + (lane&7) + 8*((lane>>3)&1)][wp*(NJc*16) + jj*16 + 8*(lane>>4)]);
                asm volatile("ldmatrix.sync.aligned.m8n8.x4.trans.shared.b16 {%0,%1,%2,%3}, [%4];"
                    : "=r"(Bv[0]),"=r"(Bv[1]),"=r"(Bv[2]),"=r"(Bv[3]) : "r"(baddr));
                #pragma unroll
                for (int ii=0;ii<WMT;ii++)
                    #pragma unroll
                    for (int j=0;j<2;j++){
                        float* d = acc[ii][jj][j];
                        asm volatile("mma.sync.aligned.m16n8k16.row.col.f32.bf16.bf16.f32 "
                            "{%0,%1,%2,%3},{%4,%5,%6,%7},{%8,%9},{%0,%1,%2,%3};"
                            : "+f"(d[0]),"+f"(d[1]),"+f"(d[2]),"+f"(d[3])
                            : "r"(A[ii][0]),"r"(A[ii][1]),"r"(A[ii][2]),"r"(A[ii][3]),
                              "r"(Bv[j*2]),"r"(Bv[j*2+1]));
                    }
            }
        }
        __syncthreads();
    }

    float st_s[WMT][2];
    float st_t[WMT][2];
    #pragma unroll
    for (int i=0;i<WMT;i++){ st_s[i][0]=st_s[i][1]=0.f; st_t[i][0]=st_t[i][1]=0.f; }

    #pragma unroll
    for (int i=0;i<WMT;i++){
        int rbase = m0 + wm*(WMT*16) + i*16 + (lane>>2);
        #pragma unroll
        for (int jj=0;jj<NJc;jj++){
            #pragma unroll
            for (int j=0;j<2;j++){
                int c = p0 + wp*(NJc*16) + jj*16 + j*8 + (lane&3)*2;
                #pragma unroll
                for (int rr=0; rr<2; rr++){
                    int m = rbase + rr*8;
                    size_t idx = ((size_t)b*M + m)*HWN + c;
                    float v0 = acc[i][jj][j][rr*2+0], v1 = acc[i][jj][j][rr*2+1];
                    if (EPI==1){
                        float2 a = ldbf2(aux+idx);
                        v0 += a.x; v1 += a.y;
                    } else if (EPI==2){
                        float sc = scal[0];
                        size_t mi = (size_t)b*HWN + c;
                        float2 mk = *(const float2*)(mask+mi);
                        float2 yv = ldbf2(y+idx);
                        v0 = (v0 - yv.x)*(1.0f-mk.x)*sc;
                        v1 = (v1 - yv.y)*(1.0f-mk.y)*sc;
                    } else if (EPI==3){
                        float2 a = ldbf2(aux+idx);
                        v0 *= gelu_grad(a.x); v1 *= gelu_grad(a.y);
                    } else if (EPI==4){
                        size_t mi = (size_t)b*HWN + c;
                        float2 mk = *(const float2*)(mask+mi);
                        float2 a  = ldbf2(aux+idx);
                        float2 yv = ldbf2(y+idx);
                        float cA = g_cA[m], cB = g_cB[m], cm = g_cm[m];
                        v0 = v0*mk.x - a.x + cA + cB*(yv.x-cm);
                        v1 = v1*mk.y - a.y + cA + cB*(yv.y-cm);
                    } else if (EPI==5){
                        float sc = scal[0]*g_gate[b];
                        float2 xf = *(const float2*)(mask+idx);   // mask = x (fp32)
                        v0 = xf.x + sc*v0; v1 = xf.y + sc*v1;
                    }
                    if (STAT==3){
                        st_s[i][rr] += v0+v1;
                        st_t[i][rr] += v0*v0 + v1*v1;
                    }
                    if (sizeof(TO)==4)
                        *(float2*)((float*)out+idx) = make_float2(v0, v1);
                    else
                        *(unsigned*)((bft*)out+idx) = pack_bf2(v0, v1);
                }
            }
        }
    }

    if (STAT==3){
        #pragma unroll
        for (int i=0;i<WMT;i++)
            #pragma unroll
            for (int rr=0;rr<2;rr++){
                float s=st_s[i][rr], t=st_t[i][rr];
                s += __shfl_xor_sync(0xffffffffu, s, 1); t += __shfl_xor_sync(0xffffffffu, t, 1);
                s += __shfl_xor_sync(0xffffffffu, s, 2); t += __shfl_xor_sync(0xffffffffu, t, 2);
                if ((lane&3)==0) srow[wm*(WMT*16) + i*16 + rr*8 + (lane>>2)][wp] = make_float2(s, t);
            }
        __syncthreads();
        if (tid < BM){
            float2 a = srow[tid][0], b2 = srow[tid][1];
            g_rowp[((size_t)b*M + m0 + tid)*49 + blockIdx.x] = make_float2(a.x+b2.x, a.y+b2.y);
        }
    }
}

__global__ void gn_reduce(){
    int bg = threadIdx.x;  // 128
    float s=0.f, sq=0.f;
    for (int i=0;i<49;i++){
        float2 v = g_gnp[(size_t)bg*49 + i];
        s += v.x; sq += v.y;
    }
    float n = (float)(CGg*HWN);
    float mean = s/n;
    float var  = sq/n - mean*mean;
    g_mu[bg] = mean;
    g_rstd[bg] = rsqrtf(var + 1e-5f);
}

__global__ void dgn_rowreduce(){
    int idx = blockIdx.x*blockDim.x + threadIdx.x;
    float s=0.f, t=0.f;
    for (int x=0; x<49; x++){
        float2 v = g_rowp[(size_t)idx*49 + x];
        s += v.x; t += v.y;
    }
    g_part[idx*2+0] = s;
    g_part[idx*2+1] = t;
}

__global__ void chan_reduce(const float* __restrict__ rm, const float* __restrict__ rv){
    int c = blockIdx.x;
    float s=0.f, sq=0.f;
    for (int i=threadIdx.x; i<BN*49; i+=256){
        int b=i/49, x=i%49;
        float2 v = g_rowp[((size_t)b*CC + c)*49 + x];
        s += v.x; sq += v.y;
    }
    block_reduce2(s, sq);
    if (threadIdx.x==0){
        float n = (float)NTOT;
        float cm = s/n;
        float cv = (sq - n*cm*cm)/(n - 1.0f);
        float rve = rv[c] + 1e-8f;
        g_cm[c] = cm;
        g_cA[c] = 0.1f*2.0f*(cm - rm[c])/(256.0f*n);
        g_cB[c] = 0.1f*4.0f*(cv/rve - 1.0f)/(rve*256.0f*(n - 1.0f));
    }
}

// ============================================================================
// NT GEMM 128x128, double-buffered, bf16 partial output.
// XOPB: 0 none, 3 B'=gelu(GN(B));  XOPA: 0 none, 1 A'=dh1 from stored dgn
// ============================================================================
template<int XOPB, int XOPA>
__global__ __launch_bounds__(256,2) void gemm_nt_bf16(
    const bft* __restrict__ A, const bft* __restrict__ Bm, const bft* __restrict__ Hm,
    bft* __restrict__ part, int Ma, int Nb)
{
    __shared__ bft As[2][128][40];
    __shared__ bft Bs[2][128][40];
    int z  = blockIdx.z;
    int m0 = blockIdx.y*128, n0 = blockIdx.x*128;
    int tid  = threadIdx.x;
    int lane = tid & 31, warp = tid >> 5;
    int wm = warp >> 1, wp = warp & 1;
    float acc[2][8][4] = {};

    int r  = tid >> 1, c0 = (tid & 1)*16;

    #define POFF(it) ((((it)%PBZ)*SPLITK + z)*32)
    #define AP(it) (A  + ((size_t)((it)/PBZ)*Ma + m0 + r)*HWN + POFF(it) + c0)
    #define BP(it) (Bm + ((size_t)((it)/PBZ)*Nb + n0 + r)*HWN + POFF(it) + c0)
    #define HP(it) (Hm + ((size_t)((it)/PBZ)*Ma + m0 + r)*HWN + POFF(it) + c0)

    uint4 a0, a1, b0, b1, h0, h1;
    auto load_it = [&](int it){
        a0 = *(const uint4*)AP(it); a1 = *(const uint4*)(AP(it)+8);
        b0 = *(const uint4*)BP(it); b1 = *(const uint4*)(BP(it)+8);
        if (XOPA==1){ h0 = *(const uint4*)HP(it); h1 = *(const uint4*)(HP(it)+8); }
    };
    auto store_it = [&](int buf, int it){
        if (XOPA==0){
            *(uint4*)&As[buf][r][c0]   = a0;
            *(uint4*)&As[buf][r][c0+8] = a1;
        } else {
            int b = it/PBZ;
            int o = m0 + r;
            int bg = b*NGRP + o/CGg;
            float mu=g_mu[bg], rs=g_rstd[bg], ga=g_gamma[o];
            float s1=g_s1[bg], s2=g_s2[bg];
            float av[8], hv[8];
            unpack8(a0, av); unpack8(h0, hv);
            #pragma unroll
            for (int j=0;j<8;j++){
                float hat=(hv[j]-mu)*rs;
                av[j] = rs*(av[j]*ga - s1 - hat*s2);
            }
            *(uint4*)&As[buf][r][c0] = pack8(av);
            unpack8(a1, av); unpack8(h1, hv);
            #pragma unroll
            for (int j=0;j<8;j++){
                float hat=(hv[j]-mu)*rs;
                av[j] = rs*(av[j]*ga - s1 - hat*s2);
            }
            *(uint4*)&As[buf][r][c0+8] = pack8(av);
        }
        if (XOPB==0){
            *(uint4*)&Bs[buf][r][c0]   = b0;
            *(uint4*)&Bs[buf][r][c0+8] = b1;
        } else {
            int b = it/PBZ;
            int o = n0 + r;
            int bg = b*NGRP + o/CGg;
            float mu=g_mu[bg], rs=g_rstd[bg], ga=g_gamma[o], be=g_beta[o];
            float v[8];
            unpack8(b0, v);
            #pragma unroll
            for (int j=0;j<8;j++) v[j] = geluf((v[j]-mu)*rs*ga + be);
            *(uint4*)&Bs[buf][r][c0] = pack8(v);
            unpack8(b1, v);
            #pragma unroll
            for (int j=0;j<8;j++) v[j] = geluf((v[j]-mu)*rs*ga + be);
            *(uint4*)&Bs[buf][r][c0+8] = pack8(v);
        }
    };

    load_it(0);
    store_it(0, 0);
    __syncthreads();

    const int ITERS = BN*PBZ;
    for (int it=0; it<ITERS; it++){
        int cur = it & 1;
        if (it+1 < ITERS) load_it(it+1);

        #pragma unroll
        for (int h=0; h<2; h++){
            int kb = h*16;
            unsigned Af[2][4];
            #pragma unroll
            for (int i=0;i<2;i++){
                unsigned addr = smem_u32(&As[cur][wm*32 + i*16 + (lane&15)][kb + (lane>>4)*8]);
                asm volatile("ldmatrix.sync.aligned.m8n8.x4.shared.b16 {%0,%1,%2,%3}, [%4];"
                    : "=r"(Af[i][0]),"=r"(Af[i][1]),"=r"(Af[i][2]),"=r"(Af[i][3]) : "r"(addr));
            }
            #pragma unroll
            for (int jj=0; jj<4; jj++){
                unsigned Bv[4];
                unsigned baddr = smem_u32(&Bs[cur][wp*64 + jj*16 + (lane&7) + 8*(lane>>4)][kb + 8*((lane>>3)&1)]);
                asm volatile("ldmatrix.sync.aligned.m8n8.x4.shared.b16 {%0,%1,%2,%3}, [%4];"
                    : "=r"(Bv[0]),"=r"(Bv[1]),"=r"(Bv[2]),"=r"(Bv[3]) : "r"(baddr));
                #pragma unroll
                for (int i=0;i<2;i++)
                    #pragma unroll
                    for (int j=0;j<2;j++){
                        float* d = acc[i][jj*2+j];
                        asm volatile("mma.sync.aligned.m16n8k16.row.col.f32.bf16.bf16.f32 "
                            "{%0,%1,%2,%3},{%4,%5,%6,%7},{%8,%9},{%0,%1,%2,%3};"
                            : "+f"(d[0]),"+f"(d[1]),"+f"(d[2]),"+f"(d[3])
                            : "r"(Af[i][0]),"r"(Af[i][1]),"r"(Af[i][2]),"r"(Af[i][3]),
                              "r"(Bv[j*2]),"r"(Bv[j*2+1]));
                    }
            }
        }
        if (it+1 < ITERS) store_it(cur^1, it+1);
        __syncthreads();
    }
    #undef AP
    #undef BP
    #undef HP
    #undef POFF

    #pragma unroll
    for (int i=0;i<2;i++){
        int rbase = m0 + wm*32 + i*16 + (lane>>2);
        #pragma unroll
        for (int jc=0;jc<8;jc++){
            int n = n0 + wp*64 + (jc>>1)*16 + (jc&1)*8 + (lane&3)*2;
            #pragma unroll
            for (int rr=0; rr<2; rr++){
                int m = rbase + rr*8;
                size_t idx = ((size_t)z*Ma + m)*Nb + n;
                *(unsigned*)(part+idx) = pack_bf2(acc[i][jc][rr*2], acc[i][jc][rr*2+1]);
            }
        }
    }
}

__global__ void reduce_part(){
    int t = threadIdx.x;  // 512
    float db=0.f, dga=0.f;
    for (int b=0;b<BN;b++){
        db  += g_part[(b*HIDN+t)*2+0];
        dga += g_part[(b*HIDN+t)*2+1];
    }
    g_dbeta[t]=db; g_dgamma[t]=dga;
    if (t < BN*NGRP){
        int b=t/NGRP, g=t%NGRP;
        float s1=0.f, s2=0.f;
        for (int j=0;j<CGg;j++){
            int o=g*CGg+j;
            float ga=g_gamma[o];
            s1 += ga*g_part[(b*HIDN+o)*2+0];
            s2 += ga*g_part[(b*HIDN+o)*2+1];
        }
        float inv = 1.0f/(float)(CGg*HWN);
        g_s1[t]=s1*inv; g_s2[t]=s2*inv;
    }
}

// fused: reduce both split buffers + SGD update + refresh bf16 copies
__global__ void update_fused(){
    int i2 = blockIdx.x*blockDim.x + threadIdx.x;   // 65536 (pairs)
    int i = i2*2;
    {   // W2 (g_split1, layout [z][c*HIDN+o])
        float s0=0.f, s1=0.f;
        const bft* p = g_split1 + i;
        for (int z=0; z<SPLITK; z++){
            float2 v = ldbf2(p + (size_t)z*HIDN*CC);
            s0 += v.x; s1 += v.y;
        }
        int c = i/HIDN, o = i%HIDN;
        float v0 = g_w2[i]   - LRc*s0;
        float v1 = g_w2[i+1] - LRc*s1;
        g_w2[i]=v0; g_w2[i+1]=v1;
        bft b0=__float2bfloat16(v0), b1=__float2bfloat16(v1);
        g_w2b[i]=b0; g_w2b[i+1]=b1;
        g_w2tb[o*CC+c]=b0; g_w2tb[(o+1)*CC+c]=b1;
    }
    {   // W1 (g_split2, layout [z][o*CC+c])
        float s0=0.f, s1=0.f;
        const bft* p = g_split2 + i;
        for (int z=0; z<SPLITK; z++){
            float2 v = ldbf2(p + (size_t)z*HIDN*CC);
            s0 += v.x; s1 += v.y;
        }
        float v0 = g_w1[i]   - LRc*s0;
        float v1 = g_w1[i+1] - LRc*s1;
        g_w1[i]=v0; g_w1[i+1]=v1;
        g_w1b[i]=__float2bfloat16(v0); g_w1b[i+1]=__float2bfloat16(v1);
    }
    if (i2 < HIDN){
        g_gamma[i2] -= LRc*g_dgamma[i2];
        g_beta[i2]  -= LRc*g_dbeta[i2];
    }
}

// ---------------- gate ----------------
__global__ void gate_kernel(const float* __restrict__ gw1, const float* __restrict__ gb1,
                            const float* __restrict__ gw2, const float* __restrict__ gb2){
    __shared__ float gh[BN*CU];
    int t = threadIdx.x;
    for (int j=t; j<BN*CU; j+=256){
        int b=j/CU, u=j%CU;
        float s = gb1[u];
        const float* pr = &g_pooled[b*CC];
        const float* wr = &gw1[u*CC];
        for (int c=0;c<CC;c++) s += pr[c]*wr[c];
        gh[j] = geluf(s);
    }
    __syncthreads();
    if (t < BN){
        float s = gb2[0];
        for (int u=0;u<CU;u++) s += gh[t*CU+u]*gw2[u];
        g_gate[t] = 1.0f/(1.0f + expf(-s));
    }
}

// ---------------- host orchestration ----------------
extern "C" void kernel_launch(void* const* d_in, const int* in_sizes, int n_in,
                              void* d_out, int out_size){
    const float* x        = (const float*)d_in[0];
    const float* conv1_w  = (const float*)d_in[1];
    const float* gn_gammaI= (const float*)d_in[2];
    const float* gn_betaI = (const float*)d_in[3];
    const float* conv2_w  = (const float*)d_in[4];
    const float* rw1      = (const float*)d_in[5];
    const float* rw2      = (const float*)d_in[6];
    const float* gw1      = (const float*)d_in[7];
    const float* gb1      = (const float*)d_in[8];
    const float* gw2      = (const float*)d_in[9];
    const float* gb2      = (const float*)d_in[10];
    const float* rscale   = (const float*)d_in[11];
    const float* rm       = (const float*)d_in[12];
    const float* rv       = (const float*)d_in[13];
    const void*  masks    = d_in[14];

    void* p;
    #define SYMF(sym) (cudaGetSymbolAddress(&p, sym), (float*)p)
    #define SYMB(sym) (cudaGetSymbolAddress(&p, sym), (bft*)p)
    bft*   pw1b   = SYMB(g_w1b);
    bft*   pw2b   = SYMB(g_w2b);
    bft*   pw2tb  = SYMB(g_w2tb);
    bft*   prw1b  = SYMB(g_rw1b);
    bft*   prw1tb = SYMB(g_rw1tb);
    bft*   prw2b  = SYMB(g_rw2b);
    bft*   prw2tb = SYMB(g_rw2tb);
    bft*   ph1    = SYMB(g_h1);
    bft*   pdg    = SYMB(g_dg);
    bft*   py     = SYMB(g_y);
    bft*   pdrec  = SYMB(g_drec);
    bft*   pdy    = SYMB(g_dy);
    bft*   ppre   = SYMB(g_pre);
    bft*   pdpre  = SYMB(g_dpre);
    bft*   pxb    = SYMB(g_xb);
    bft*   psplit1= SYMB(g_split1);
    bft*   psplit2= SYMB(g_split2);
    float* pmaskf = SYMF(g_maskf);
    float* pdscale= SYMF(g_dscale);
    #undef SYMF
    #undef SYMB

    const int SMEM512 = 3*WSTG + 3*XSTG;   // 136704
    cudaFuncSetAttribute(gemm512<1>, cudaFuncAttributeMaxDynamicSharedMemorySize, SMEM512);
    cudaFuncSetAttribute(gemm512<2>, cudaFuncAttributeMaxDynamicSharedMemorySize, SMEM512);

    // init
    reset_copy<<<512,256>>>(conv1_w, gn_gammaI, gn_betaI, conv2_w, rw1, rw2);
    mask_detect<<<32,256>>>((const unsigned int*)masks);
    convert_pool<<<dim3(CC,BN),256>>>(x, pxb);

    for (int s=0; s<2; s++){
        const float* mk = pmaskf + (size_t)s*NTOT;
        const float* sc = pdscale + s;

        // forward
        gemm512<1><<<dim3(49,1,BN),256,SMEM512>>>(pw1b, pxb, ph1, nullptr);
        gn_reduce<<<1,128>>>();
        if (s==0){
            mask_convert<<<98,1024>>>(masks);
            inv_scale_kernel<<<1,128>>>();
        }
        gemm_bf16<3,1,256,3,bft><<<dim3(49,1,BN),256>>>(pw2b, ph1,  py,   256,512, nullptr, pxb,   nullptr,nullptr);
        chan_reduce<<<256,256>>>(rm, rv);
        gemm_bf16<1,0, 64,0,bft><<<dim3(49,1,BN),256>>>(prw1b, py,   ppre,  64,256, mk,      nullptr,nullptr,nullptr);
        gemm_bf16<2,2,256,0,bft><<<dim3(49,1,BN),256>>>(prw2b, ppre, pdrec,256, 64, mk,      nullptr, py,    sc);

        // backward through surprise
        gemm_bf16<0,3, 64,0,bft><<<dim3(49,1,BN),256>>>(prw2tb, pdrec, pdpre, 64,256, nullptr, ppre,  nullptr,nullptr);
        gemm_bf16<0,4,256,0,bft><<<dim3(49,1,BN),256>>>(prw1tb, pdpre, pdy,  256, 64, mk,      pdrec, py,     nullptr);

        // backward through modifier (emits dgn + per-row partials)
        gemm512<2><<<dim3(49,1,BN),256,SMEM512>>>(pw2tb, pdy, pdg, ph1);
        dgn_rowreduce<<<32,256>>>();
        reduce_part<<<1,512>>>();

        gemm_nt_bf16<3,0><<<dim3(4,2,SPLITK),256>>>(pdy, ph1, nullptr, psplit1, 256,512);   // dW2
        gemm_nt_bf16<0,1><<<dim3(2,4,SPLITK),256>>>(pdg, pxb, ph1,     psplit2, 512,256);   // dW1
        update_fused<<<256,256>>>();
    }

    // gate (pooled computed in convert_pool)
    gate_kernel<<<1,256>>>(gw1, gb1, gw2, gb2);

    // final forward (fused output)
    gemm512<1><<<dim3(49,1,BN),256,SMEM512>>>(pw1b, pxb, ph1, nullptr);
    gn_reduce<<<1,128>>>();
    gemm_bf16<3,5,256,0,float><<<dim3(49,1,BN),256>>>(pw2b, ph1, (float*)d_out, 256,512, x, nullptr, nullptr, rscale);

    (void)in_sizes; (void)n_in; (void)out_size;
}

// round 15
// speedup vs baseline: 1.6790x; 1.0515x over previous
#include <cuda_runtime.h>
#include <cuda_bf16.h>
#include <cstdint>
#include <math.h>

// ---------------- problem constants ----------------
#define BN    16
#define CC    256
#define HIDN  512
#define NGRP  8
#define CGg   64
#define HWN   3136
#define CU    64
#define NTOT  (BN*HWN)
#define LRc   0.01f
#define SPLITK 98
#define PBZ   1           // (HWN/32)/SPLITK

typedef __nv_bfloat16 bft;

// ---------------- device scratch ----------------
__device__ float g_w1[HIDN*CC];
__device__ float g_w2[CC*HIDN];
__device__ float g_gamma[HIDN];
__device__ float g_beta[HIDN];

__device__ bft g_w1b [HIDN*CC];
__device__ bft g_w2b [CC*HIDN];
__device__ bft g_w2tb[HIDN*CC];
__device__ bft g_rw1b [CU*CC];
__device__ bft g_rw1tb[CC*CU];
__device__ bft g_rw2b [CC*CU];
__device__ bft g_rw2tb[CU*CC];

__device__ bft g_h1 [(size_t)BN*HIDN*HWN];
__device__ bft g_dg [(size_t)BN*HIDN*HWN];   // holds dgn after dg-GEMM
__device__ bft g_y  [(size_t)BN*CC*HWN];
__device__ bft g_dy [(size_t)BN*CC*HWN];
__device__ bft g_xb [(size_t)BN*CC*HWN];

__device__ float g_mu[BN*NGRP];
__device__ float g_rstd[BN*NGRP];
__device__ float2 g_gnp[BN*NGRP*49];
__device__ float2 g_rowp[(size_t)BN*HIDN*49];
__device__ float g_part[BN*HIDN*2];
__device__ float g_s1[BN*NGRP], g_s2[BN*NGRP];
__device__ float g_dgamma[HIDN], g_dbeta[HIDN];
__device__ float g_cm[CC], g_cA[CC], g_cB[CC];
__device__ bft g_split1[(size_t)SPLITK*HIDN*CC];   // dW2 partials (bf16)
__device__ bft g_split2[(size_t)SPLITK*HIDN*CC];   // dW1 partials (bf16)
__device__ float g_maskf[2*NTOT];
__device__ float2 g_mpart[98];
__device__ float g_dscale[2];
__device__ float g_pooled[BN*CC];
__device__ float g_gate[BN];
__device__ int   g_flagF, g_flagW;

// ---------------- math helpers ----------------
__device__ __forceinline__ float geluf(float x){
    return 0.5f*x*(1.0f + erff(x*0.70710678118654752440f));
}
__device__ __forceinline__ float gelu_grad(float x){
    float cdf = 0.5f*(1.0f + erff(x*0.70710678118654752440f));
    float pdf = 0.3989422804014327f*__expf(-0.5f*x*x);
    return cdf + x*pdf;
}
__device__ __forceinline__ void block_reduce2(float& a, float& b){
    __shared__ float sa[256], sb[256];
    int t = threadIdx.x;
    sa[t]=a; sb[t]=b; __syncthreads();
    for (int s=128; s>0; s>>=1){
        if (t<s){ sa[t]+=sa[t+s]; sb[t]+=sb[t+s]; }
        __syncthreads();
    }
    a=sa[0]; b=sb[0];
}
__device__ __forceinline__ unsigned pack_bf2(float a, float b){
    __nv_bfloat162 p = __floats2bfloat162_rn(a, b);
    return *(unsigned*)&p;
}
__device__ __forceinline__ unsigned smem_u32(const void* p){
    return (unsigned)__cvta_generic_to_shared(p);
}
__device__ __forceinline__ void unpack8(uint4 u, float* v){
    __nv_bfloat162 p;
    p=*(__nv_bfloat162*)&u.x; v[0]=__low2float(p); v[1]=__high2float(p);
    p=*(__nv_bfloat162*)&u.y; v[2]=__low2float(p); v[3]=__high2float(p);
    p=*(__nv_bfloat162*)&u.z; v[4]=__low2float(p); v[5]=__high2float(p);
    p=*(__nv_bfloat162*)&u.w; v[6]=__low2float(p); v[7]=__high2float(p);
}
__device__ __forceinline__ uint4 pack8(const float* v){
    uint4 u;
    u.x=pack_bf2(v[0],v[1]); u.y=pack_bf2(v[2],v[3]);
    u.z=pack_bf2(v[4],v[5]); u.w=pack_bf2(v[6],v[7]);
    return u;
}
__device__ __forceinline__ float2 ldbf2(const bft* p){
    __nv_bfloat162 v = *(const __nv_bfloat162*)p;
    return make_float2(__low2float(v), __high2float(v));
}

#define LDMX4(A, addr) \
    asm volatile("ldmatrix.sync.aligned.m8n8.x4.shared.b16 {%0,%1,%2,%3}, [%4];" \
        : "=r"((A)[0]),"=r"((A)[1]),"=r"((A)[2]),"=r"((A)[3]) : "r"(addr))
#define LDMX4T(A, addr) \
    asm volatile("ldmatrix.sync.aligned.m8n8.x4.trans.shared.b16 {%0,%1,%2,%3}, [%4];" \
        : "=r"((A)[0]),"=r"((A)[1]),"=r"((A)[2]),"=r"((A)[3]) : "r"(addr))
#define MMA16816(d, A, b0, b1) \
    asm volatile("mma.sync.aligned.m16n8k16.row.col.f32.bf16.bf16.f32 " \
        "{%0,%1,%2,%3},{%4,%5,%6,%7},{%8,%9},{%0,%1,%2,%3};" \
        : "+f"((d)[0]),"+f"((d)[1]),"+f"((d)[2]),"+f"((d)[3]) \
        : "r"((A)[0]),"r"((A)[1]),"r"((A)[2]),"r"((A)[3]), "r"(b0),"r"(b1))

// ---------------- init / mask handling ----------------
__global__ void reset_copy(const float* __restrict__ w1, const float* __restrict__ gam,
                           const float* __restrict__ bet, const float* __restrict__ w2,
                           const float* __restrict__ rw1, const float* __restrict__ rw2){
    int i = blockIdx.x*blockDim.x + threadIdx.x;
    if (i==0){ g_flagF=0; g_flagW=0; }
    if (i < HIDN*CC){ float v=w1[i]; g_w1[i]=v; g_w1b[i]=__float2bfloat16(v); }
    if (i < CC*HIDN){
        float v=w2[i]; g_w2[i]=v;
        bft bv=__float2bfloat16(v);
        g_w2b[i]=bv;
        int c=i/HIDN, o=i%HIDN;
        g_w2tb[o*CC+c]=bv;
    }
    if (i < CU*CC){
        bft bv=__float2bfloat16(rw1[i]);
        g_rw1b[i]=bv;
        int u=i/CC, c=i%CC;
        g_rw1tb[c*CU+u]=bv;
    }
    if (i < CC*CU){
        bft bv=__float2bfloat16(rw2[i]);
        g_rw2b[i]=bv;
        int c=i/CU, u=i%CU;
        g_rw2tb[u*CC+c]=bv;
    }
    if (i < HIDN){ g_gamma[i]=gam[i]; g_beta[i]=bet[i]; }
}

__global__ void mask_detect(const unsigned int* __restrict__ mw){
    int f=0, wd=0;
    for (int i = blockIdx.x*blockDim.x + threadIdx.x; i < 25088; i += gridDim.x*blockDim.x){
        unsigned v = mw[i];
        if (v == 0x3F800000u) f = 1;
        else if (v != 0u && v != 1u) wd = 1;
    }
    if (f)  atomicOr(&g_flagF, 1);
    if (wd) atomicOr(&g_flagW, 1);
}

__global__ void mask_convert(const void* __restrict__ mp){
    int mode = g_flagW ? 2 : (g_flagF ? 1 : 0);
    int n = 2*NTOT;
    float c0 = 0.f, c1 = 0.f;
    for (int i = blockIdx.x*blockDim.x + threadIdx.x; i < n; i += gridDim.x*blockDim.x){
        bool v;
        if (mode==0)      v = ((const int*)mp)[i] != 0;
        else if (mode==1) v = ((const float*)mp)[i] != 0.0f;
        else              v = ((const unsigned char*)mp)[i] != 0;
        g_maskf[i] = v ? 1.0f : 0.0f;
        if (!v){ if (i < NTOT) c0 += 1.0f; else c1 += 1.0f; }
    }
    __shared__ float sa[32], sb[32];
    int lane = threadIdx.x & 31, w = threadIdx.x >> 5;
    #pragma unroll
    for (int off=16; off; off>>=1){
        c0 += __shfl_xor_sync(0xffffffffu, c0, off);
        c1 += __shfl_xor_sync(0xffffffffu, c1, off);
    }
    if (lane==0){ sa[w]=c0; sb[w]=c1; }
    __syncthreads();
    if (threadIdx.x==0){
        float a=0.f, b=0.f;
        for (int j=0;j<32;j++){ a+=sa[j]; b+=sb[j]; }
        g_mpart[blockIdx.x] = make_float2(a, b);
    }
}

__global__ void inv_scale_kernel(){
    int t = threadIdx.x;  // 128
    float a = 0.f, b = 0.f;
    if (t < 98){ float2 v = g_mpart[t]; a=v.x; b=v.y; }
    __shared__ float sa[128], sb[128];
    sa[t]=a; sb[t]=b; __syncthreads();
    for (int s=64; s>0; s>>=1){
        if (t<s){ sa[t]+=sa[t+s]; sb[t]+=sb[t+s]; }
        __syncthreads();
    }
    if (t==0){
        g_dscale[0] = 2.0f/(sa[0]*256.0f + 1e-8f);
        g_dscale[1] = 2.0f/(sb[0]*256.0f + 1e-8f);
    }
}

// fused: x -> bf16 copy + channel mean (pooled)
__global__ void convert_pool(const float* __restrict__ x, bft* __restrict__ xb){
    int c = blockIdx.x, b = blockIdx.y;
    size_t base = ((size_t)b*CC + c)*HWN;
    float s = 0.f, d = 0.f;
    for (int i = threadIdx.x; i < HWN/8; i += 256){
        size_t off = base + (size_t)i*8;
        float4 a0 = *(const float4*)(x+off);
        float4 a1 = *(const float4*)(x+off+4);
        float v[8] = {a0.x,a0.y,a0.z,a0.w,a1.x,a1.y,a1.z,a1.w};
        *(uint4*)(xb+off) = pack8(v);
        #pragma unroll
        for (int j=0;j<8;j++) s += v[j];
    }
    block_reduce2(s, d);
    if (threadIdx.x==0) g_pooled[b*CC+c] = s/(float)HWN;
}

// ============================================================================
// surprise_fused: for each (b, p-tile of 64), computes the whole chain
//   pre = (rw1 @ y) * mask          (64 x 64, K=256)
//   drec = (rw2 @ gelu(pre) - y) * (1-mask) * scal    (256 x 64, K=64)
//   dpre = (rw2^T @ drec) * gelu'(pre)                (64 x 64, K=256)
//   dy   = (rw1^T @ dpre)*mask - drec + cA + cB*(y-cm)  (256 x 64, K=64)
// Only dy hits global memory.
// ============================================================================
#define SF_YS   0
#define SF_DS   36864
#define SF_WB1  73728
#define SF_WB2  107520
#define SF_PG   144384
#define SF_GP   153600
#define SF_DPS  162816
#define SF_SMEM 172032

__global__ __launch_bounds__(256) void surprise_fused(
    const bft* __restrict__ Y, bft* __restrict__ DY,
    const float* __restrict__ mask, const float* __restrict__ scal)
{
    extern __shared__ char dsm[];
    bft* ys  = (bft*)(dsm + SF_YS);    // [256][72]
    bft* ds  = (bft*)(dsm + SF_DS);    // [256][72]
    bft* wb1 = (bft*)(dsm + SF_WB1);   // [64][264]
    bft* wb2 = (bft*)(dsm + SF_WB2);   // [256][72]
    bft* pg  = (bft*)(dsm + SF_PG);    // [64][72]
    bft* gp  = (bft*)(dsm + SF_GP);    // [64][72]
    bft* dps = (bft*)(dsm + SF_DPS);   // [64][72]
    int b = blockIdx.z;
    int p0 = blockIdx.x*64;
    int tid=threadIdx.x, lane=tid&31, warp=tid>>5;
    const bft* Yb = Y + (size_t)b*CC*HWN;
    const float* mr = mask + (size_t)b*HWN + p0;

    // loads: ys (y tile), wb1=rw1b, wb2=rw2b
    #pragma unroll
    for (int j=0;j<8;j++){
        int idx = tid + j*256;
        { int row=idx>>3, col=(idx&7)*8;
          *(uint4*)&ys[row*72+col] = *(const uint4*)(Yb + (size_t)row*HWN + p0 + col); }
        { int row=idx>>5, col=(idx&31)*8;
          *(uint4*)&wb1[row*264+col] = *(const uint4*)(g_rw1b + row*256 + col); }
        { int row=idx>>3, col=(idx&7)*8;
          *(uint4*)&wb2[row*72+col] = *(const uint4*)(g_rw2b + row*64 + col); }
    }
    __syncthreads();

    // ---- Stage A: pre = (rw1 @ y) * mask  (M=64, K=256) ----
    {
        int wm = warp>>2, wp = warp&3;
        float acc[2][2][4] = {};
        for (int kb=0; kb<256; kb+=16){
            unsigned A[2][4];
            #pragma unroll
            for (int i=0;i<2;i++)
                LDMX4(A[i], smem_u32(&wb1[(wm*32+i*16+(lane&15))*264 + kb + (lane>>4)*8]));
            unsigned Bv[4];
            LDMX4T(Bv, smem_u32(&ys[(kb + (lane&7) + 8*((lane>>3)&1))*72 + wp*16 + 8*(lane>>4)]));
            #pragma unroll
            for (int i=0;i<2;i++)
                #pragma unroll
                for (int j=0;j<2;j++) MMA16816(acc[i][j], A[i], Bv[j*2], Bv[j*2+1]);
        }
        #pragma unroll
        for (int i=0;i<2;i++)
            #pragma unroll
            for (int j=0;j<2;j++)
                #pragma unroll
                for (int rr=0;rr<2;rr++){
                    int m = wm*32+i*16+rr*8+(lane>>2);
                    int c = wp*16 + j*8 + (lane&3)*2;
                    float v0 = acc[i][j][rr*2]  *mr[c];
                    float v1 = acc[i][j][rr*2+1]*mr[c+1];
                    *(unsigned*)&pg[m*72+c] = pack_bf2(geluf(v0), geluf(v1));
                    *(unsigned*)&gp[m*72+c] = pack_bf2(gelu_grad(v0), gelu_grad(v1));
                }
    }
    __syncthreads();

    // reload wb1 = rw2tb (for stage C); stage B doesn't touch wb1
    #pragma unroll
    for (int j=0;j<8;j++){
        int idx = tid + j*256;
        int row=idx>>5, col=(idx&31)*8;
        *(uint4*)&wb1[row*264+col] = *(const uint4*)(g_rw2tb + row*256 + col);
    }

    // ---- Stage B: drec = (rw2 @ gelu(pre) - y)*(1-mask)*scal  (M=256, K=64) ----
    {
        float acc[2][4][2][4] = {};
        for (int kb=0; kb<64; kb+=16){
            unsigned A[2][4];
            #pragma unroll
            for (int i=0;i<2;i++)
                LDMX4(A[i], smem_u32(&wb2[(warp*32+i*16+(lane&15))*72 + kb + (lane>>4)*8]));
            #pragma unroll
            for (int jj=0;jj<4;jj++){
                unsigned Bv[4];
                LDMX4T(Bv, smem_u32(&pg[(kb + (lane&7) + 8*((lane>>3)&1))*72 + jj*16 + 8*(lane>>4)]));
                #pragma unroll
                for (int i=0;i<2;i++)
                    #pragma unroll
                    for (int j=0;j<2;j++) MMA16816(acc[i][jj][j], A[i], Bv[j*2], Bv[j*2+1]);
            }
        }
        float sc = scal[0];
        #pragma unroll
        for (int i=0;i<2;i++)
            #pragma unroll
            for (int jj=0;jj<4;jj++)
                #pragma unroll
                for (int j=0;j<2;j++)
                    #pragma unroll
                    for (int rr=0;rr<2;rr++){
                        int m = warp*32+i*16+rr*8+(lane>>2);
                        int c = jj*16 + j*8 + (lane&3)*2;
                        float2 yv = ldbf2(&ys[m*72+c]);
                        float v0 = (acc[i][jj][j][rr*2]  -yv.x)*(1.0f-mr[c])  *sc;
                        float v1 = (acc[i][jj][j][rr*2+1]-yv.y)*(1.0f-mr[c+1])*sc;
                        *(unsigned*)&ds[m*72+c] = pack_bf2(v0, v1);
                    }
    }
    __syncthreads();

    // reload wb2 = rw1tb (for stage D); stage C doesn't touch wb2
    #pragma unroll
    for (int j=0;j<8;j++){
        int idx = tid + j*256;
        int row=idx>>3, col=(idx&7)*8;
        *(uint4*)&wb2[row*72+col] = *(const uint4*)(g_rw1tb + row*64 + col);
    }

    // ---- Stage C: dpre = (rw2^T @ drec) * gelu'(pre)  (M=64, K=256) ----
    {
        int wm = warp>>2, wp = warp&3;
        float acc[2][2][4] = {};
        for (int kb=0; kb<256; kb+=16){
            unsigned A[2][4];
            #pragma unroll
            for (int i=0;i<2;i++)
                LDMX4(A[i], smem_u32(&wb1[(wm*32+i*16+(lane&15))*264 + kb + (lane>>4)*8]));
            unsigned Bv[4];
            LDMX4T(Bv, smem_u32(&ds[(kb + (lane&7) + 8*((lane>>3)&1))*72 + wp*16 + 8*(lane>>4)]));
            #pragma unroll
            for (int i=0;i<2;i++)
                #pragma unroll
                for (int j=0;j<2;j++) MMA16816(acc[i][j], A[i], Bv[j*2], Bv[j*2+1]);
        }
        #pragma unroll
        for (int i=0;i<2;i++)
            #pragma unroll
            for (int j=0;j<2;j++)
                #pragma unroll
                for (int rr=0;rr<2;rr++){
                    int m = wm*32+i*16+rr*8+(lane>>2);
                    int c = wp*16 + j*8 + (lane&3)*2;
                    float2 gv = ldbf2(&gp[m*72+c]);
                    *(unsigned*)&dps[m*72+c] =
                        pack_bf2(acc[i][j][rr*2]*gv.x, acc[i][j][rr*2+1]*gv.y);
                }
    }
    __syncthreads();

    // ---- Stage D: dy = (rw1^T @ dpre)*mask - drec + cA + cB*(y-cm)  (M=256, K=64) ----
    {
        float acc[2][4][2][4] = {};
        for (int kb=0; kb<64; kb+=16){
            unsigned A[2][4];
            #pragma unroll
            for (int i=0;i<2;i++)
                LDMX4(A[i], smem_u32(&wb2[(warp*32+i*16+(lane&15))*72 + kb + (lane>>4)*8]));
            #pragma unroll
            for (int jj=0;jj<4;jj++){
                unsigned Bv[4];
                LDMX4T(Bv, smem_u32(&dps[(kb + (lane&7) + 8*((lane>>3)&1))*72 + jj*16 + 8*(lane>>4)]));
                #pragma unroll
                for (int i=0;i<2;i++)
                    #pragma unroll
                    for (int j=0;j<2;j++) MMA16816(acc[i][jj][j], A[i], Bv[j*2], Bv[j*2+1]);
            }
        }
        #pragma unroll
        for (int i=0;i<2;i++)
            #pragma unroll
            for (int jj=0;jj<4;jj++)
                #pragma unroll
                for (int j=0;j<2;j++)
                    #pragma unroll
                    for (int rr=0;rr<2;rr++){
                        int m = warp*32+i*16+rr*8+(lane>>2);
                        int c = jj*16 + j*8 + (lane&3)*2;
                        float2 dsv = ldbf2(&ds[m*72+c]);
                        float2 yv  = ldbf2(&ys[m*72+c]);
                        float cA=g_cA[m], cBv=g_cB[m], cmv=g_cm[m];
                        float v0 = acc[i][jj][j][rr*2]  *mr[c]   - dsv.x + cA + cBv*(yv.x-cmv);
                        float v1 = acc[i][jj][j][rr*2+1]*mr[c+1] - dsv.y + cA + cBv*(yv.y-cmv);
                        *(unsigned*)(DY + ((size_t)b*CC + m)*HWN + p0 + c) = pack_bf2(v0, v1);
                    }
    }
}

// ============================================================================
// gemm512: M=512, K=256, BP=64, 256 threads, warp tile 64x64, 3-stage cp.async.
// STAT 1: GN group partials.  STAT 2: dgn epilogue (stores dgn, row partials).
// ============================================================================
#define WSTG (512*40*2)
#define XSTG (32*72*2)
template<int STAT>
__global__ __launch_bounds__(256) void gemm512(
    const bft* __restrict__ W, const bft* __restrict__ X, bft* __restrict__ out,
    const bft* __restrict__ aux)
{
    extern __shared__ char dsm[];
    const unsigned WsU = smem_u32(dsm);                  // [3][512][40]
    const unsigned XsU = WsU + 3*WSTG;                   // [3][32][72]
    int b  = blockIdx.z;
    int p0 = blockIdx.x*64;
    const bft* Xb = X + (size_t)b*256*HWN;
    int tid  = threadIdx.x;
    int lane = tid & 31, wm = tid >> 5;
    float acc[4][4][2][4] = {};

    auto issue = [&](int it){
        int k0 = it*32;
        int st = it % 3;
        unsigned wb = WsU + (unsigned)(st*WSTG);
        #pragma unroll
        for (int j=0;j<8;j++){
            int chunk = tid + j*256;
            int row = chunk>>2, q = chunk&3;
            unsigned dst = wb + (unsigned)((row*40 + q*8)*2);
            const bft* src = W + (size_t)row*256 + k0 + q*8;
            asm volatile("cp.async.cg.shared.global [%0], [%1], 16;" :: "r"(dst), "l"(src));
        }
        {
            int row = tid>>3, c = (tid&7)*8;
            unsigned dst = XsU + (unsigned)((st*32*72 + row*72 + c)*2);
            const bft* src = Xb + (size_t)(k0+row)*HWN + p0 + c;
            asm volatile("cp.async.cg.shared.global [%0], [%1], 16;" :: "r"(dst), "l"(src));
        }
        asm volatile("cp.async.commit_group;");
    };

    issue(0);
    issue(1);
    #pragma unroll 1
    for (int it = 0; it < 8; it++){
        if (it + 2 < 8){
            issue(it+2);
            asm volatile("cp.async.wait_group 2;");
        } else if (it + 1 < 8){
            asm volatile("cp.async.wait_group 1;");
        } else {
            asm volatile("cp.async.wait_group 0;");
        }
        __syncthreads();
        int st = it % 3;
        unsigned wb  = WsU + (unsigned)(st*WSTG);
        unsigned xb2 = XsU + (unsigned)(st*32*72*2);
        #pragma unroll
        for (int h=0; h<2; h++){
            int kb = h*16;
            unsigned A[4][4];
            #pragma unroll
            for (int ii=0;ii<4;ii++)
                LDMX4(A[ii], wb + (unsigned)((((wm*64 + ii*16 + (lane&15))*40) + kb + (lane>>4)*8)*2));
            #pragma unroll
            for (int jj=0; jj<4; jj++){
                unsigned Bv[4];
                LDMX4T(Bv, xb2 + (unsigned)((((kb + (lane&7) + 8*((lane>>3)&1))*72) + jj*16 + 8*(lane>>4))*2));
                #pragma unroll
                for (int ii=0;ii<4;ii++)
                    #pragma unroll
                    for (int j=0;j<2;j++) MMA16816(acc[ii][jj][j], A[ii], Bv[j*2], Bv[j*2+1]);
            }
        }
        __syncthreads();
    }

    if (STAT==1){
        __shared__ float2 sgn[8];
        float s=0.f, sq=0.f;
        #pragma unroll
        for (int ii=0;ii<4;ii++)
            #pragma unroll
            for (int jj=0;jj<4;jj++)
                #pragma unroll
                for (int j=0;j<2;j++)
                    #pragma unroll
                    for (int r=0;r<4;r++){
                        float v = acc[ii][jj][j][r];
                        s += v; sq += v*v;
                    }
        #pragma unroll
        for (int off=16; off; off>>=1){
            s  += __shfl_xor_sync(0xffffffffu, s, off);
            sq += __shfl_xor_sync(0xffffffffu, sq, off);
        }
        if (lane==0) sgn[wm] = make_float2(s, sq);
        __syncthreads();
        if (tid < 8){
            float2 v = sgn[tid];
            g_gnp[((size_t)b*NGRP + tid)*49 + blockIdx.x] = v;
        }
    }

    float bg_mu=0.f, bg_rs=0.f;
    if (STAT==2){ int bg=b*NGRP+wm; bg_mu=g_mu[bg]; bg_rs=g_rstd[bg]; }

    float st_s[4][2], st_t[4][2];
    #pragma unroll
    for (int i=0;i<4;i++){ st_s[i][0]=st_s[i][1]=0.f; st_t[i][0]=st_t[i][1]=0.f; }

    #pragma unroll
    for (int ii=0;ii<4;ii++){
        #pragma unroll
        for (int rr=0;rr<2;rr++){
            int m = wm*64 + ii*16 + rr*8 + (lane>>2);
            float ga=0.f, be=0.f;
            if (STAT==2){ ga=g_gamma[m]; be=g_beta[m]; }
            #pragma unroll
            for (int jj=0;jj<4;jj++){
                #pragma unroll
                for (int j=0;j<2;j++){
                    int c = p0 + jj*16 + j*8 + (lane&3)*2;
                    size_t idx = ((size_t)b*512 + m)*HWN + c;
                    float v0 = acc[ii][jj][j][rr*2+0], v1 = acc[ii][jj][j][rr*2+1];
                    if (STAT==2){
                        float2 hv = ldbf2(aux+idx);
                        float hat0=(hv.x-bg_mu)*bg_rs, hat1=(hv.y-bg_mu)*bg_rs;
                        v0 *= gelu_grad(hat0*ga+be);
                        v1 *= gelu_grad(hat1*ga+be);
                        st_s[ii][rr] += v0+v1;
                        st_t[ii][rr] += v0*hat0 + v1*hat1;
                    }
                    *(unsigned*)(out+idx) = pack_bf2(v0, v1);
                }
            }
        }
    }

    if (STAT==2){
        #pragma unroll
        for (int ii=0;ii<4;ii++)
            #pragma unroll
            for (int rr=0;rr<2;rr++){
                float s=st_s[ii][rr], t=st_t[ii][rr];
                s += __shfl_xor_sync(0xffffffffu, s, 1); t += __shfl_xor_sync(0xffffffffu, t, 1);
                s += __shfl_xor_sync(0xffffffffu, s, 2); t += __shfl_xor_sync(0xffffffffu, t, 2);
                if ((lane&3)==0){
                    int m = wm*64 + ii*16 + rr*8 + (lane>>2);
                    g_rowp[((size_t)b*512 + m)*49 + blockIdx.x] = make_float2(s, t);
                }
            }
    }
}

// ============================================================================
// bf16 tensor-core GEMM (register path) — M=256 cases (gemm2, final).
// XOP: 3 X=gelu(GN(X))
// EPI: 1 +aux, 5 final out
// STAT: 0 none, 3 chan row partials
// ============================================================================
template<int XOP, int EPI, int BM, int STAT, typename TO>
__global__ __launch_bounds__(256,2) void gemm_bf16(
    const bft* __restrict__ W, const bft* __restrict__ X, TO* __restrict__ out,
    int M, int K,
    const float* __restrict__ mask, const bft* __restrict__ aux,
    const bft* __restrict__ y, const float* __restrict__ scal)
{
    constexpr int WPp = 2;
    constexpr int NJc = 2;
    constexpr int WMT = 4;
    constexpr int NW  = 4;
    __shared__ bft Ws[BM][40];
    __shared__ bft Xs[32][72];
    __shared__ float2 srow[BM][2];
    int b  = blockIdx.z;
    int m0 = blockIdx.y*BM, p0 = blockIdx.x*64;
    const bft* Xb = X + (size_t)b*K*HWN;
    int tid  = threadIdx.x;
    int lane = tid & 31, warp = tid >> 5;
    int wm = warp / WPp, wp = warp % WPp;
    float acc[WMT][NJc][2][4] = {};

    int xk = tid>>3, xc = (tid&7)*8;

    uint4 wreg[NW];
    uint4 xreg;

    auto load_tile = [&](int k0){
        const bft* w = W + (size_t)(m0 + tid)*K + k0;
        #pragma unroll
        for (int q=0;q<NW;q++) wreg[q] = *(const uint4*)(w + q*8);
        xreg = *(const uint4*)(Xb + (size_t)(k0+xk)*HWN + p0 + xc);
    };

    auto store_tile = [&](int k0){
        #pragma unroll
        for (int q=0;q<NW;q++) *(uint4*)&Ws[tid][q*8] = wreg[q];
        if (XOP==0){
            *(uint4*)&Xs[xk][xc] = xreg;
        } else {
            float vv[8]; unpack8(xreg, vv);
            int o = k0 + xk;
            int bg = b*NGRP + o/CGg;
            float mu=g_mu[bg], rs=g_rstd[bg], ga=g_gamma[o], be=g_beta[o];
            #pragma unroll
            for (int j=0;j<8;j++) vv[j] = geluf((vv[j]-mu)*rs*ga + be);
            *(uint4*)&Xs[xk][xc] = pack8(vv);
        }
    };

    const int NK = K >> 5;
    load_tile(0);
    for (int i = 0; i < NK; i++){
        store_tile(i*32);
        __syncthreads();
        if (i+1 < NK) load_tile((i+1)*32);

        #pragma unroll
        for (int h=0; h<2; h++){
            int kb = h*16;
            unsigned A[WMT][4];
            #pragma unroll
            for (int ii=0;ii<WMT;ii++)
                LDMX4(A[ii], smem_u32(&Ws[wm*(WMT*16) + ii*16 + (lane&15)][kb + (lane>>4)*8]));
            #pragma unroll
            for (int jj=0; jj<NJc; jj++){
                unsigned Bv[4];
                LDMX4T(Bv, smem_u32(&Xs[kb + (lane&7) + 8*((lane>>3)&1)][wp*(NJc*16) + jj*16 + 8*(lane>>4)]));
                #pragma unroll
                for (int ii=0;ii<WMT;ii++)
                    #pragma unroll
                    for (int j=0;j<2;j++) MMA16816(acc[ii][jj][j], A[ii], Bv[j*2], Bv[j*2+1]);
            }
        }
        __syncthreads();
    }

    float st_s[WMT][2];
    float st_t[WMT][2];
    #pragma unroll
    for (int i=0;i<WMT;i++){ st_s[i][0]=st_s[i][1]=0.f; st_t[i][0]=st_t[i][1]=0.f; }

    #pragma unroll
    for (int i=0;i<WMT;i++){
        int rbase = m0 + wm*(WMT*16) + i*16 + (lane>>2);
        #pragma unroll
        for (int jj=0;jj<NJc;jj++){
            #pragma unroll
            for (int j=0;j<2;j++){
                int c = p0 + wp*(NJc*16) + jj*16 + j*8 + (lane&3)*2;
                #pragma unroll
                for (int rr=0; rr<2; rr++){
                    int m = rbase + rr*8;
                    size_t idx = ((size_t)b*M + m)*HWN + c;
                    float v0 = acc[i][jj][j][rr*2+0], v1 = acc[i][jj][j][rr*2+1];
                    if (EPI==1){
                        float2 a = ldbf2(aux+idx);
                        v0 += a.x; v1 += a.y;
                    } else if (EPI==5){
                        float sc = scal[0]*g_gate[b];
                        float2 xf = *(const float2*)(mask+idx);   // mask = x (fp32)
                        v0 = xf.x + sc*v0; v1 = xf.y + sc*v1;
                    }
                    if (STAT==3){
                        st_s[i][rr] += v0+v1;
                        st_t[i][rr] += v0*v0 + v1*v1;
                    }
                    if (sizeof(TO)==4)
                        *(float2*)((float*)out+idx) = make_float2(v0, v1);
                    else
                        *(unsigned*)((bft*)out+idx) = pack_bf2(v0, v1);
                }
            }
        }
    }

    if (STAT==3){
        #pragma unroll
        for (int i=0;i<WMT;i++)
            #pragma unroll
            for (int rr=0;rr<2;rr++){
                float s=st_s[i][rr], t=st_t[i][rr];
                s += __shfl_xor_sync(0xffffffffu, s, 1); t += __shfl_xor_sync(0xffffffffu, t, 1);
                s += __shfl_xor_sync(0xffffffffu, s, 2); t += __shfl_xor_sync(0xffffffffu, t, 2);
                if ((lane&3)==0) srow[wm*(WMT*16) + i*16 + rr*8 + (lane>>2)][wp] = make_float2(s, t);
            }
        __syncthreads();
        if (tid < BM){
            float2 a = srow[tid][0], b2 = srow[tid][1];
            g_rowp[((size_t)b*M + m0 + tid)*49 + blockIdx.x] = make_float2(a.x+b2.x, a.y+b2.y);
        }
    }
}

__global__ void gn_reduce(){
    int bg = threadIdx.x;  // 128
    float s=0.f, sq=0.f;
    for (int i=0;i<49;i++){
        float2 v = g_gnp[(size_t)bg*49 + i];
        s += v.x; sq += v.y;
    }
    float n = (float)(CGg*HWN);
    float mean = s/n;
    float var  = sq/n - mean*mean;
    g_mu[bg] = mean;
    g_rstd[bg] = rsqrtf(var + 1e-5f);
}

__global__ void dgn_rowreduce(){
    int idx = blockIdx.x*blockDim.x + threadIdx.x;
    float s=0.f, t=0.f;
    for (int x=0; x<49; x++){
        float2 v = g_rowp[(size_t)idx*49 + x];
        s += v.x; t += v.y;
    }
    g_part[idx*2+0] = s;
    g_part[idx*2+1] = t;
}

__global__ void chan_reduce(const float* __restrict__ rm, const float* __restrict__ rv){
    int c = blockIdx.x;
    float s=0.f, sq=0.f;
    for (int i=threadIdx.x; i<BN*49; i+=256){
        int b=i/49, x=i%49;
        float2 v = g_rowp[((size_t)b*CC + c)*49 + x];
        s += v.x; sq += v.y;
    }
    block_reduce2(s, sq);
    if (threadIdx.x==0){
        float n = (float)NTOT;
        float cm = s/n;
        float cv = (sq - n*cm*cm)/(n - 1.0f);
        float rve = rv[c] + 1e-8f;
        g_cm[c] = cm;
        g_cA[c] = 0.1f*2.0f*(cm - rm[c])/(256.0f*n);
        g_cB[c] = 0.1f*4.0f*(cv/rve - 1.0f)/(rve*256.0f*(n - 1.0f));
    }
}

// ============================================================================
// NT GEMM 128x128, double-buffered, bf16 partial output.
// XOPB: 0 none, 3 B'=gelu(GN(B));  XOPA: 0 none, 1 A'=dh1 from stored dgn
// ============================================================================
template<int XOPB, int XOPA>
__global__ __launch_bounds__(256,2) void gemm_nt_bf16(
    const bft* __restrict__ A, const bft* __restrict__ Bm, const bft* __restrict__ Hm,
    bft* __restrict__ part, int Ma, int Nb)
{
    __shared__ bft As[2][128][40];
    __shared__ bft Bs[2][128][40];
    int z  = blockIdx.z;
    int m0 = blockIdx.y*128, n0 = blockIdx.x*128;
    int tid  = threadIdx.x;
    int lane = tid & 31, warp = tid >> 5;
    int wm = warp >> 1, wp = warp & 1;
    float acc[2][8][4] = {};

    int r  = tid >> 1, c0 = (tid & 1)*16;

    #define POFF(it) ((((it)%PBZ)*SPLITK + z)*32)
    #define AP(it) (A  + ((size_t)((it)/PBZ)*Ma + m0 + r)*HWN + POFF(it) + c0)
    #define BP(it) (Bm + ((size_t)((it)/PBZ)*Nb + n0 + r)*HWN + POFF(it) + c0)
    #define HP(it) (Hm + ((size_t)((it)/PBZ)*Ma + m0 + r)*HWN + POFF(it) + c0)

    uint4 a0, a1, b0, b1, h0, h1;
    auto load_it = [&](int it){
        a0 = *(const uint4*)AP(it); a1 = *(const uint4*)(AP(it)+8);
        b0 = *(const uint4*)BP(it); b1 = *(const uint4*)(BP(it)+8);
        if (XOPA==1){ h0 = *(const uint4*)HP(it); h1 = *(const uint4*)(HP(it)+8); }
    };
    auto store_it = [&](int buf, int it){
        if (XOPA==0){
            *(uint4*)&As[buf][r][c0]   = a0;
            *(uint4*)&As[buf][r][c0+8] = a1;
        } else {
            int b = it/PBZ;
            int o = m0 + r;
            int bg = b*NGRP + o/CGg;
            float mu=g_mu[bg], rs=g_rstd[bg], ga=g_gamma[o];
            float s1=g_s1[bg], s2=g_s2[bg];
            float av[8], hv[8];
            unpack8(a0, av); unpack8(h0, hv);
            #pragma unroll
            for (int j=0;j<8;j++){
                float hat=(hv[j]-mu)*rs;
                av[j] = rs*(av[j]*ga - s1 - hat*s2);
            }
            *(uint4*)&As[buf][r][c0] = pack8(av);
            unpack8(a1, av); unpack8(h1, hv);
            #pragma unroll
            for (int j=0;j<8;j++){
                float hat=(hv[j]-mu)*rs;
                av[j] = rs*(av[j]*ga - s1 - hat*s2);
            }
            *(uint4*)&As[buf][r][c0+8] = pack8(av);
        }
        if (XOPB==0){
            *(uint4*)&Bs[buf][r][c0]   = b0;
            *(uint4*)&Bs[buf][r][c0+8] = b1;
        } else {
            int b = it/PBZ;
            int o = n0 + r;
            int bg = b*NGRP + o/CGg;
            float mu=g_mu[bg], rs=g_rstd[bg], ga=g_gamma[o], be=g_beta[o];
            float v[8];
            unpack8(b0, v);
            #pragma unroll
            for (int j=0;j<8;j++) v[j] = geluf((v[j]-mu)*rs*ga + be);
            *(uint4*)&Bs[buf][r][c0] = pack8(v);
            unpack8(b1, v);
            #pragma unroll
            for (int j=0;j<8;j++) v[j] = geluf((v[j]-mu)*rs*ga + be);
            *(uint4*)&Bs[buf][r][c0+8] = pack8(v);
        }
    };

    load_it(0);
    store_it(0, 0);
    __syncthreads();

    const int ITERS = BN*PBZ;
    for (int it=0; it<ITERS; it++){
        int cur = it & 1;
        if (it+1 < ITERS) load_it(it+1);

        #pragma unroll
        for (int h=0; h<2; h++){
            int kb = h*16;
            unsigned Af[2][4];
            #pragma unroll
            for (int i=0;i<2;i++)
                LDMX4(Af[i], smem_u32(&As[cur][wm*32 + i*16 + (lane&15)][kb + (lane>>4)*8]));
            #pragma unroll
            for (int jj=0; jj<4; jj++){
                unsigned Bv[4];
                LDMX4(Bv, smem_u32(&Bs[cur][wp*64 + jj*16 + (lane&7) + 8*(lane>>4)][kb + 8*((lane>>3)&1)]));
                #pragma unroll
                for (int i=0;i<2;i++)
                    #pragma unroll
                    for (int j=0;j<2;j++) MMA16816(acc[i][jj*2+j], Af[i], Bv[j*2], Bv[j*2+1]);
            }
        }
        if (it+1 < ITERS) store_it(cur^1, it+1);
        __syncthreads();
    }
    #undef AP
    #undef BP
    #undef HP
    #undef POFF

    #pragma unroll
    for (int i=0;i<2;i++){
        int rbase = m0 + wm*32 + i*16 + (lane>>2);
        #pragma unroll
        for (int jc=0;jc<8;jc++){
            int n = n0 + wp*64 + (jc>>1)*16 + (jc&1)*8 + (lane&3)*2;
            #pragma unroll
            for (int rr=0; rr<2; rr++){
                int m = rbase + rr*8;
                size_t idx = ((size_t)z*Ma + m)*Nb + n;
                *(unsigned*)(part+idx) = pack_bf2(acc[i][jc][rr*2], acc[i][jc][rr*2+1]);
            }
        }
    }
}

__global__ void reduce_part(){
    int t = threadIdx.x;  // 512
    float db=0.f, dga=0.f;
    for (int b=0;b<BN;b++){
        db  += g_part[(b*HIDN+t)*2+0];
        dga += g_part[(b*HIDN+t)*2+1];
    }
    g_dbeta[t]=db; g_dgamma[t]=dga;
    if (t < BN*NGRP){
        int b=t/NGRP, g=t%NGRP;
        float s1=0.f, s2=0.f;
        for (int j=0;j<CGg;j++){
            int o=g*CGg+j;
            float ga=g_gamma[o];
            s1 += ga*g_part[(b*HIDN+o)*2+0];
            s2 += ga*g_part[(b*HIDN+o)*2+1];
        }
        float inv = 1.0f/(float)(CGg*HWN);
        g_s1[t]=s1*inv; g_s2[t]=s2*inv;
    }
}

// fused: reduce both split buffers + SGD update + refresh bf16 copies
__global__ void update_fused(){
    int i2 = blockIdx.x*blockDim.x + threadIdx.x;   // 65536 (pairs)
    int i = i2*2;
    {   // W2 (g_split1, layout [z][c*HIDN+o])
        float s0=0.f, s1=0.f;
        const bft* p = g_split1 + i;
        for (int z=0; z<SPLITK; z++){
            float2 v = ldbf2(p + (size_t)z*HIDN*CC);
            s0 += v.x; s1 += v.y;
        }
        int c = i/HIDN, o = i%HIDN;
        float v0 = g_w2[i]   - LRc*s0;
        float v1 = g_w2[i+1] - LRc*s1;
        g_w2[i]=v0; g_w2[i+1]=v1;
        bft b0=__float2bfloat16(v0), b1=__float2bfloat16(v1);
        g_w2b[i]=b0; g_w2b[i+1]=b1;
        g_w2tb[o*CC+c]=b0; g_w2tb[(o+1)*CC+c]=b1;
    }
    {   // W1 (g_split2, layout [z][o*CC+c])
        float s0=0.f, s1=0.f;
        const bft* p = g_split2 + i;
        for (int z=0; z<SPLITK; z++){
            float2 v = ldbf2(p + (size_t)z*HIDN*CC);
            s0 += v.x; s1 += v.y;
        }
        float v0 = g_w1[i]   - LRc*s0;
        float v1 = g_w1[i+1] - LRc*s1;
        g_w1[i]=v0; g_w1[i+1]=v1;
        g_w1b[i]=__float2bfloat16(v0); g_w1b[i+1]=__float2bfloat16(v1);
    }
    if (i2 < HIDN){
        g_gamma[i2] -= LRc*g_dgamma[i2];
        g_beta[i2]  -= LRc*g_dbeta[i2];
    }
}

// ---------------- gate ----------------
__global__ void gate_kernel(const float* __restrict__ gw1, const float* __restrict__ gb1,
                            const float* __restrict__ gw2, const float* __restrict__ gb2){
    __shared__ float gh[BN*CU];
    int t = threadIdx.x;
    for (int j=t; j<BN*CU; j+=256){
        int b=j/CU, u=j%CU;
        float s = gb1[u];
        const float* pr = &g_pooled[b*CC];
        const float* wr = &gw1[u*CC];
        for (int c=0;c<CC;c++) s += pr[c]*wr[c];
        gh[j] = geluf(s);
    }
    __syncthreads();
    if (t < BN){
        float s = gb2[0];
        for (int u=0;u<CU;u++) s += gh[t*CU+u]*gw2[u];
        g_gate[t] = 1.0f/(1.0f + expf(-s));
    }
}

// ---------------- host orchestration ----------------
extern "C" void kernel_launch(void* const* d_in, const int* in_sizes, int n_in,
                              void* d_out, int out_size){
    const float* x        = (const float*)d_in[0];
    const float* conv1_w  = (const float*)d_in[1];
    const float* gn_gammaI= (const float*)d_in[2];
    const float* gn_betaI = (const float*)d_in[3];
    const float* conv2_w  = (const float*)d_in[4];
    const float* rw1      = (const float*)d_in[5];
    const float* rw2      = (const float*)d_in[6];
    const float* gw1      = (const float*)d_in[7];
    const float* gb1      = (const float*)d_in[8];
    const float* gw2      = (const float*)d_in[9];
    const float* gb2      = (const float*)d_in[10];
    const float* rscale   = (const float*)d_in[11];
    const float* rm       = (const float*)d_in[12];
    const float* rv       = (const float*)d_in[13];
    const void*  masks    = d_in[14];

    void* p;
    #define SYMF(sym) (cudaGetSymbolAddress(&p, sym), (float*)p)
    #define SYMB(sym) (cudaGetSymbolAddress(&p, sym), (bft*)p)
    bft*   pw1b   = SYMB(g_w1b);
    bft*   pw2b   = SYMB(g_w2b);
    bft*   pw2tb  = SYMB(g_w2tb);
    bft*   ph1    = SYMB(g_h1);
    bft*   pdg    = SYMB(g_dg);
    bft*   py     = SYMB(g_y);
    bft*   pdy    = SYMB(g_dy);
    bft*   pxb    = SYMB(g_xb);
    bft*   psplit1= SYMB(g_split1);
    bft*   psplit2= SYMB(g_split2);
    float* pmaskf = SYMF(g_maskf);
    float* pdscale= SYMF(g_dscale);
    #undef SYMF
    #undef SYMB

    const int SMEM512 = 3*WSTG + 3*XSTG;   // 136704
    cudaFuncSetAttribute(gemm512<1>, cudaFuncAttributeMaxDynamicSharedMemorySize, SMEM512);
    cudaFuncSetAttribute(gemm512<2>, cudaFuncAttributeMaxDynamicSharedMemorySize, SMEM512);
    cudaFuncSetAttribute(surprise_fused, cudaFuncAttributeMaxDynamicSharedMemorySize, SF_SMEM);

    // init
    reset_copy<<<512,256>>>(conv1_w, gn_gammaI, gn_betaI, conv2_w, rw1, rw2);
    mask_detect<<<32,256>>>((const unsigned int*)masks);
    convert_pool<<<dim3(CC,BN),256>>>(x, pxb);

    for (int s=0; s<2; s++){
        const float* mk = pmaskf + (size_t)s*NTOT;
        const float* sc = pdscale + s;

        // forward
        gemm512<1><<<dim3(49,1,BN),256,SMEM512>>>(pw1b, pxb, ph1, nullptr);
        gn_reduce<<<1,128>>>();
        if (s==0){
            mask_convert<<<98,1024>>>(masks);
            inv_scale_kernel<<<1,128>>>();
        }
        gemm_bf16<3,1,256,3,bft><<<dim3(49,1,BN),256>>>(pw2b, ph1, py, 256,512, nullptr, pxb, nullptr,nullptr);
        chan_reduce<<<256,256>>>(rm, rv);

        // surprise chain fully fused (pre, drec, dpre, dy)
        surprise_fused<<<dim3(49,1,BN),256,SF_SMEM>>>(py, pdy, mk, sc);

        // backward through modifier (emits dgn + per-row partials)
        gemm512<2><<<dim3(49,1,BN),256,SMEM512>>>(pw2tb, pdy, pdg, ph1);
        dgn_rowreduce<<<32,256>>>();
        reduce_part<<<1,512>>>();

        gemm_nt_bf16<3,0><<<dim3(4,2,SPLITK),256>>>(pdy, ph1, nullptr, psplit1, 256,512);   // dW2
        gemm_nt_bf16<0,1><<<dim3(2,4,SPLITK),256>>>(pdg, pxb, ph1,     psplit2, 512,256);   // dW1
        update_fused<<<256,256>>>();
    }

    // gate (pooled computed in convert_pool)
    gate_kernel<<<1,256>>>(gw1, gb1, gw2, gb2);

    // final forward (fused output)
    gemm512<1><<<dim3(49,1,BN),256,SMEM512>>>(pw1b, pxb, ph1, nullptr);
    gn_reduce<<<1,128>>>();
    gemm_bf16<3,5,256,0,float><<<dim3(49,1,BN),256>>>(pw2b, ph1, (float*)d_out, 256,512, x, nullptr, nullptr, rscale);

    (void)in_sizes; (void)n_in; (void)out_size;
}

// round 16
// speedup vs baseline: 1.7945x; 1.0688x over previous
#include <cuda_runtime.h>
#include <cuda_bf16.h>
#include <cuda_fp16.h>
#include <cstdint>
#include <math.h>

// ---------------- problem constants ----------------
#define BN    16
#define CC    256
#define HIDN  512
#define NGRP  8
#define CGg   64
#define HWN   3136
#define CU    64
#define NTOT  (BN*HWN)
#define LRc   0.01f
#define SPLITK 98
#define PBZ   1           // (HWN/32)/SPLITK

typedef __nv_bfloat16 bft;

// ---------------- device scratch ----------------
__device__ float g_w1[HIDN*CC];
__device__ float g_w2[CC*HIDN];
__device__ float g_gamma[HIDN];
__device__ float g_beta[HIDN];

__device__ bft    g_w2tb[HIDN*CC];
__device__ __half g_w1h [HIDN*CC];
__device__ __half g_w2h [CC*HIDN];
__device__ bft g_rw1b [CU*CC];
__device__ bft g_rw1tb[CC*CU];
__device__ bft g_rw2b [CC*CU];
__device__ bft g_rw2tb[CU*CC];

__device__ bft    g_h1 [(size_t)BN*HIDN*HWN];
__device__ bft    g_dg [(size_t)BN*HIDN*HWN];
__device__ bft    g_y  [(size_t)BN*CC*HWN];
__device__ bft    g_dy [(size_t)BN*CC*HWN];
__device__ bft    g_xb [(size_t)BN*CC*HWN];
__device__ __half g_xh [(size_t)BN*CC*HWN];

__device__ float g_mu[BN*NGRP];
__device__ float g_rstd[BN*NGRP];
__device__ float2 g_gnp[BN*NGRP*49];
__device__ float2 g_rowp[(size_t)BN*HIDN*49];
__device__ float g_part[BN*HIDN*2];
__device__ float g_s1[BN*NGRP], g_s2[BN*NGRP];
__device__ float g_dgamma[HIDN], g_dbeta[HIDN];
__device__ float g_cm[CC], g_cA[CC], g_cB[CC];
__device__ bft g_split1[(size_t)SPLITK*HIDN*CC];
__device__ bft g_split2[(size_t)SPLITK*HIDN*CC];
__device__ float g_maskf[2*NTOT];
__device__ float2 g_mpart[98];
__device__ float g_dscale[2];
__device__ float g_pooled[BN*CC];
__device__ float g_gate[BN];
__device__ int   g_flagF, g_flagW;

// ---------------- math helpers ----------------
__device__ __forceinline__ float geluf(float x){
    return 0.5f*x*(1.0f + erff(x*0.70710678118654752440f));
}
__device__ __forceinline__ float gelu_grad(float x){
    float cdf = 0.5f*(1.0f + erff(x*0.70710678118654752440f));
    float pdf = 0.3989422804014327f*__expf(-0.5f*x*x);
    return cdf + x*pdf;
}
__device__ __forceinline__ void block_reduce2(float& a, float& b){
    __shared__ float sa[256], sb[256];
    int t = threadIdx.x;
    sa[t]=a; sb[t]=b; __syncthreads();
    for (int s=128; s>0; s>>=1){
        if (t<s){ sa[t]+=sa[t+s]; sb[t]+=sb[t+s]; }
        __syncthreads();
    }
    a=sa[0]; b=sb[0];
}
__device__ __forceinline__ unsigned pack_bf2(float a, float b){
    __nv_bfloat162 p = __floats2bfloat162_rn(a, b);
    return *(unsigned*)&p;
}
__device__ __forceinline__ unsigned pack_h2(float a, float b){
    __half2 p = __floats2half2_rn(a, b);
    return *(unsigned*)&p;
}
__device__ __forceinline__ float2 h2f2(unsigned u){
    __half2 h = *(__half2*)&u;
    return __half22float2(h);
}
__device__ __forceinline__ unsigned smem_u32(const void* p){
    return (unsigned)__cvta_generic_to_shared(p);
}
__device__ __forceinline__ void unpack8(uint4 u, float* v){
    __nv_bfloat162 p;
    p=*(__nv_bfloat162*)&u.x; v[0]=__low2float(p); v[1]=__high2float(p);
    p=*(__nv_bfloat162*)&u.y; v[2]=__low2float(p); v[3]=__high2float(p);
    p=*(__nv_bfloat162*)&u.z; v[4]=__low2float(p); v[5]=__high2float(p);
    p=*(__nv_bfloat162*)&u.w; v[6]=__low2float(p); v[7]=__high2float(p);
}
__device__ __forceinline__ uint4 pack8(const float* v){
    uint4 u;
    u.x=pack_bf2(v[0],v[1]); u.y=pack_bf2(v[2],v[3]);
    u.z=pack_bf2(v[4],v[5]); u.w=pack_bf2(v[6],v[7]);
    return u;
}
__device__ __forceinline__ uint4 pack8h(const float* v){
    uint4 u;
    u.x=pack_h2(v[0],v[1]); u.y=pack_h2(v[2],v[3]);
    u.z=pack_h2(v[4],v[5]); u.w=pack_h2(v[6],v[7]);
    return u;
}
__device__ __forceinline__ float2 ldbf2(const bft* p){
    __nv_bfloat162 v = *(const __nv_bfloat162*)p;
    return make_float2(__low2float(v), __high2float(v));
}

#define LDMX4(A, addr) \
    asm volatile("ldmatrix.sync.aligned.m8n8.x4.shared.b16 {%0,%1,%2,%3}, [%4];" \
        : "=r"((A)[0]),"=r"((A)[1]),"=r"((A)[2]),"=r"((A)[3]) : "r"(addr))
#define LDMX4T(A, addr) \
    asm volatile("ldmatrix.sync.aligned.m8n8.x4.trans.shared.b16 {%0,%1,%2,%3}, [%4];" \
        : "=r"((A)[0]),"=r"((A)[1]),"=r"((A)[2]),"=r"((A)[3]) : "r"(addr))
#define MMA16816(d, A, b0, b1) \
    asm volatile("mma.sync.aligned.m16n8k16.row.col.f32.bf16.bf16.f32 " \
        "{%0,%1,%2,%3},{%4,%5,%6,%7},{%8,%9},{%0,%1,%2,%3};" \
        : "+f"((d)[0]),"+f"((d)[1]),"+f"((d)[2]),"+f"((d)[3]) \
        : "r"((A)[0]),"r"((A)[1]),"r"((A)[2]),"r"((A)[3]), "r"(b0),"r"(b1))
#define MMAF16(d, A, b0, b1) \
    asm volatile("mma.sync.aligned.m16n8k16.row.col.f16.f16.f16.f16 " \
        "{%0,%1},{%2,%3,%4,%5},{%6,%7},{%0,%1};" \
        : "+r"((d)[0]),"+r"((d)[1]) \
        : "r"((A)[0]),"r"((A)[1]),"r"((A)[2]),"r"((A)[3]), "r"(b0),"r"(b1))

// ---------------- init / mask handling ----------------
__global__ void reset_copy(const float* __restrict__ w1, const float* __restrict__ gam,
                           const float* __restrict__ bet, const float* __restrict__ w2,
                           const float* __restrict__ rw1, const float* __restrict__ rw2){
    int i = blockIdx.x*blockDim.x + threadIdx.x;
    if (i==0){ g_flagF=0; g_flagW=0; }
    if (i < HIDN*CC){ float v=w1[i]; g_w1[i]=v; g_w1h[i]=__float2half(v); }
    if (i < CC*HIDN){
        float v=w2[i]; g_w2[i]=v;
        g_w2h[i]=__float2half(v);
        int c=i/HIDN, o=i%HIDN;
        g_w2tb[o*CC+c]=__float2bfloat16(v);
    }
    if (i < CU*CC){
        bft bv=__float2bfloat16(rw1[i]);
        g_rw1b[i]=bv;
        int u=i/CC, c=i%CC;
        g_rw1tb[c*CU+u]=bv;
    }
    if (i < CC*CU){
        bft bv=__float2bfloat16(rw2[i]);
        g_rw2b[i]=bv;
        int c=i/CU, u=i%CU;
        g_rw2tb[u*CC+c]=bv;
    }
    if (i < HIDN){ g_gamma[i]=gam[i]; g_beta[i]=bet[i]; }
}

__global__ void mask_detect(const unsigned int* __restrict__ mw){
    int f=0, wd=0;
    for (int i = blockIdx.x*blockDim.x + threadIdx.x; i < 25088; i += gridDim.x*blockDim.x){
        unsigned v = mw[i];
        if (v == 0x3F800000u) f = 1;
        else if (v != 0u && v != 1u) wd = 1;
    }
    if (f)  atomicOr(&g_flagF, 1);
    if (wd) atomicOr(&g_flagW, 1);
}

__global__ void mask_convert(const void* __restrict__ mp){
    int mode = g_flagW ? 2 : (g_flagF ? 1 : 0);
    int n = 2*NTOT;
    float c0 = 0.f, c1 = 0.f;
    for (int i = blockIdx.x*blockDim.x + threadIdx.x; i < n; i += gridDim.x*blockDim.x){
        bool v;
        if (mode==0)      v = ((const int*)mp)[i] != 0;
        else if (mode==1) v = ((const float*)mp)[i] != 0.0f;
        else              v = ((const unsigned char*)mp)[i] != 0;
        g_maskf[i] = v ? 1.0f : 0.0f;
        if (!v){ if (i < NTOT) c0 += 1.0f; else c1 += 1.0f; }
    }
    __shared__ float sa[32], sb[32];
    int lane = threadIdx.x & 31, w = threadIdx.x >> 5;
    #pragma unroll
    for (int off=16; off; off>>=1){
        c0 += __shfl_xor_sync(0xffffffffu, c0, off);
        c1 += __shfl_xor_sync(0xffffffffu, c1, off);
    }
    if (lane==0){ sa[w]=c0; sb[w]=c1; }
    __syncthreads();
    if (threadIdx.x==0){
        float a=0.f, b=0.f;
        for (int j=0;j<32;j++){ a+=sa[j]; b+=sb[j]; }
        g_mpart[blockIdx.x] = make_float2(a, b);
    }
}

__global__ void inv_scale_kernel(){
    int t = threadIdx.x;  // 128
    float a = 0.f, b = 0.f;
    if (t < 98){ float2 v = g_mpart[t]; a=v.x; b=v.y; }
    __shared__ float sa[128], sb[128];
    sa[t]=a; sb[t]=b; __syncthreads();
    for (int s=64; s>0; s>>=1){
        if (t<s){ sa[t]+=sa[t+s]; sb[t]+=sb[t+s]; }
        __syncthreads();
    }
    if (t==0){
        g_dscale[0] = 2.0f/(sa[0]*256.0f + 1e-8f);
        g_dscale[1] = 2.0f/(sb[0]*256.0f + 1e-8f);
    }
}

// fused: x -> bf16 + fp16 copies + channel mean (pooled)
__global__ void convert_pool(const float* __restrict__ x, bft* __restrict__ xb,
                             __half* __restrict__ xh){
    int c = blockIdx.x, b = blockIdx.y;
    size_t base = ((size_t)b*CC + c)*HWN;
    float s = 0.f, d = 0.f;
    for (int i = threadIdx.x; i < HWN/8; i += 256){
        size_t off = base + (size_t)i*8;
        float4 a0 = *(const float4*)(x+off);
        float4 a1 = *(const float4*)(x+off+4);
        float v[8] = {a0.x,a0.y,a0.z,a0.w,a1.x,a1.y,a1.z,a1.w};
        *(uint4*)(xb+off) = pack8(v);
        *(uint4*)(xh+off) = pack8h(v);
        #pragma unroll
        for (int j=0;j<8;j++) s += v[j];
    }
    block_reduce2(s, d);
    if (threadIdx.x==0) g_pooled[b*CC+c] = s/(float)HWN;
}

// ============================================================================
// surprise_fused (unchanged from R15)
// ============================================================================
#define SF_YS   0
#define SF_DS   36864
#define SF_WB1  73728
#define SF_WB2  107520
#define SF_PG   144384
#define SF_GP   153600
#define SF_DPS  162816
#define SF_SMEM 172032

__global__ __launch_bounds__(256) void surprise_fused(
    const bft* __restrict__ Y, bft* __restrict__ DY,
    const float* __restrict__ mask, const float* __restrict__ scal)
{
    extern __shared__ char dsm[];
    bft* ys  = (bft*)(dsm + SF_YS);
    bft* ds  = (bft*)(dsm + SF_DS);
    bft* wb1 = (bft*)(dsm + SF_WB1);
    bft* wb2 = (bft*)(dsm + SF_WB2);
    bft* pg  = (bft*)(dsm + SF_PG);
    bft* gp  = (bft*)(dsm + SF_GP);
    bft* dps = (bft*)(dsm + SF_DPS);
    int b = blockIdx.z;
    int p0 = blockIdx.x*64;
    int tid=threadIdx.x, lane=tid&31, warp=tid>>5;
    const bft* Yb = Y + (size_t)b*CC*HWN;
    const float* mr = mask + (size_t)b*HWN + p0;

    #pragma unroll
    for (int j=0;j<8;j++){
        int idx = tid + j*256;
        { int row=idx>>3, col=(idx&7)*8;
          *(uint4*)&ys[row*72+col] = *(const uint4*)(Yb + (size_t)row*HWN + p0 + col); }
        { int row=idx>>5, col=(idx&31)*8;
          *(uint4*)&wb1[row*264+col] = *(const uint4*)(g_rw1b + row*256 + col); }
        { int row=idx>>3, col=(idx&7)*8;
          *(uint4*)&wb2[row*72+col] = *(const uint4*)(g_rw2b + row*64 + col); }
    }
    __syncthreads();

    {   // Stage A
        int wm = warp>>2, wp = warp&3;
        float acc[2][2][4] = {};
        for (int kb=0; kb<256; kb+=16){
            unsigned A[2][4];
            #pragma unroll
            for (int i=0;i<2;i++)
                LDMX4(A[i], smem_u32(&wb1[(wm*32+i*16+(lane&15))*264 + kb + (lane>>4)*8]));
            unsigned Bv[4];
            LDMX4T(Bv, smem_u32(&ys[(kb + (lane&7) + 8*((lane>>3)&1))*72 + wp*16 + 8*(lane>>4)]));
            #pragma unroll
            for (int i=0;i<2;i++)
                #pragma unroll
                for (int j=0;j<2;j++) MMA16816(acc[i][j], A[i], Bv[j*2], Bv[j*2+1]);
        }
        #pragma unroll
        for (int i=0;i<2;i++)
            #pragma unroll
            for (int j=0;j<2;j++)
                #pragma unroll
                for (int rr=0;rr<2;rr++){
                    int m = wm*32+i*16+rr*8+(lane>>2);
                    int c = wp*16 + j*8 + (lane&3)*2;
                    float v0 = acc[i][j][rr*2]  *mr[c];
                    float v1 = acc[i][j][rr*2+1]*mr[c+1];
                    *(unsigned*)&pg[m*72+c] = pack_bf2(geluf(v0), geluf(v1));
                    *(unsigned*)&gp[m*72+c] = pack_bf2(gelu_grad(v0), gelu_grad(v1));
                }
    }
    __syncthreads();

    #pragma unroll
    for (int j=0;j<8;j++){
        int idx = tid + j*256;
        int row=idx>>5, col=(idx&31)*8;
        *(uint4*)&wb1[row*264+col] = *(const uint4*)(g_rw2tb + row*256 + col);
    }

    {   // Stage B
        float acc[2][4][2][4] = {};
        for (int kb=0; kb<64; kb+=16){
            unsigned A[2][4];
            #pragma unroll
            for (int i=0;i<2;i++)
                LDMX4(A[i], smem_u32(&wb2[(warp*32+i*16+(lane&15))*72 + kb + (lane>>4)*8]));
            #pragma unroll
            for (int jj=0;jj<4;jj++){
                unsigned Bv[4];
                LDMX4T(Bv, smem_u32(&pg[(kb + (lane&7) + 8*((lane>>3)&1))*72 + jj*16 + 8*(lane>>4)]));
                #pragma unroll
                for (int i=0;i<2;i++)
                    #pragma unroll
                    for (int j=0;j<2;j++) MMA16816(acc[i][jj][j], A[i], Bv[j*2], Bv[j*2+1]);
            }
        }
        float sc = scal[0];
        #pragma unroll
        for (int i=0;i<2;i++)
            #pragma unroll
            for (int jj=0;jj<4;jj++)
                #pragma unroll
                for (int j=0;j<2;j++)
                    #pragma unroll
                    for (int rr=0;rr<2;rr++){
                        int m = warp*32+i*16+rr*8+(lane>>2);
                        int c = jj*16 + j*8 + (lane&3)*2;
                        float2 yv = ldbf2(&ys[m*72+c]);
                        float v0 = (acc[i][jj][j][rr*2]  -yv.x)*(1.0f-mr[c])  *sc;
                        float v1 = (acc[i][jj][j][rr*2+1]-yv.y)*(1.0f-mr[c+1])*sc;
                        *(unsigned*)&ds[m*72+c] = pack_bf2(v0, v1);
                    }
    }
    __syncthreads();

    #pragma unroll
    for (int j=0;j<8;j++){
        int idx = tid + j*256;
        int row=idx>>3, col=(idx&7)*8;
        *(uint4*)&wb2[row*72+col] = *(const uint4*)(g_rw1tb + row*64 + col);
    }

    {   // Stage C
        int wm = warp>>2, wp = warp&3;
        float acc[2][2][4] = {};
        for (int kb=0; kb<256; kb+=16){
            unsigned A[2][4];
            #pragma unroll
            for (int i=0;i<2;i++)
                LDMX4(A[i], smem_u32(&wb1[(wm*32+i*16+(lane&15))*264 + kb + (lane>>4)*8]));
            unsigned Bv[4];
            LDMX4T(Bv, smem_u32(&ds[(kb + (lane&7) + 8*((lane>>3)&1))*72 + wp*16 + 8*(lane>>4)]));
            #pragma unroll
            for (int i=0;i<2;i++)
                #pragma unroll
                for (int j=0;j<2;j++) MMA16816(acc[i][j], A[i], Bv[j*2], Bv[j*2+1]);
        }
        #pragma unroll
        for (int i=0;i<2;i++)
            #pragma unroll
            for (int j=0;j<2;j++)
                #pragma unroll
                for (int rr=0;rr<2;rr++){
                    int m = wm*32+i*16+rr*8+(lane>>2);
                    int c = wp*16 + j*8 + (lane&3)*2;
                    float2 gv = ldbf2(&gp[m*72+c]);
                    *(unsigned*)&dps[m*72+c] =
                        pack_bf2(acc[i][j][rr*2]*gv.x, acc[i][j][rr*2+1]*gv.y);
                }
    }
    __syncthreads();

    {   // Stage D
        float acc[2][4][2][4] = {};
        for (int kb=0; kb<64; kb+=16){
            unsigned A[2][4];
            #pragma unroll
            for (int i=0;i<2;i++)
                LDMX4(A[i], smem_u32(&wb2[(warp*32+i*16+(lane&15))*72 + kb + (lane>>4)*8]));
            #pragma unroll
            for (int jj=0;jj<4;jj++){
                unsigned Bv[4];
                LDMX4T(Bv, smem_u32(&dps[(kb + (lane&7) + 8*((lane>>3)&1))*72 + jj*16 + 8*(lane>>4)]));
                #pragma unroll
                for (int i=0;i<2;i++)
                    #pragma unroll
                    for (int j=0;j<2;j++) MMA16816(acc[i][jj][j], A[i], Bv[j*2], Bv[j*2+1]);
            }
        }
        #pragma unroll
        for (int i=0;i<2;i++)
            #pragma unroll
            for (int jj=0;jj<4;jj++)
                #pragma unroll
                for (int j=0;j<2;j++)
                    #pragma unroll
                    for (int rr=0;rr<2;rr++){
                        int m = warp*32+i*16+rr*8+(lane>>2);
                        int c = jj*16 + j*8 + (lane&3)*2;
                        float2 dsv = ldbf2(&ds[m*72+c]);
                        float2 yv  = ldbf2(&ys[m*72+c]);
                        float cA=g_cA[m], cBv=g_cB[m], cmv=g_cm[m];
                        float v0 = acc[i][jj][j][rr*2]  *mr[c]   - dsv.x + cA + cBv*(yv.x-cmv);
                        float v1 = acc[i][jj][j][rr*2+1]*mr[c+1] - dsv.y + cA + cBv*(yv.y-cmv);
                        *(unsigned*)(DY + ((size_t)b*CC + m)*HWN + p0 + c) = pack_bf2(v0, v1);
                    }
    }
}

// ============================================================================
// gemm512h: fp16 in / fp16 accum, M=512, K=256, 2-stage cp.async, occ 2.
// h1 = w1 @ x, emits GN group partials.
// ============================================================================
#define WSTG (512*40*2)
#define XSTG (32*72*2)
#define SMEM512H (2*WSTG + 2*XSTG)
__global__ __launch_bounds__(256,2) void gemm512h(
    const __half* __restrict__ W, const __half* __restrict__ X, bft* __restrict__ out)
{
    extern __shared__ char dsm[];
    const unsigned WsU = smem_u32(dsm);                  // [2][512][40]
    const unsigned XsU = WsU + 2*WSTG;                   // [2][32][72]
    int b  = blockIdx.z;
    int p0 = blockIdx.x*64;
    const __half* Xb = X + (size_t)b*256*HWN;
    int tid  = threadIdx.x;
    int lane = tid & 31, wm = tid >> 5;
    unsigned acc[4][4][2][2] = {};

    auto issue = [&](int it){
        int k0 = it*32;
        unsigned wb = WsU + (unsigned)((it&1)*WSTG);
        #pragma unroll
        for (int j=0;j<8;j++){
            int chunk = tid + j*256;
            int row = chunk>>2, q = chunk&3;
            unsigned dst = wb + (unsigned)((row*40 + q*8)*2);
            const __half* src = W + (size_t)row*256 + k0 + q*8;
            asm volatile("cp.async.cg.shared.global [%0], [%1], 16;" :: "r"(dst), "l"(src));
        }
        {
            int row = tid>>3, c = (tid&7)*8;
            unsigned dst = XsU + (unsigned)(((it&1)*32*72 + row*72 + c)*2);
            const __half* src = Xb + (size_t)(k0+row)*HWN + p0 + c;
            asm volatile("cp.async.cg.shared.global [%0], [%1], 16;" :: "r"(dst), "l"(src));
        }
        asm volatile("cp.async.commit_group;");
    };

    issue(0);
    #pragma unroll 1
    for (int it = 0; it < 8; it++){
        if (it + 1 < 8){
            issue(it+1);
            asm volatile("cp.async.wait_group 1;");
        } else {
            asm volatile("cp.async.wait_group 0;");
        }
        __syncthreads();
        unsigned wb  = WsU + (unsigned)((it&1)*WSTG);
        unsigned xb2 = XsU + (unsigned)((it&1)*32*72*2);
        #pragma unroll
        for (int h=0; h<2; h++){
            int kb = h*16;
            unsigned A[4][4];
            #pragma unroll
            for (int ii=0;ii<4;ii++)
                LDMX4(A[ii], wb + (unsigned)((((wm*64 + ii*16 + (lane&15))*40) + kb + (lane>>4)*8)*2));
            #pragma unroll
            for (int jj=0; jj<4; jj++){
                unsigned Bv[4];
                LDMX4T(Bv, xb2 + (unsigned)((((kb + (lane&7) + 8*((lane>>3)&1))*72) + jj*16 + 8*(lane>>4))*2));
                #pragma unroll
                for (int ii=0;ii<4;ii++)
                    #pragma unroll
                    for (int j=0;j<2;j++) MMAF16(acc[ii][jj][j], A[ii], Bv[j*2], Bv[j*2+1]);
            }
        }
        __syncthreads();
    }

    // GN group partials + store
    float s=0.f, sq=0.f;
    #pragma unroll
    for (int ii=0;ii<4;ii++)
        #pragma unroll
        for (int rr=0;rr<2;rr++){
            int m = wm*64 + ii*16 + rr*8 + (lane>>2);
            #pragma unroll
            for (int jj=0;jj<4;jj++)
                #pragma unroll
                for (int j=0;j<2;j++){
                    int c = p0 + jj*16 + j*8 + (lane&3)*2;
                    float2 vv = h2f2(acc[ii][jj][j][rr]);
                    s += vv.x+vv.y; sq += vv.x*vv.x + vv.y*vv.y;
                    *(unsigned*)(out + ((size_t)b*512 + m)*HWN + c) = pack_bf2(vv.x, vv.y);
                }
        }
    __shared__ float2 sgn[8];
    #pragma unroll
    for (int off=16; off; off>>=1){
        s  += __shfl_xor_sync(0xffffffffu, s, off);
        sq += __shfl_xor_sync(0xffffffffu, sq, off);
    }
    if (lane==0) sgn[wm] = make_float2(s, sq);
    __syncthreads();
    if (tid < 8){
        float2 v = sgn[tid];
        g_gnp[((size_t)b*NGRP + tid)*49 + blockIdx.x] = v;
    }
}

// ============================================================================
// gemm512: bf16/f32 path, 3-stage. STAT=2 only (dgn epilogue).
// ============================================================================
__global__ __launch_bounds__(256) void gemm512b(
    const bft* __restrict__ W, const bft* __restrict__ X, bft* __restrict__ out,
    const bft* __restrict__ aux)
{
    extern __shared__ char dsm[];
    const unsigned WsU = smem_u32(dsm);
    const unsigned XsU = WsU + 3*WSTG;
    int b  = blockIdx.z;
    int p0 = blockIdx.x*64;
    const bft* Xb = X + (size_t)b*256*HWN;
    int tid  = threadIdx.x;
    int lane = tid & 31, wm = tid >> 5;
    float acc[4][4][2][4] = {};

    auto issue = [&](int it){
        int k0 = it*32;
        int st = it % 3;
        unsigned wb = WsU + (unsigned)(st*WSTG);
        #pragma unroll
        for (int j=0;j<8;j++){
            int chunk = tid + j*256;
            int row = chunk>>2, q = chunk&3;
            unsigned dst = wb + (unsigned)((row*40 + q*8)*2);
            const bft* src = W + (size_t)row*256 + k0 + q*8;
            asm volatile("cp.async.cg.shared.global [%0], [%1], 16;" :: "r"(dst), "l"(src));
        }
        {
            int row = tid>>3, c = (tid&7)*8;
            unsigned dst = XsU + (unsigned)((st*32*72 + row*72 + c)*2);
            const bft* src = Xb + (size_t)(k0+row)*HWN + p0 + c;
            asm volatile("cp.async.cg.shared.global [%0], [%1], 16;" :: "r"(dst), "l"(src));
        }
        asm volatile("cp.async.commit_group;");
    };

    issue(0);
    issue(1);
    #pragma unroll 1
    for (int it = 0; it < 8; it++){
        if (it + 2 < 8){
            issue(it+2);
            asm volatile("cp.async.wait_group 2;");
        } else if (it + 1 < 8){
            asm volatile("cp.async.wait_group 1;");
        } else {
            asm volatile("cp.async.wait_group 0;");
        }
        __syncthreads();
        int st = it % 3;
        unsigned wb  = WsU + (unsigned)(st*WSTG);
        unsigned xb2 = XsU + (unsigned)(st*32*72*2);
        #pragma unroll
        for (int h=0; h<2; h++){
            int kb = h*16;
            unsigned A[4][4];
            #pragma unroll
            for (int ii=0;ii<4;ii++)
                LDMX4(A[ii], wb + (unsigned)((((wm*64 + ii*16 + (lane&15))*40) + kb + (lane>>4)*8)*2));
            #pragma unroll
            for (int jj=0; jj<4; jj++){
                unsigned Bv[4];
                LDMX4T(Bv, xb2 + (unsigned)((((kb + (lane&7) + 8*((lane>>3)&1))*72) + jj*16 + 8*(lane>>4))*2));
                #pragma unroll
                for (int ii=0;ii<4;ii++)
                    #pragma unroll
                    for (int j=0;j<2;j++) MMA16816(acc[ii][jj][j], A[ii], Bv[j*2], Bv[j*2+1]);
            }
        }
        __syncthreads();
    }

    int bg=b*NGRP+wm;
    float bg_mu=g_mu[bg], bg_rs=g_rstd[bg];

    float st_s[4][2], st_t[4][2];
    #pragma unroll
    for (int i=0;i<4;i++){ st_s[i][0]=st_s[i][1]=0.f; st_t[i][0]=st_t[i][1]=0.f; }

    #pragma unroll
    for (int ii=0;ii<4;ii++){
        #pragma unroll
        for (int rr=0;rr<2;rr++){
            int m = wm*64 + ii*16 + rr*8 + (lane>>2);
            float ga=g_gamma[m], be=g_beta[m];
            #pragma unroll
            for (int jj=0;jj<4;jj++){
                #pragma unroll
                for (int j=0;j<2;j++){
                    int c = p0 + jj*16 + j*8 + (lane&3)*2;
                    size_t idx = ((size_t)b*512 + m)*HWN + c;
                    float v0 = acc[ii][jj][j][rr*2+0], v1 = acc[ii][jj][j][rr*2+1];
                    float2 hv = ldbf2(aux+idx);
                    float hat0=(hv.x-bg_mu)*bg_rs, hat1=(hv.y-bg_mu)*bg_rs;
                    v0 *= gelu_grad(hat0*ga+be);
                    v1 *= gelu_grad(hat1*ga+be);
                    st_s[ii][rr] += v0+v1;
                    st_t[ii][rr] += v0*hat0 + v1*hat1;
                    *(unsigned*)(out+idx) = pack_bf2(v0, v1);
                }
            }
        }
    }

    #pragma unroll
    for (int ii=0;ii<4;ii++)
        #pragma unroll
        for (int rr=0;rr<2;rr++){
            float s=st_s[ii][rr], t=st_t[ii][rr];
            s += __shfl_xor_sync(0xffffffffu, s, 1); t += __shfl_xor_sync(0xffffffffu, t, 1);
            s += __shfl_xor_sync(0xffffffffu, s, 2); t += __shfl_xor_sync(0xffffffffu, t, 2);
            if ((lane&3)==0){
                int m = wm*64 + ii*16 + rr*8 + (lane>>2);
                g_rowp[((size_t)b*512 + m)*49 + blockIdx.x] = make_float2(s, t);
            }
        }
}

// ============================================================================
// gemm_f16: fp16 W / fp16 accum, M=256, K=512, X = gelu(GN(h1)) from bf16.
// EPI 1: + aux(xb), out bf16 (y). EPI 5: final out = xf + scal*gate*acc.
// STAT 3: chan row partials.
// ============================================================================
template<int EPI, int STAT>
__global__ __launch_bounds__(256,2) void gemm_f16(
    const __half* __restrict__ W, const bft* __restrict__ X, void* __restrict__ out_,
    const float* __restrict__ xf, const bft* __restrict__ aux,
    const float* __restrict__ scal)
{
    __shared__ __half Ws[256][40];
    __shared__ __half Xs[32][72];
    __shared__ float2 srow[256][2];
    int b  = blockIdx.z;
    int p0 = blockIdx.x*64;
    const bft* Xb = X + (size_t)b*512*HWN;
    int tid  = threadIdx.x;
    int lane = tid & 31, warp = tid >> 5;
    int wm = warp >> 1, wp = warp & 1;
    unsigned acc[4][2][2][2] = {};

    int xk = tid>>3, xc = (tid&7)*8;
    uint4 wreg[4];
    uint4 xreg;

    auto load_tile = [&](int k0){
        const __half* w = W + (size_t)tid*512 + k0;
        #pragma unroll
        for (int q=0;q<4;q++) wreg[q] = *(const uint4*)(w + q*8);
        xreg = *(const uint4*)(Xb + (size_t)(k0+xk)*HWN + p0 + xc);
    };

    auto store_tile = [&](int k0){
        #pragma unroll
        for (int q=0;q<4;q++) *(uint4*)&Ws[tid][q*8] = wreg[q];
        float vv[8]; unpack8(xreg, vv);
        int o = k0 + xk;
        int bg = b*NGRP + o/CGg;
        float mu=g_mu[bg], rs=g_rstd[bg], ga=g_gamma[o], be=g_beta[o];
        #pragma unroll
        for (int j=0;j<8;j++) vv[j] = geluf((vv[j]-mu)*rs*ga + be);
        *(uint4*)&Xs[xk][xc] = pack8h(vv);
    };

    load_tile(0);
    for (int i = 0; i < 16; i++){
        store_tile(i*32);
        __syncthreads();
        if (i+1 < 16) load_tile((i+1)*32);

        #pragma unroll
        for (int h=0; h<2; h++){
            int kb = h*16;
            unsigned A[4][4];
            #pragma unroll
            for (int ii=0;ii<4;ii++)
                LDMX4(A[ii], smem_u32(&Ws[wm*64 + ii*16 + (lane&15)][kb + (lane>>4)*8]));
            #pragma unroll
            for (int jj=0; jj<2; jj++){
                unsigned Bv[4];
                LDMX4T(Bv, smem_u32(&Xs[kb + (lane&7) + 8*((lane>>3)&1)][wp*32 + jj*16 + 8*(lane>>4)]));
                #pragma unroll
                for (int ii=0;ii<4;ii++)
                    #pragma unroll
                    for (int j=0;j<2;j++) MMAF16(acc[ii][jj][j], A[ii], Bv[j*2], Bv[j*2+1]);
            }
        }
        __syncthreads();
    }

    float st_s[4][2], st_t[4][2];
    #pragma unroll
    for (int i=0;i<4;i++){ st_s[i][0]=st_s[i][1]=0.f; st_t[i][0]=st_t[i][1]=0.f; }

    #pragma unroll
    for (int i=0;i<4;i++){
        #pragma unroll
        for (int rr=0;rr<2;rr++){
            int m = wm*64 + i*16 + rr*8 + (lane>>2);
            #pragma unroll
            for (int jj=0;jj<2;jj++){
                #pragma unroll
                for (int j=0;j<2;j++){
                    int c = p0 + wp*32 + jj*16 + j*8 + (lane&3)*2;
                    size_t idx = ((size_t)b*256 + m)*HWN + c;
                    float2 vv = h2f2(acc[i][jj][j][rr]);
                    float v0 = vv.x, v1 = vv.y;
                    if (EPI==1){
                        float2 a = ldbf2(aux+idx);
                        v0 += a.x; v1 += a.y;
                    } else {
                        float sc = scal[0]*g_gate[b];
                        float2 x2 = *(const float2*)(xf+idx);
                        v0 = x2.x + sc*v0; v1 = x2.y + sc*v1;
                    }
                    if (STAT==3){
                        st_s[i][rr] += v0+v1;
                        st_t[i][rr] += v0*v0 + v1*v1;
                    }
                    if (EPI==5)
                        *(float2*)((float*)out_+idx) = make_float2(v0, v1);
                    else
                        *(unsigned*)((bft*)out_+idx) = pack_bf2(v0, v1);
                }
            }
        }
    }

    if (STAT==3){
        #pragma unroll
        for (int i=0;i<4;i++)
            #pragma unroll
            for (int rr=0;rr<2;rr++){
                float s=st_s[i][rr], t=st_t[i][rr];
                s += __shfl_xor_sync(0xffffffffu, s, 1); t += __shfl_xor_sync(0xffffffffu, t, 1);
                s += __shfl_xor_sync(0xffffffffu, s, 2); t += __shfl_xor_sync(0xffffffffu, t, 2);
                if ((lane&3)==0) srow[wm*64 + i*16 + rr*8 + (lane>>2)][wp] = make_float2(s, t);
            }
        __syncthreads();
        if (tid < 256){
            float2 a = srow[tid][0], b2 = srow[tid][1];
            g_rowp[((size_t)b*256 + tid)*49 + blockIdx.x] = make_float2(a.x+b2.x, a.y+b2.y);
        }
    }
}

__global__ void gn_reduce(){
    int bg = threadIdx.x;  // 128
    float s=0.f, sq=0.f;
    for (int i=0;i<49;i++){
        float2 v = g_gnp[(size_t)bg*49 + i];
        s += v.x; sq += v.y;
    }
    float n = (float)(CGg*HWN);
    float mean = s/n;
    float var  = sq/n - mean*mean;
    g_mu[bg] = mean;
    g_rstd[bg] = rsqrtf(var + 1e-5f);
}

__global__ void dgn_rowreduce(){
    int idx = blockIdx.x*blockDim.x + threadIdx.x;
    float s=0.f, t=0.f;
    for (int x=0; x<49; x++){
        float2 v = g_rowp[(size_t)idx*49 + x];
        s += v.x; t += v.y;
    }
    g_part[idx*2+0] = s;
    g_part[idx*2+1] = t;
}

__global__ void chan_reduce(const float* __restrict__ rm, const float* __restrict__ rv){
    int c = blockIdx.x;
    float s=0.f, sq=0.f;
    for (int i=threadIdx.x; i<BN*49; i+=256){
        int b=i/49, x=i%49;
        float2 v = g_rowp[((size_t)b*CC + c)*49 + x];
        s += v.x; sq += v.y;
    }
    block_reduce2(s, sq);
    if (threadIdx.x==0){
        float n = (float)NTOT;
        float cm = s/n;
        float cv = (sq - n*cm*cm)/(n - 1.0f);
        float rve = rv[c] + 1e-8f;
        g_cm[c] = cm;
        g_cA[c] = 0.1f*2.0f*(cm - rm[c])/(256.0f*n);
        g_cB[c] = 0.1f*4.0f*(cv/rve - 1.0f)/(rve*256.0f*(n - 1.0f));
    }
}

// ============================================================================
// NT GEMM 128x128 (bf16/f32, unchanged)
// ============================================================================
template<int XOPB, int XOPA>
__global__ __launch_bounds__(256,2) void gemm_nt_bf16(
    const bft* __restrict__ A, const bft* __restrict__ Bm, const bft* __restrict__ Hm,
    bft* __restrict__ part, int Ma, int Nb)
{
    __shared__ bft As[2][128][40];
    __shared__ bft Bs[2][128][40];
    int z  = blockIdx.z;
    int m0 = blockIdx.y*128, n0 = blockIdx.x*128;
    int tid  = threadIdx.x;
    int lane = tid & 31, warp = tid >> 5;
    int wm = warp >> 1, wp = warp & 1;
    float acc[2][8][4] = {};

    int r  = tid >> 1, c0 = (tid & 1)*16;

    #define POFF(it) ((((it)%PBZ)*SPLITK + z)*32)
    #define AP(it) (A  + ((size_t)((it)/PBZ)*Ma + m0 + r)*HWN + POFF(it) + c0)
    #define BP(it) (Bm + ((size_t)((it)/PBZ)*Nb + n0 + r)*HWN + POFF(it) + c0)
    #define HP(it) (Hm + ((size_t)((it)/PBZ)*Ma + m0 + r)*HWN + POFF(it) + c0)

    uint4 a0, a1, b0, b1, h0, h1;
    auto load_it = [&](int it){
        a0 = *(const uint4*)AP(it); a1 = *(const uint4*)(AP(it)+8);
        b0 = *(const uint4*)BP(it); b1 = *(const uint4*)(BP(it)+8);
        if (XOPA==1){ h0 = *(const uint4*)HP(it); h1 = *(const uint4*)(HP(it)+8); }
    };
    auto store_it = [&](int buf, int it){
        if (XOPA==0){
            *(uint4*)&As[buf][r][c0]   = a0;
            *(uint4*)&As[buf][r][c0+8] = a1;
        } else {
            int b = it/PBZ;
            int o = m0 + r;
            int bg = b*NGRP + o/CGg;
            float mu=g_mu[bg], rs=g_rstd[bg], ga=g_gamma[o];
            float s1=g_s1[bg], s2=g_s2[bg];
            float av[8], hv[8];
            unpack8(a0, av); unpack8(h0, hv);
            #pragma unroll
            for (int j=0;j<8;j++){
                float hat=(hv[j]-mu)*rs;
                av[j] = rs*(av[j]*ga - s1 - hat*s2);
            }
            *(uint4*)&As[buf][r][c0] = pack8(av);
            unpack8(a1, av); unpack8(h1, hv);
            #pragma unroll
            for (int j=0;j<8;j++){
                float hat=(hv[j]-mu)*rs;
                av[j] = rs*(av[j]*ga - s1 - hat*s2);
            }
            *(uint4*)&As[buf][r][c0+8] = pack8(av);
        }
        if (XOPB==0){
            *(uint4*)&Bs[buf][r][c0]   = b0;
            *(uint4*)&Bs[buf][r][c0+8] = b1;
        } else {
            int b = it/PBZ;
            int o = n0 + r;
            int bg = b*NGRP + o/CGg;
            float mu=g_mu[bg], rs=g_rstd[bg], ga=g_gamma[o], be=g_beta[o];
            float v[8];
            unpack8(b0, v);
            #pragma unroll
            for (int j=0;j<8;j++) v[j] = geluf((v[j]-mu)*rs*ga + be);
            *(uint4*)&Bs[buf][r][c0] = pack8(v);
            unpack8(b1, v);
            #pragma unroll
            for (int j=0;j<8;j++) v[j] = geluf((v[j]-mu)*rs*ga + be);
            *(uint4*)&Bs[buf][r][c0+8] = pack8(v);
        }
    };

    load_it(0);
    store_it(0, 0);
    __syncthreads();

    const int ITERS = BN*PBZ;
    for (int it=0; it<ITERS; it++){
        int cur = it & 1;
        if (it+1 < ITERS) load_it(it+1);

        #pragma unroll
        for (int h=0; h<2; h++){
            int kb = h*16;
            unsigned Af[2][4];
            #pragma unroll
            for (int i=0;i<2;i++)
                LDMX4(Af[i], smem_u32(&As[cur][wm*32 + i*16 + (lane&15)][kb + (lane>>4)*8]));
            #pragma unroll
            for (int jj=0; jj<4; jj++){
                unsigned Bv[4];
                LDMX4(Bv, smem_u32(&Bs[cur][wp*64 + jj*16 + (lane&7) + 8*(lane>>4)][kb + 8*((lane>>3)&1)]));
                #pragma unroll
                for (int i=0;i<2;i++)
                    #pragma unroll
                    for (int j=0;j<2;j++) MMA16816(acc[i][jj*2+j], Af[i], Bv[j*2], Bv[j*2+1]);
            }
        }
        if (it+1 < ITERS) store_it(cur^1, it+1);
        __syncthreads();
    }
    #undef AP
    #undef BP
    #undef HP
    #undef POFF

    #pragma unroll
    for (int i=0;i<2;i++){
        int rbase = m0 + wm*32 + i*16 + (lane>>2);
        #pragma unroll
        for (int jc=0;jc<8;jc++){
            int n = n0 + wp*64 + (jc>>1)*16 + (jc&1)*8 + (lane&3)*2;
            #pragma unroll
            for (int rr=0; rr<2; rr++){
                int m = rbase + rr*8;
                size_t idx = ((size_t)z*Ma + m)*Nb + n;
                *(unsigned*)(part+idx) = pack_bf2(acc[i][jc][rr*2], acc[i][jc][rr*2+1]);
            }
        }
    }
}

__global__ void reduce_part(){
    int t = threadIdx.x;  // 512
    float db=0.f, dga=0.f;
    for (int b=0;b<BN;b++){
        db  += g_part[(b*HIDN+t)*2+0];
        dga += g_part[(b*HIDN+t)*2+1];
    }
    g_dbeta[t]=db; g_dgamma[t]=dga;
    if (t < BN*NGRP){
        int b=t/NGRP, g=t%NGRP;
        float s1=0.f, s2=0.f;
        for (int j=0;j<CGg;j++){
            int o=g*CGg+j;
            float ga=g_gamma[o];
            s1 += ga*g_part[(b*HIDN+o)*2+0];
            s2 += ga*g_part[(b*HIDN+o)*2+1];
        }
        float inv = 1.0f/(float)(CGg*HWN);
        g_s1[t]=s1*inv; g_s2[t]=s2*inv;
    }
}

// fused: reduce both split buffers + SGD update + refresh fp16/bf16 copies
__global__ void update_fused(){
    int i2 = blockIdx.x*blockDim.x + threadIdx.x;
    int i = i2*2;
    {   // W2
        float s0=0.f, s1=0.f;
        const bft* p = g_split1 + i;
        for (int z=0; z<SPLITK; z++){
            float2 v = ldbf2(p + (size_t)z*HIDN*CC);
            s0 += v.x; s1 += v.y;
        }
        int c = i/HIDN, o = i%HIDN;
        float v0 = g_w2[i]   - LRc*s0;
        float v1 = g_w2[i+1] - LRc*s1;
        g_w2[i]=v0; g_w2[i+1]=v1;
        g_w2h[i]=__float2half(v0); g_w2h[i+1]=__float2half(v1);
        g_w2tb[o*CC+c]=__float2bfloat16(v0); g_w2tb[(o+1)*CC+c]=__float2bfloat16(v1);
    }
    {   // W1
        float s0=0.f, s1=0.f;
        const bft* p = g_split2 + i;
        for (int z=0; z<SPLITK; z++){
            float2 v = ldbf2(p + (size_t)z*HIDN*CC);
            s0 += v.x; s1 += v.y;
        }
        float v0 = g_w1[i]   - LRc*s0;
        float v1 = g_w1[i+1] - LRc*s1;
        g_w1[i]=v0; g_w1[i+1]=v1;
        g_w1h[i]=__float2half(v0); g_w1h[i+1]=__float2half(v1);
    }
    if (i2 < HIDN){
        g_gamma[i2] -= LRc*g_dgamma[i2];
        g_beta[i2]  -= LRc*g_dbeta[i2];
    }
}

// ---------------- gate ----------------
__global__ void gate_kernel(const float* __restrict__ gw1, const float* __restrict__ gb1,
                            const float* __restrict__ gw2, const float* __restrict__ gb2){
    __shared__ float gh[BN*CU];
    int t = threadIdx.x;
    for (int j=t; j<BN*CU; j+=256){
        int b=j/CU, u=j%CU;
        float s = gb1[u];
        const float* pr = &g_pooled[b*CC];
        const float* wr = &gw1[u*CC];
        for (int c=0;c<CC;c++) s += pr[c]*wr[c];
        gh[j] = geluf(s);
    }
    __syncthreads();
    if (t < BN){
        float s = gb2[0];
        for (int u=0;u<CU;u++) s += gh[t*CU+u]*gw2[u];
        g_gate[t] = 1.0f/(1.0f + expf(-s));
    }
}

// ---------------- host orchestration ----------------
extern "C" void kernel_launch(void* const* d_in, const int* in_sizes, int n_in,
                              void* d_out, int out_size){
    const float* x        = (const float*)d_in[0];
    const float* conv1_w  = (const float*)d_in[1];
    const float* gn_gammaI= (const float*)d_in[2];
    const float* gn_betaI = (const float*)d_in[3];
    const float* conv2_w  = (const float*)d_in[4];
    const float* rw1      = (const float*)d_in[5];
    const float* rw2      = (const float*)d_in[6];
    const float* gw1      = (const float*)d_in[7];
    const float* gb1      = (const float*)d_in[8];
    const float* gw2      = (const float*)d_in[9];
    const float* gb2      = (const float*)d_in[10];
    const float* rscale   = (const float*)d_in[11];
    const float* rm       = (const float*)d_in[12];
    const float* rv       = (const float*)d_in[13];
    const void*  masks    = d_in[14];

    void* p;
    #define SYMF(sym) (cudaGetSymbolAddress(&p, sym), (float*)p)
    #define SYMB(sym) (cudaGetSymbolAddress(&p, sym), (bft*)p)
    #define SYMH(sym) (cudaGetSymbolAddress(&p, sym), (__half*)p)
    __half* pw1h  = SYMH(g_w1h);
    __half* pw2h  = SYMH(g_w2h);
    bft*   pw2tb  = SYMB(g_w2tb);
    bft*   ph1    = SYMB(g_h1);
    bft*   pdg    = SYMB(g_dg);
    bft*   py     = SYMB(g_y);
    bft*   pdy    = SYMB(g_dy);
    bft*   pxb    = SYMB(g_xb);
    __half* pxh   = SYMH(g_xh);
    bft*   psplit1= SYMB(g_split1);
    bft*   psplit2= SYMB(g_split2);
    float* pmaskf = SYMF(g_maskf);
    float* pdscale= SYMF(g_dscale);
    #undef SYMF
    #undef SYMB
    #undef SYMH

    const int SMEM512 = 3*WSTG + 3*XSTG;
    cudaFuncSetAttribute(gemm512b, cudaFuncAttributeMaxDynamicSharedMemorySize, SMEM512);
    cudaFuncSetAttribute(gemm512h, cudaFuncAttributeMaxDynamicSharedMemorySize, SMEM512H);
    cudaFuncSetAttribute(surprise_fused, cudaFuncAttributeMaxDynamicSharedMemorySize, SF_SMEM);

    // init
    reset_copy<<<512,256>>>(conv1_w, gn_gammaI, gn_betaI, conv2_w, rw1, rw2);
    mask_detect<<<32,256>>>((const unsigned int*)masks);
    convert_pool<<<dim3(CC,BN),256>>>(x, pxb, pxh);

    for (int s=0; s<2; s++){
        const float* mk = pmaskf + (size_t)s*NTOT;
        const float* sc = pdscale + s;

        // forward
        gemm512h<<<dim3(49,1,BN),256,SMEM512H>>>(pw1h, pxh, ph1);
        gn_reduce<<<1,128>>>();
        if (s==0){
            mask_convert<<<98,1024>>>(masks);
            inv_scale_kernel<<<1,128>>>();
        }
        gemm_f16<1,3><<<dim3(49,1,BN),256>>>(pw2h, ph1, py, nullptr, pxb, nullptr);
        chan_reduce<<<256,256>>>(rm, rv);

        // surprise chain fully fused
        surprise_fused<<<dim3(49,1,BN),256,SF_SMEM>>>(py, pdy, mk, sc);

        // backward through modifier
        gemm512b<<<dim3(49,1,BN),256,SMEM512>>>(pw2tb, pdy, pdg, ph1);
        dgn_rowreduce<<<32,256>>>();
        reduce_part<<<1,512>>>();

        gemm_nt_bf16<3,0><<<dim3(4,2,SPLITK),256>>>(pdy, ph1, nullptr, psplit1, 256,512);
        gemm_nt_bf16<0,1><<<dim3(2,4,SPLITK),256>>>(pdg, pxb, ph1,     psplit2, 512,256);
        update_fused<<<256,256>>>();
    }

    // gate
    gate_kernel<<<1,256>>>(gw1, gb1, gw2, gb2);

    // final forward (fused output)
    gemm512h<<<dim3(49,1,BN),256,SMEM512H>>>(pw1h, pxh, ph1);
    gn_reduce<<<1,128>>>();
    gemm_f16<5,0><<<dim3(49,1,BN),256>>>(pw2h, ph1, (float*)d_out, x, nullptr, rscale);

    (void)in_sizes; (void)n_in; (void)out_size;
}

// round 17
// speedup vs baseline: 1.8538x; 1.0330x over previous
#include <cuda_runtime.h>
#include <cuda_bf16.h>
#include <cuda_fp16.h>
#include <cstdint>
#include <math.h>

// ---------------- problem constants ----------------
#define BN    16
#define CC    256
#define HIDN  512
#define NGRP  8
#define CGg   64
#define HWN   3136
#define CU    64
#define NTOT  (BN*HWN)
#define LRc   0.01f
#define SPLITK 98
#define PBZ   1           // (HWN/32)/SPLITK

typedef __nv_bfloat16 bft;

// ---------------- device scratch ----------------
__device__ float g_w1[HIDN*CC];
__device__ float g_w2[CC*HIDN];
__device__ float g_gamma[HIDN];
__device__ float g_beta[HIDN];

__device__ bft    g_w2tb[HIDN*CC];
__device__ __half g_w1h [HIDN*CC];
__device__ __half g_w2h [CC*HIDN];
__device__ bft g_rw1b [CU*CC];
__device__ bft g_rw1tb[CC*CU];
__device__ bft g_rw2b [CC*CU];
__device__ bft g_rw2tb[CU*CC];

__device__ bft    g_h1 [(size_t)BN*HIDN*HWN];
__device__ bft    g_dg [(size_t)BN*HIDN*HWN];
__device__ bft    g_y  [(size_t)BN*CC*HWN];
__device__ bft    g_dy [(size_t)BN*CC*HWN];
__device__ bft    g_xb [(size_t)BN*CC*HWN];
__device__ __half g_xh [(size_t)BN*CC*HWN];

__device__ float g_mu[BN*NGRP];
__device__ float g_rstd[BN*NGRP];
__device__ float2 g_gnp[BN*NGRP*49];
__device__ float2 g_rowp[(size_t)BN*HIDN*49];
__device__ float g_part[BN*HIDN*2];
__device__ float g_s1[BN*NGRP], g_s2[BN*NGRP];
__device__ float g_dgamma[HIDN], g_dbeta[HIDN];
__device__ float g_cm[CC], g_cA[CC], g_cB[CC];
__device__ bft g_split1[(size_t)SPLITK*HIDN*CC];
__device__ bft g_split2[(size_t)SPLITK*HIDN*CC];
__device__ float g_maskf[2*NTOT];
__device__ float2 g_mpart[98];
__device__ float g_dscale[2];
__device__ float g_pooled[BN*CC];
__device__ float g_gate[BN];
__device__ int   g_flagF, g_flagW;

// ---------------- math helpers ----------------
__device__ __forceinline__ float geluf(float x){
    return 0.5f*x*(1.0f + erff(x*0.70710678118654752440f));
}
__device__ __forceinline__ float gelu_grad(float x){
    float cdf = 0.5f*(1.0f + erff(x*0.70710678118654752440f));
    float pdf = 0.3989422804014327f*__expf(-0.5f*x*x);
    return cdf + x*pdf;
}
__device__ __forceinline__ void block_reduce2(float& a, float& b){
    __shared__ float sa[256], sb[256];
    int t = threadIdx.x;
    sa[t]=a; sb[t]=b; __syncthreads();
    for (int s=128; s>0; s>>=1){
        if (t<s){ sa[t]+=sa[t+s]; sb[t]+=sb[t+s]; }
        __syncthreads();
    }
    a=sa[0]; b=sb[0];
}
__device__ __forceinline__ unsigned pack_bf2(float a, float b){
    __nv_bfloat162 p = __floats2bfloat162_rn(a, b);
    return *(unsigned*)&p;
}
__device__ __forceinline__ unsigned pack_h2(float a, float b){
    __half2 p = __floats2half2_rn(a, b);
    return *(unsigned*)&p;
}
__device__ __forceinline__ float2 h2f2(unsigned u){
    __half2 h = *(__half2*)&u;
    return __half22float2(h);
}
__device__ __forceinline__ unsigned smem_u32(const void* p){
    return (unsigned)__cvta_generic_to_shared(p);
}
__device__ __forceinline__ void unpack8(uint4 u, float* v){
    __nv_bfloat162 p;
    p=*(__nv_bfloat162*)&u.x; v[0]=__low2float(p); v[1]=__high2float(p);
    p=*(__nv_bfloat162*)&u.y; v[2]=__low2float(p); v[3]=__high2float(p);
    p=*(__nv_bfloat162*)&u.z; v[4]=__low2float(p); v[5]=__high2float(p);
    p=*(__nv_bfloat162*)&u.w; v[6]=__low2float(p); v[7]=__high2float(p);
}
__device__ __forceinline__ uint4 pack8(const float* v){
    uint4 u;
    u.x=pack_bf2(v[0],v[1]); u.y=pack_bf2(v[2],v[3]);
    u.z=pack_bf2(v[4],v[5]); u.w=pack_bf2(v[6],v[7]);
    return u;
}
__device__ __forceinline__ uint4 pack8h(const float* v){
    uint4 u;
    u.x=pack_h2(v[0],v[1]); u.y=pack_h2(v[2],v[3]);
    u.z=pack_h2(v[4],v[5]); u.w=pack_h2(v[6],v[7]);
    return u;
}
__device__ __forceinline__ float2 ldbf2(const bft* p){
    __nv_bfloat162 v = *(const __nv_bfloat162*)p;
    return make_float2(__low2float(v), __high2float(v));
}

#define LDMX4(A, addr) \
    asm volatile("ldmatrix.sync.aligned.m8n8.x4.shared.b16 {%0,%1,%2,%3}, [%4];" \
        : "=r"((A)[0]),"=r"((A)[1]),"=r"((A)[2]),"=r"((A)[3]) : "r"(addr))
#define LDMX4T(A, addr) \
    asm volatile("ldmatrix.sync.aligned.m8n8.x4.trans.shared.b16 {%0,%1,%2,%3}, [%4];" \
        : "=r"((A)[0]),"=r"((A)[1]),"=r"((A)[2]),"=r"((A)[3]) : "r"(addr))
#define MMA16816(d, A, b0, b1) \
    asm volatile("mma.sync.aligned.m16n8k16.row.col.f32.bf16.bf16.f32 " \
        "{%0,%1,%2,%3},{%4,%5,%6,%7},{%8,%9},{%0,%1,%2,%3};" \
        : "+f"((d)[0]),"+f"((d)[1]),"+f"((d)[2]),"+f"((d)[3]) \
        : "r"((A)[0]),"r"((A)[1]),"r"((A)[2]),"r"((A)[3]), "r"(b0),"r"(b1))
#define MMAF16(d, A, b0, b1) \
    asm volatile("mma.sync.aligned.m16n8k16.row.col.f16.f16.f16.f16 " \
        "{%0,%1},{%2,%3,%4,%5},{%6,%7},{%0,%1};" \
        : "+r"((d)[0]),"+r"((d)[1]) \
        : "r"((A)[0]),"r"((A)[1]),"r"((A)[2]),"r"((A)[3]), "r"(b0),"r"(b1))

// ---------------- init / mask handling ----------------
__global__ void reset_copy(const float* __restrict__ w1, const float* __restrict__ gam,
                           const float* __restrict__ bet, const float* __restrict__ w2,
                           const float* __restrict__ rw1, const float* __restrict__ rw2){
    int i = blockIdx.x*blockDim.x + threadIdx.x;
    if (i==0){ g_flagF=0; g_flagW=0; }
    if (i < HIDN*CC){ float v=w1[i]; g_w1[i]=v; g_w1h[i]=__float2half(v); }
    if (i < CC*HIDN){
        float v=w2[i]; g_w2[i]=v;
        g_w2h[i]=__float2half(v);
        int c=i/HIDN, o=i%HIDN;
        g_w2tb[o*CC+c]=__float2bfloat16(v);
    }
    if (i < CU*CC){
        bft bv=__float2bfloat16(rw1[i]);
        g_rw1b[i]=bv;
        int u=i/CC, c=i%CC;
        g_rw1tb[c*CU+u]=bv;
    }
    if (i < CC*CU){
        bft bv=__float2bfloat16(rw2[i]);
        g_rw2b[i]=bv;
        int c=i/CU, u=i%CU;
        g_rw2tb[u*CC+c]=bv;
    }
    if (i < HIDN){ g_gamma[i]=gam[i]; g_beta[i]=bet[i]; }
}

__global__ void mask_detect(const unsigned int* __restrict__ mw){
    int f=0, wd=0;
    for (int i = blockIdx.x*blockDim.x + threadIdx.x; i < 25088; i += gridDim.x*blockDim.x){
        unsigned v = mw[i];
        if (v == 0x3F800000u) f = 1;
        else if (v != 0u && v != 1u) wd = 1;
    }
    if (f)  atomicOr(&g_flagF, 1);
    if (wd) atomicOr(&g_flagW, 1);
}

__global__ void mask_convert(const void* __restrict__ mp){
    int mode = g_flagW ? 2 : (g_flagF ? 1 : 0);
    int n = 2*NTOT;
    float c0 = 0.f, c1 = 0.f;
    for (int i = blockIdx.x*blockDim.x + threadIdx.x; i < n; i += gridDim.x*blockDim.x){
        bool v;
        if (mode==0)      v = ((const int*)mp)[i] != 0;
        else if (mode==1) v = ((const float*)mp)[i] != 0.0f;
        else              v = ((const unsigned char*)mp)[i] != 0;
        g_maskf[i] = v ? 1.0f : 0.0f;
        if (!v){ if (i < NTOT) c0 += 1.0f; else c1 += 1.0f; }
    }
    __shared__ float sa[32], sb[32];
    int lane = threadIdx.x & 31, w = threadIdx.x >> 5;
    #pragma unroll
    for (int off=16; off; off>>=1){
        c0 += __shfl_xor_sync(0xffffffffu, c0, off);
        c1 += __shfl_xor_sync(0xffffffffu, c1, off);
    }
    if (lane==0){ sa[w]=c0; sb[w]=c1; }
    __syncthreads();
    if (threadIdx.x==0){
        float a=0.f, b=0.f;
        for (int j=0;j<32;j++){ a+=sa[j]; b+=sb[j]; }
        g_mpart[blockIdx.x] = make_float2(a, b);
    }
}

__global__ void inv_scale_kernel(){
    int t = threadIdx.x;  // 128
    float a = 0.f, b = 0.f;
    if (t < 98){ float2 v = g_mpart[t]; a=v.x; b=v.y; }
    __shared__ float sa[128], sb[128];
    sa[t]=a; sb[t]=b; __syncthreads();
    for (int s=64; s>0; s>>=1){
        if (t<s){ sa[t]+=sa[t+s]; sb[t]+=sb[t+s]; }
        __syncthreads();
    }
    if (t==0){
        g_dscale[0] = 2.0f/(sa[0]*256.0f + 1e-8f);
        g_dscale[1] = 2.0f/(sb[0]*256.0f + 1e-8f);
    }
}

// fused: x -> bf16 + fp16 copies + channel mean (pooled)
__global__ void convert_pool(const float* __restrict__ x, bft* __restrict__ xb,
                             __half* __restrict__ xh){
    int c = blockIdx.x, b = blockIdx.y;
    size_t base = ((size_t)b*CC + c)*HWN;
    float s = 0.f, d = 0.f;
    for (int i = threadIdx.x; i < HWN/8; i += 256){
        size_t off = base + (size_t)i*8;
        float4 a0 = *(const float4*)(x+off);
        float4 a1 = *(const float4*)(x+off+4);
        float v[8] = {a0.x,a0.y,a0.z,a0.w,a1.x,a1.y,a1.z,a1.w};
        *(uint4*)(xb+off) = pack8(v);
        *(uint4*)(xh+off) = pack8h(v);
        #pragma unroll
        for (int j=0;j<8;j++) s += v[j];
    }
    block_reduce2(s, d);
    if (threadIdx.x==0) g_pooled[b*CC+c] = s/(float)HWN;
}

// ============================================================================
// surprise_fused (unchanged from R15/16)
// ============================================================================
#define SF_YS   0
#define SF_DS   36864
#define SF_WB1  73728
#define SF_WB2  107520
#define SF_PG   144384
#define SF_GP   153600
#define SF_DPS  162816
#define SF_SMEM 172032

__global__ __launch_bounds__(256) void surprise_fused(
    const bft* __restrict__ Y, bft* __restrict__ DY,
    const float* __restrict__ mask, const float* __restrict__ scal)
{
    extern __shared__ char dsm[];
    bft* ys  = (bft*)(dsm + SF_YS);
    bft* ds  = (bft*)(dsm + SF_DS);
    bft* wb1 = (bft*)(dsm + SF_WB1);
    bft* wb2 = (bft*)(dsm + SF_WB2);
    bft* pg  = (bft*)(dsm + SF_PG);
    bft* gp  = (bft*)(dsm + SF_GP);
    bft* dps = (bft*)(dsm + SF_DPS);
    int b = blockIdx.z;
    int p0 = blockIdx.x*64;
    int tid=threadIdx.x, lane=tid&31, warp=tid>>5;
    const bft* Yb = Y + (size_t)b*CC*HWN;
    const float* mr = mask + (size_t)b*HWN + p0;

    #pragma unroll
    for (int j=0;j<8;j++){
        int idx = tid + j*256;
        { int row=idx>>3, col=(idx&7)*8;
          *(uint4*)&ys[row*72+col] = *(const uint4*)(Yb + (size_t)row*HWN + p0 + col); }
        { int row=idx>>5, col=(idx&31)*8;
          *(uint4*)&wb1[row*264+col] = *(const uint4*)(g_rw1b + row*256 + col); }
        { int row=idx>>3, col=(idx&7)*8;
          *(uint4*)&wb2[row*72+col] = *(const uint4*)(g_rw2b + row*64 + col); }
    }
    __syncthreads();

    {   // Stage A
        int wm = warp>>2, wp = warp&3;
        float acc[2][2][4] = {};
        for (int kb=0; kb<256; kb+=16){
            unsigned A[2][4];
            #pragma unroll
            for (int i=0;i<2;i++)
                LDMX4(A[i], smem_u32(&wb1[(wm*32+i*16+(lane&15))*264 + kb + (lane>>4)*8]));
            unsigned Bv[4];
            LDMX4T(Bv, smem_u32(&ys[(kb + (lane&7) + 8*((lane>>3)&1))*72 + wp*16 + 8*(lane>>4)]));
            #pragma unroll
            for (int i=0;i<2;i++)
                #pragma unroll
                for (int j=0;j<2;j++) MMA16816(acc[i][j], A[i], Bv[j*2], Bv[j*2+1]);
        }
        #pragma unroll
        for (int i=0;i<2;i++)
            #pragma unroll
            for (int j=0;j<2;j++)
                #pragma unroll
                for (int rr=0;rr<2;rr++){
                    int m = wm*32+i*16+rr*8+(lane>>2);
                    int c = wp*16 + j*8 + (lane&3)*2;
                    float v0 = acc[i][j][rr*2]  *mr[c];
                    float v1 = acc[i][j][rr*2+1]*mr[c+1];
                    *(unsigned*)&pg[m*72+c] = pack_bf2(geluf(v0), geluf(v1));
                    *(unsigned*)&gp[m*72+c] = pack_bf2(gelu_grad(v0), gelu_grad(v1));
                }
    }
    __syncthreads();

    #pragma unroll
    for (int j=0;j<8;j++){
        int idx = tid + j*256;
        int row=idx>>5, col=(idx&31)*8;
        *(uint4*)&wb1[row*264+col] = *(const uint4*)(g_rw2tb + row*256 + col);
    }

    {   // Stage B
        float acc[2][4][2][4] = {};
        for (int kb=0; kb<64; kb+=16){
            unsigned A[2][4];
            #pragma unroll
            for (int i=0;i<2;i++)
                LDMX4(A[i], smem_u32(&wb2[(warp*32+i*16+(lane&15))*72 + kb + (lane>>4)*8]));
            #pragma unroll
            for (int jj=0;jj<4;jj++){
                unsigned Bv[4];
                LDMX4T(Bv, smem_u32(&pg[(kb + (lane&7) + 8*((lane>>3)&1))*72 + jj*16 + 8*(lane>>4)]));
                #pragma unroll
                for (int i=0;i<2;i++)
                    #pragma unroll
                    for (int j=0;j<2;j++) MMA16816(acc[i][jj][j], A[i], Bv[j*2], Bv[j*2+1]);
            }
        }
        float sc = scal[0];
        #pragma unroll
        for (int i=0;i<2;i++)
            #pragma unroll
            for (int jj=0;jj<4;jj++)
                #pragma unroll
                for (int j=0;j<2;j++)
                    #pragma unroll
                    for (int rr=0;rr<2;rr++){
                        int m = warp*32+i*16+rr*8+(lane>>2);
                        int c = jj*16 + j*8 + (lane&3)*2;
                        float2 yv = ldbf2(&ys[m*72+c]);
                        float v0 = (acc[i][jj][j][rr*2]  -yv.x)*(1.0f-mr[c])  *sc;
                        float v1 = (acc[i][jj][j][rr*2+1]-yv.y)*(1.0f-mr[c+1])*sc;
                        *(unsigned*)&ds[m*72+c] = pack_bf2(v0, v1);
                    }
    }
    __syncthreads();

    #pragma unroll
    for (int j=0;j<8;j++){
        int idx = tid + j*256;
        int row=idx>>3, col=(idx&7)*8;
        *(uint4*)&wb2[row*72+col] = *(const uint4*)(g_rw1tb + row*64 + col);
    }

    {   // Stage C
        int wm = warp>>2, wp = warp&3;
        float acc[2][2][4] = {};
        for (int kb=0; kb<256; kb+=16){
            unsigned A[2][4];
            #pragma unroll
            for (int i=0;i<2;i++)
                LDMX4(A[i], smem_u32(&wb1[(wm*32+i*16+(lane&15))*264 + kb + (lane>>4)*8]));
            unsigned Bv[4];
            LDMX4T(Bv, smem_u32(&ds[(kb + (lane&7) + 8*((lane>>3)&1))*72 + wp*16 + 8*(lane>>4)]));
            #pragma unroll
            for (int i=0;i<2;i++)
                #pragma unroll
                for (int j=0;j<2;j++) MMA16816(acc[i][j], A[i], Bv[j*2], Bv[j*2+1]);
        }
        #pragma unroll
        for (int i=0;i<2;i++)
            #pragma unroll
            for (int j=0;j<2;j++)
                #pragma unroll
                for (int rr=0;rr<2;rr++){
                    int m = wm*32+i*16+rr*8+(lane>>2);
                    int c = wp*16 + j*8 + (lane&3)*2;
                    float2 gv = ldbf2(&gp[m*72+c]);
                    *(unsigned*)&dps[m*72+c] =
                        pack_bf2(acc[i][j][rr*2]*gv.x, acc[i][j][rr*2+1]*gv.y);
                }
    }
    __syncthreads();

    {   // Stage D
        float acc[2][4][2][4] = {};
        for (int kb=0; kb<64; kb+=16){
            unsigned A[2][4];
            #pragma unroll
            for (int i=0;i<2;i++)
                LDMX4(A[i], smem_u32(&wb2[(warp*32+i*16+(lane&15))*72 + kb + (lane>>4)*8]));
            #pragma unroll
            for (int jj=0;jj<4;jj++){
                unsigned Bv[4];
                LDMX4T(Bv, smem_u32(&dps[(kb + (lane&7) + 8*((lane>>3)&1))*72 + jj*16 + 8*(lane>>4)]));
                #pragma unroll
                for (int i=0;i<2;i++)
                    #pragma unroll
                    for (int j=0;j<2;j++) MMA16816(acc[i][jj][j], A[i], Bv[j*2], Bv[j*2+1]);
            }
        }
        #pragma unroll
        for (int i=0;i<2;i++)
            #pragma unroll
            for (int jj=0;jj<4;jj++)
                #pragma unroll
                for (int j=0;j<2;j++)
                    #pragma unroll
                    for (int rr=0;rr<2;rr++){
                        int m = warp*32+i*16+rr*8+(lane>>2);
                        int c = jj*16 + j*8 + (lane&3)*2;
                        float2 dsv = ldbf2(&ds[m*72+c]);
                        float2 yv  = ldbf2(&ys[m*72+c]);
                        float cA=g_cA[m], cBv=g_cB[m], cmv=g_cm[m];
                        float v0 = acc[i][jj][j][rr*2]  *mr[c]   - dsv.x + cA + cBv*(yv.x-cmv);
                        float v1 = acc[i][jj][j][rr*2+1]*mr[c+1] - dsv.y + cA + cBv*(yv.y-cmv);
                        *(unsigned*)(DY + ((size_t)b*CC + m)*HWN + p0 + c) = pack_bf2(v0, v1);
                    }
    }
}

// ============================================================================
// gemm512h: fp16 in / fp16 accum, M=512, K=256, 2-stage cp.async, occ 2.
// ============================================================================
#define WSTG (512*40*2)
#define XSTG (32*72*2)
#define SMEM512H (2*WSTG + 2*XSTG)
__global__ __launch_bounds__(256,2) void gemm512h(
    const __half* __restrict__ W, const __half* __restrict__ X, bft* __restrict__ out)
{
    extern __shared__ char dsm[];
    const unsigned WsU = smem_u32(dsm);
    const unsigned XsU = WsU + 2*WSTG;
    int b  = blockIdx.z;
    int p0 = blockIdx.x*64;
    const __half* Xb = X + (size_t)b*256*HWN;
    int tid  = threadIdx.x;
    int lane = tid & 31, wm = tid >> 5;
    unsigned acc[4][4][2][2] = {};

    auto issue = [&](int it){
        int k0 = it*32;
        unsigned wb = WsU + (unsigned)((it&1)*WSTG);
        #pragma unroll
        for (int j=0;j<8;j++){
            int chunk = tid + j*256;
            int row = chunk>>2, q = chunk&3;
            unsigned dst = wb + (unsigned)((row*40 + q*8)*2);
            const __half* src = W + (size_t)row*256 + k0 + q*8;
            asm volatile("cp.async.cg.shared.global [%0], [%1], 16;" :: "r"(dst), "l"(src));
        }
        {
            int row = tid>>3, c = (tid&7)*8;
            unsigned dst = XsU + (unsigned)(((it&1)*32*72 + row*72 + c)*2);
            const __half* src = Xb + (size_t)(k0+row)*HWN + p0 + c;
            asm volatile("cp.async.cg.shared.global [%0], [%1], 16;" :: "r"(dst), "l"(src));
        }
        asm volatile("cp.async.commit_group;");
    };

    issue(0);
    #pragma unroll 1
    for (int it = 0; it < 8; it++){
        if (it + 1 < 8){
            issue(it+1);
            asm volatile("cp.async.wait_group 1;");
        } else {
            asm volatile("cp.async.wait_group 0;");
        }
        __syncthreads();
        unsigned wb  = WsU + (unsigned)((it&1)*WSTG);
        unsigned xb2 = XsU + (unsigned)((it&1)*32*72*2);
        #pragma unroll
        for (int h=0; h<2; h++){
            int kb = h*16;
            unsigned A[4][4];
            #pragma unroll
            for (int ii=0;ii<4;ii++)
                LDMX4(A[ii], wb + (unsigned)((((wm*64 + ii*16 + (lane&15))*40) + kb + (lane>>4)*8)*2));
            #pragma unroll
            for (int jj=0; jj<4; jj++){
                unsigned Bv[4];
                LDMX4T(Bv, xb2 + (unsigned)((((kb + (lane&7) + 8*((lane>>3)&1))*72) + jj*16 + 8*(lane>>4))*2));
                #pragma unroll
                for (int ii=0;ii<4;ii++)
                    #pragma unroll
                    for (int j=0;j<2;j++) MMAF16(acc[ii][jj][j], A[ii], Bv[j*2], Bv[j*2+1]);
            }
        }
        __syncthreads();
    }

    float s=0.f, sq=0.f;
    #pragma unroll
    for (int ii=0;ii<4;ii++)
        #pragma unroll
        for (int rr=0;rr<2;rr++){
            int m = wm*64 + ii*16 + rr*8 + (lane>>2);
            #pragma unroll
            for (int jj=0;jj<4;jj++)
                #pragma unroll
                for (int j=0;j<2;j++){
                    int c = p0 + jj*16 + j*8 + (lane&3)*2;
                    float2 vv = h2f2(acc[ii][jj][j][rr]);
                    s += vv.x+vv.y; sq += vv.x*vv.x + vv.y*vv.y;
                    *(unsigned*)(out + ((size_t)b*512 + m)*HWN + c) = pack_bf2(vv.x, vv.y);
                }
        }
    __shared__ float2 sgn[8];
    #pragma unroll
    for (int off=16; off; off>>=1){
        s  += __shfl_xor_sync(0xffffffffu, s, off);
        sq += __shfl_xor_sync(0xffffffffu, sq, off);
    }
    if (lane==0) sgn[wm] = make_float2(s, sq);
    __syncthreads();
    if (tid < 8){
        float2 v = sgn[tid];
        g_gnp[((size_t)b*NGRP + tid)*49 + blockIdx.x] = v;
    }
}

// ============================================================================
// gemm512b: bf16/f32 path, 3-stage, dgn epilogue.
// ============================================================================
__global__ __launch_bounds__(256) void gemm512b(
    const bft* __restrict__ W, const bft* __restrict__ X, bft* __restrict__ out,
    const bft* __restrict__ aux)
{
    extern __shared__ char dsm[];
    const unsigned WsU = smem_u32(dsm);
    const unsigned XsU = WsU + 3*WSTG;
    int b  = blockIdx.z;
    int p0 = blockIdx.x*64;
    const bft* Xb = X + (size_t)b*256*HWN;
    int tid  = threadIdx.x;
    int lane = tid & 31, wm = tid >> 5;
    float acc[4][4][2][4] = {};

    auto issue = [&](int it){
        int k0 = it*32;
        int st = it % 3;
        unsigned wb = WsU + (unsigned)(st*WSTG);
        #pragma unroll
        for (int j=0;j<8;j++){
            int chunk = tid + j*256;
            int row = chunk>>2, q = chunk&3;
            unsigned dst = wb + (unsigned)((row*40 + q*8)*2);
            const bft* src = W + (size_t)row*256 + k0 + q*8;
            asm volatile("cp.async.cg.shared.global [%0], [%1], 16;" :: "r"(dst), "l"(src));
        }
        {
            int row = tid>>3, c = (tid&7)*8;
            unsigned dst = XsU + (unsigned)((st*32*72 + row*72 + c)*2);
            const bft* src = Xb + (size_t)(k0+row)*HWN + p0 + c;
            asm volatile("cp.async.cg.shared.global [%0], [%1], 16;" :: "r"(dst), "l"(src));
        }
        asm volatile("cp.async.commit_group;");
    };

    issue(0);
    issue(1);
    #pragma unroll 1
    for (int it = 0; it < 8; it++){
        if (it + 2 < 8){
            issue(it+2);
            asm volatile("cp.async.wait_group 2;");
        } else if (it + 1 < 8){
            asm volatile("cp.async.wait_group 1;");
        } else {
            asm volatile("cp.async.wait_group 0;");
        }
        __syncthreads();
        int st = it % 3;
        unsigned wb  = WsU + (unsigned)(st*WSTG);
        unsigned xb2 = XsU + (unsigned)(st*32*72*2);
        #pragma unroll
        for (int h=0; h<2; h++){
            int kb = h*16;
            unsigned A[4][4];
            #pragma unroll
            for (int ii=0;ii<4;ii++)
                LDMX4(A[ii], wb + (unsigned)((((wm*64 + ii*16 + (lane&15))*40) + kb + (lane>>4)*8)*2));
            #pragma unroll
            for (int jj=0; jj<4; jj++){
                unsigned Bv[4];
                LDMX4T(Bv, xb2 + (unsigned)((((kb + (lane&7) + 8*((lane>>3)&1))*72) + jj*16 + 8*(lane>>4))*2));
                #pragma unroll
                for (int ii=0;ii<4;ii++)
                    #pragma unroll
                    for (int j=0;j<2;j++) MMA16816(acc[ii][jj][j], A[ii], Bv[j*2], Bv[j*2+1]);
            }
        }
        __syncthreads();
    }

    int bg=b*NGRP+wm;
    float bg_mu=g_mu[bg], bg_rs=g_rstd[bg];

    float st_s[4][2], st_t[4][2];
    #pragma unroll
    for (int i=0;i<4;i++){ st_s[i][0]=st_s[i][1]=0.f; st_t[i][0]=st_t[i][1]=0.f; }

    #pragma unroll
    for (int ii=0;ii<4;ii++){
        #pragma unroll
        for (int rr=0;rr<2;rr++){
            int m = wm*64 + ii*16 + rr*8 + (lane>>2);
            float ga=g_gamma[m], be=g_beta[m];
            #pragma unroll
            for (int jj=0;jj<4;jj++){
                #pragma unroll
                for (int j=0;j<2;j++){
                    int c = p0 + jj*16 + j*8 + (lane&3)*2;
                    size_t idx = ((size_t)b*512 + m)*HWN + c;
                    float v0 = acc[ii][jj][j][rr*2+0], v1 = acc[ii][jj][j][rr*2+1];
                    float2 hv = ldbf2(aux+idx);
                    float hat0=(hv.x-bg_mu)*bg_rs, hat1=(hv.y-bg_mu)*bg_rs;
                    v0 *= gelu_grad(hat0*ga+be);
                    v1 *= gelu_grad(hat1*ga+be);
                    st_s[ii][rr] += v0+v1;
                    st_t[ii][rr] += v0*hat0 + v1*hat1;
                    *(unsigned*)(out+idx) = pack_bf2(v0, v1);
                }
            }
        }
    }

    #pragma unroll
    for (int ii=0;ii<4;ii++)
        #pragma unroll
        for (int rr=0;rr<2;rr++){
            float s=st_s[ii][rr], t=st_t[ii][rr];
            s += __shfl_xor_sync(0xffffffffu, s, 1); t += __shfl_xor_sync(0xffffffffu, t, 1);
            s += __shfl_xor_sync(0xffffffffu, s, 2); t += __shfl_xor_sync(0xffffffffu, t, 2);
            if ((lane&3)==0){
                int m = wm*64 + ii*16 + rr*8 + (lane>>2);
                g_rowp[((size_t)b*512 + m)*49 + blockIdx.x] = make_float2(s, t);
            }
        }
}

// ============================================================================
// gemm_f16: fp16 W (cp.async 2-stage) / fp16 accum, M=256, K=512,
// X = gelu(GN(h1)) via registers. EPI 1: +aux(xb) -> y(bf16). EPI 5: final out.
// ============================================================================
#define FWSTG (256*40*2)
#define SMEMF16 (2*FWSTG)
template<int EPI, int STAT>
__global__ __launch_bounds__(256,2) void gemm_f16(
    const __half* __restrict__ W, const bft* __restrict__ X, void* __restrict__ out_,
    const float* __restrict__ xf, const bft* __restrict__ aux,
    const float* __restrict__ scal)
{
    extern __shared__ char dsm[];
    const unsigned WsU = smem_u32(dsm);                 // [2][256][40] half
    __shared__ __half Xs[32][72];
    __shared__ float2 srow[256][2];
    int b  = blockIdx.z;
    int p0 = blockIdx.x*64;
    const bft* Xb = X + (size_t)b*512*HWN;
    int tid  = threadIdx.x;
    int lane = tid & 31, warp = tid >> 5;
    int wm = warp >> 1, wp = warp & 1;
    unsigned acc[4][2][2][2] = {};

    int xk = tid>>3, xc = (tid&7)*8;
    uint4 xreg;

    auto issue_w = [&](int it){
        int k0 = it*32;
        unsigned wb = WsU + (unsigned)((it&1)*FWSTG);
        #pragma unroll
        for (int j=0;j<4;j++){
            int chunk = tid + j*256;
            int row = chunk>>2, q = chunk&3;
            unsigned dst = wb + (unsigned)((row*40 + q*8)*2);
            const __half* src = W + (size_t)row*512 + k0 + q*8;
            asm volatile("cp.async.cg.shared.global [%0], [%1], 16;" :: "r"(dst), "l"(src));
        }
        asm volatile("cp.async.commit_group;");
    };
    auto load_x = [&](int k0){
        xreg = *(const uint4*)(Xb + (size_t)(k0+xk)*HWN + p0 + xc);
    };
    auto store_x = [&](int k0){
        float vv[8]; unpack8(xreg, vv);
        int o = k0 + xk;
        int bg = b*NGRP + o/CGg;
        float mu=g_mu[bg], rs=g_rstd[bg], ga=g_gamma[o], be=g_beta[o];
        #pragma unroll
        for (int j=0;j<8;j++) vv[j] = geluf((vv[j]-mu)*rs*ga + be);
        *(uint4*)&Xs[xk][xc] = pack8h(vv);
    };

    issue_w(0);
    load_x(0);
    #pragma unroll 1
    for (int i = 0; i < 16; i++){
        store_x(i*32);
        if (i+1 < 16){
            issue_w(i+1);
            asm volatile("cp.async.wait_group 1;");
        } else {
            asm volatile("cp.async.wait_group 0;");
        }
        __syncthreads();
        if (i+1 < 16) load_x((i+1)*32);
        unsigned wb = WsU + (unsigned)((i&1)*FWSTG);

        #pragma unroll
        for (int h=0; h<2; h++){
            int kb = h*16;
            unsigned A[4][4];
            #pragma unroll
            for (int ii=0;ii<4;ii++)
                LDMX4(A[ii], wb + (unsigned)((((wm*64 + ii*16 + (lane&15))*40) + kb + (lane>>4)*8)*2));
            #pragma unroll
            for (int jj=0; jj<2; jj++){
                unsigned Bv[4];
                LDMX4T(Bv, smem_u32(&Xs[kb + (lane&7) + 8*((lane>>3)&1)][wp*32 + jj*16 + 8*(lane>>4)]));
                #pragma unroll
                for (int ii=0;ii<4;ii++)
                    #pragma unroll
                    for (int j=0;j<2;j++) MMAF16(acc[ii][jj][j], A[ii], Bv[j*2], Bv[j*2+1]);
            }
        }
        __syncthreads();
    }

    float st_s[4][2], st_t[4][2];
    #pragma unroll
    for (int i=0;i<4;i++){ st_s[i][0]=st_s[i][1]=0.f; st_t[i][0]=st_t[i][1]=0.f; }

    #pragma unroll
    for (int i=0;i<4;i++){
        #pragma unroll
        for (int rr=0;rr<2;rr++){
            int m = wm*64 + i*16 + rr*8 + (lane>>2);
            #pragma unroll
            for (int jj=0;jj<2;jj++){
                #pragma unroll
                for (int j=0;j<2;j++){
                    int c = p0 + wp*32 + jj*16 + j*8 + (lane&3)*2;
                    size_t idx = ((size_t)b*256 + m)*HWN + c;
                    float2 vv = h2f2(acc[i][jj][j][rr]);
                    float v0 = vv.x, v1 = vv.y;
                    if (EPI==1){
                        float2 a = ldbf2(aux+idx);
                        v0 += a.x; v1 += a.y;
                    } else {
                        float sc = scal[0]*g_gate[b];
                        float2 x2 = *(const float2*)(xf+idx);
                        v0 = x2.x + sc*v0; v1 = x2.y + sc*v1;
                    }
                    if (STAT==3){
                        st_s[i][rr] += v0+v1;
                        st_t[i][rr] += v0*v0 + v1*v1;
                    }
                    if (EPI==5)
                        *(float2*)((float*)out_+idx) = make_float2(v0, v1);
                    else
                        *(unsigned*)((bft*)out_+idx) = pack_bf2(v0, v1);
                }
            }
        }
    }

    if (STAT==3){
        #pragma unroll
        for (int i=0;i<4;i++)
            #pragma unroll
            for (int rr=0;rr<2;rr++){
                float s=st_s[i][rr], t=st_t[i][rr];
                s += __shfl_xor_sync(0xffffffffu, s, 1); t += __shfl_xor_sync(0xffffffffu, t, 1);
                s += __shfl_xor_sync(0xffffffffu, s, 2); t += __shfl_xor_sync(0xffffffffu, t, 2);
                if ((lane&3)==0) srow[wm*64 + i*16 + rr*8 + (lane>>2)][wp] = make_float2(s, t);
            }
        __syncthreads();
        if (tid < 256){
            float2 a = srow[tid][0], b2 = srow[tid][1];
            g_rowp[((size_t)b*256 + tid)*49 + blockIdx.x] = make_float2(a.x+b2.x, a.y+b2.y);
        }
    }
}

__global__ void gn_reduce(){
    int bg = threadIdx.x;  // 128
    float s=0.f, sq=0.f;
    for (int i=0;i<49;i++){
        float2 v = g_gnp[(size_t)bg*49 + i];
        s += v.x; sq += v.y;
    }
    float n = (float)(CGg*HWN);
    float mean = s/n;
    float var  = sq/n - mean*mean;
    g_mu[bg] = mean;
    g_rstd[bg] = rsqrtf(var + 1e-5f);
}

__global__ void dgn_rowreduce(){
    int idx = blockIdx.x*blockDim.x + threadIdx.x;
    float s=0.f, t=0.f;
    for (int x=0; x<49; x++){
        float2 v = g_rowp[(size_t)idx*49 + x];
        s += v.x; t += v.y;
    }
    g_part[idx*2+0] = s;
    g_part[idx*2+1] = t;
}

__global__ void chan_reduce(const float* __restrict__ rm, const float* __restrict__ rv){
    int c = blockIdx.x;
    float s=0.f, sq=0.f;
    for (int i=threadIdx.x; i<BN*49; i+=256){
        int b=i/49, x=i%49;
        float2 v = g_rowp[((size_t)b*CC + c)*49 + x];
        s += v.x; sq += v.y;
    }
    block_reduce2(s, sq);
    if (threadIdx.x==0){
        float n = (float)NTOT;
        float cm = s/n;
        float cv = (sq - n*cm*cm)/(n - 1.0f);
        float rve = rv[c] + 1e-8f;
        g_cm[c] = cm;
        g_cA[c] = 0.1f*2.0f*(cm - rm[c])/(256.0f*n);
        g_cB[c] = 0.1f*4.0f*(cv/rve - 1.0f)/(rve*256.0f*(n - 1.0f));
    }
}

// ============================================================================
// NT GEMM 128x128 (bf16/f32, unchanged)
// ============================================================================
template<int XOPB, int XOPA>
__global__ __launch_bounds__(256,2) void gemm_nt_bf16(
    const bft* __restrict__ A, const bft* __restrict__ Bm, const bft* __restrict__ Hm,
    bft* __restrict__ part, int Ma, int Nb)
{
    __shared__ bft As[2][128][40];
    __shared__ bft Bs[2][128][40];
    int z  = blockIdx.z;
    int m0 = blockIdx.y*128, n0 = blockIdx.x*128;
    int tid  = threadIdx.x;
    int lane = tid & 31, warp = tid >> 5;
    int wm = warp >> 1, wp = warp & 1;
    float acc[2][8][4] = {};

    int r  = tid >> 1, c0 = (tid & 1)*16;

    #define POFF(it) ((((it)%PBZ)*SPLITK + z)*32)
    #define AP(it) (A  + ((size_t)((it)/PBZ)*Ma + m0 + r)*HWN + POFF(it) + c0)
    #define BP(it) (Bm + ((size_t)((it)/PBZ)*Nb + n0 + r)*HWN + POFF(it) + c0)
    #define HP(it) (Hm + ((size_t)((it)/PBZ)*Ma + m0 + r)*HWN + POFF(it) + c0)

    uint4 a0, a1, b0, b1, h0, h1;
    auto load_it = [&](int it){
        a0 = *(const uint4*)AP(it); a1 = *(const uint4*)(AP(it)+8);
        b0 = *(const uint4*)BP(it); b1 = *(const uint4*)(BP(it)+8);
        if (XOPA==1){ h0 = *(const uint4*)HP(it); h1 = *(const uint4*)(HP(it)+8); }
    };
    auto store_it = [&](int buf, int it){
        if (XOPA==0){
            *(uint4*)&As[buf][r][c0]   = a0;
            *(uint4*)&As[buf][r][c0+8] = a1;
        } else {
            int b = it/PBZ;
            int o = m0 + r;
            int bg = b*NGRP + o/CGg;
            float mu=g_mu[bg], rs=g_rstd[bg], ga=g_gamma[o];
            float s1=g_s1[bg], s2=g_s2[bg];
            float av[8], hv[8];
            unpack8(a0, av); unpack8(h0, hv);
            #pragma unroll
            for (int j=0;j<8;j++){
                float hat=(hv[j]-mu)*rs;
                av[j] = rs*(av[j]*ga - s1 - hat*s2);
            }
            *(uint4*)&As[buf][r][c0] = pack8(av);
            unpack8(a1, av); unpack8(h1, hv);
            #pragma unroll
            for (int j=0;j<8;j++){
                float hat=(hv[j]-mu)*rs;
                av[j] = rs*(av[j]*ga - s1 - hat*s2);
            }
            *(uint4*)&As[buf][r][c0+8] = pack8(av);
        }
        if (XOPB==0){
            *(uint4*)&Bs[buf][r][c0]   = b0;
            *(uint4*)&Bs[buf][r][c0+8] = b1;
        } else {
            int b = it/PBZ;
            int o = n0 + r;
            int bg = b*NGRP + o/CGg;
            float mu=g_mu[bg], rs=g_rstd[bg], ga=g_gamma[o], be=g_beta[o];
            float v[8];
            unpack8(b0, v);
            #pragma unroll
            for (int j=0;j<8;j++) v[j] = geluf((v[j]-mu)*rs*ga + be);
            *(uint4*)&Bs[buf][r][c0] = pack8(v);
            unpack8(b1, v);
            #pragma unroll
            for (int j=0;j<8;j++) v[j] = geluf((v[j]-mu)*rs*ga + be);
            *(uint4*)&Bs[buf][r][c0+8] = pack8(v);
        }
    };

    load_it(0);
    store_it(0, 0);
    __syncthreads();

    const int ITERS = BN*PBZ;
    for (int it=0; it<ITERS; it++){
        int cur = it & 1;
        if (it+1 < ITERS) load_it(it+1);

        #pragma unroll
        for (int h=0; h<2; h++){
            int kb = h*16;
            unsigned Af[2][4];
            #pragma unroll
            for (int i=0;i<2;i++)
                LDMX4(Af[i], smem_u32(&As[cur][wm*32 + i*16 + (lane&15)][kb + (lane>>4)*8]));
            #pragma unroll
            for (int jj=0; jj<4; jj++){
                unsigned Bv[4];
                LDMX4(Bv, smem_u32(&Bs[cur][wp*64 + jj*16 + (lane&7) + 8*(lane>>4)][kb + 8*((lane>>3)&1)]));
                #pragma unroll
                for (int i=0;i<2;i++)
                    #pragma unroll
                    for (int j=0;j<2;j++) MMA16816(acc[i][jj*2+j], Af[i], Bv[j*2], Bv[j*2+1]);
            }
        }
        if (it+1 < ITERS) store_it(cur^1, it+1);
        __syncthreads();
    }
    #undef AP
    #undef BP
    #undef HP
    #undef POFF

    #pragma unroll
    for (int i=0;i<2;i++){
        int rbase = m0 + wm*32 + i*16 + (lane>>2);
        #pragma unroll
        for (int jc=0;jc<8;jc++){
            int n = n0 + wp*64 + (jc>>1)*16 + (jc&1)*8 + (lane&3)*2;
            #pragma unroll
            for (int rr=0; rr<2; rr++){
                int m = rbase + rr*8;
                size_t idx = ((size_t)z*Ma + m)*Nb + n;
                *(unsigned*)(part+idx) = pack_bf2(acc[i][jc][rr*2], acc[i][jc][rr*2+1]);
            }
        }
    }
}

__global__ void reduce_part(){
    int t = threadIdx.x;  // 512
    float db=0.f, dga=0.f;
    for (int b=0;b<BN;b++){
        db  += g_part[(b*HIDN+t)*2+0];
        dga += g_part[(b*HIDN+t)*2+1];
    }
    g_dbeta[t]=db; g_dgamma[t]=dga;
    if (t < BN*NGRP){
        int b=t/NGRP, g=t%NGRP;
        float s1=0.f, s2=0.f;
        for (int j=0;j<CGg;j++){
            int o=g*CGg+j;
            float ga=g_gamma[o];
            s1 += ga*g_part[(b*HIDN+o)*2+0];
            s2 += ga*g_part[(b*HIDN+o)*2+1];
        }
        float inv = 1.0f/(float)(CGg*HWN);
        g_s1[t]=s1*inv; g_s2[t]=s2*inv;
    }
}

// fused: reduce both split buffers + SGD update + refresh fp16/bf16 copies
__global__ void update_fused(){
    int i2 = blockIdx.x*blockDim.x + threadIdx.x;
    int i = i2*2;
    {   // W2
        float s0=0.f, s1=0.f;
        const bft* p = g_split1 + i;
        for (int z=0; z<SPLITK; z++){
            float2 v = ldbf2(p + (size_t)z*HIDN*CC);
            s0 += v.x; s1 += v.y;
        }
        int c = i/HIDN, o = i%HIDN;
        float v0 = g_w2[i]   - LRc*s0;
        float v1 = g_w2[i+1] - LRc*s1;
        g_w2[i]=v0; g_w2[i+1]=v1;
        g_w2h[i]=__float2half(v0); g_w2h[i+1]=__float2half(v1);
        g_w2tb[o*CC+c]=__float2bfloat16(v0); g_w2tb[(o+1)*CC+c]=__float2bfloat16(v1);
    }
    {   // W1
        float s0=0.f, s1=0.f;
        const bft* p = g_split2 + i;
        for (int z=0; z<SPLITK; z++){
            float2 v = ldbf2(p + (size_t)z*HIDN*CC);
            s0 += v.x; s1 += v.y;
        }
        float v0 = g_w1[i]   - LRc*s0;
        float v1 = g_w1[i+1] - LRc*s1;
        g_w1[i]=v0; g_w1[i+1]=v1;
        g_w1h[i]=__float2half(v0); g_w1h[i+1]=__float2half(v1);
    }
    if (i2 < HIDN){
        g_gamma[i2] -= LRc*g_dgamma[i2];
        g_beta[i2]  -= LRc*g_dbeta[i2];
    }
}

// ---------------- gate ----------------
__global__ void gate_kernel(const float* __restrict__ gw1, const float* __restrict__ gb1,
                            const float* __restrict__ gw2, const float* __restrict__ gb2){
    __shared__ float gh[BN*CU];
    int t = threadIdx.x;
    for (int j=t; j<BN*CU; j+=256){
        int b=j/CU, u=j%CU;
        float s = gb1[u];
        const float* pr = &g_pooled[b*CC];
        const float* wr = &gw1[u*CC];
        for (int c=0;c<CC;c++) s += pr[c]*wr[c];
        gh[j] = geluf(s);
    }
    __syncthreads();
    if (t < BN){
        float s = gb2[0];
        for (int u=0;u<CU;u++) s += gh[t*CU+u]*gw2[u];
        g_gate[t] = 1.0f/(1.0f + expf(-s));
    }
}

// ---------------- host orchestration ----------------
extern "C" void kernel_launch(void* const* d_in, const int* in_sizes, int n_in,
                              void* d_out, int out_size){
    const float* x        = (const float*)d_in[0];
    const float* conv1_w  = (const float*)d_in[1];
    const float* gn_gammaI= (const float*)d_in[2];
    const float* gn_betaI = (const float*)d_in[3];
    const float* conv2_w  = (const float*)d_in[4];
    const float* rw1      = (const float*)d_in[5];
    const float* rw2      = (const float*)d_in[6];
    const float* gw1      = (const float*)d_in[7];
    const float* gb1      = (const float*)d_in[8];
    const float* gw2      = (const float*)d_in[9];
    const float* gb2      = (const float*)d_in[10];
    const float* rscale   = (const float*)d_in[11];
    const float* rm       = (const float*)d_in[12];
    const float* rv       = (const float*)d_in[13];
    const void*  masks    = d_in[14];

    void* p;
    #define SYMF(sym) (cudaGetSymbolAddress(&p, sym), (float*)p)
    #define SYMB(sym) (cudaGetSymbolAddress(&p, sym), (bft*)p)
    #define SYMH(sym) (cudaGetSymbolAddress(&p, sym), (__half*)p)
    __half* pw1h  = SYMH(g_w1h);
    __half* pw2h  = SYMH(g_w2h);
    bft*   pw2tb  = SYMB(g_w2tb);
    bft*   ph1    = SYMB(g_h1);
    bft*   pdg    = SYMB(g_dg);
    bft*   py     = SYMB(g_y);
    bft*   pdy    = SYMB(g_dy);
    bft*   pxb    = SYMB(g_xb);
    __half* pxh   = SYMH(g_xh);
    bft*   psplit1= SYMB(g_split1);
    bft*   psplit2= SYMB(g_split2);
    float* pmaskf = SYMF(g_maskf);
    float* pdscale= SYMF(g_dscale);
    #undef SYMF
    #undef SYMB
    #undef SYMH

    const int SMEM512 = 3*WSTG + 3*XSTG;
    cudaFuncSetAttribute(gemm512b, cudaFuncAttributeMaxDynamicSharedMemorySize, SMEM512);
    cudaFuncSetAttribute(gemm512h, cudaFuncAttributeMaxDynamicSharedMemorySize, SMEM512H);
    cudaFuncSetAttribute(gemm_f16<1,3>, cudaFuncAttributeMaxDynamicSharedMemorySize, SMEMF16);
    cudaFuncSetAttribute(gemm_f16<5,0>, cudaFuncAttributeMaxDynamicSharedMemorySize, SMEMF16);
    cudaFuncSetAttribute(surprise_fused, cudaFuncAttributeMaxDynamicSharedMemorySize, SF_SMEM);

    // init
    reset_copy<<<512,256>>>(conv1_w, gn_gammaI, gn_betaI, conv2_w, rw1, rw2);
    mask_detect<<<32,256>>>((const unsigned int*)masks);
    convert_pool<<<dim3(CC,BN),256>>>(x, pxb, pxh);

    for (int s=0; s<2; s++){
        const float* mk = pmaskf + (size_t)s*NTOT;
        const float* sc = pdscale + s;

        // forward
        gemm512h<<<dim3(49,1,BN),256,SMEM512H>>>(pw1h, pxh, ph1);
        gn_reduce<<<1,128>>>();
        if (s==0){
            mask_convert<<<98,1024>>>(masks);
            inv_scale_kernel<<<1,128>>>();
        }
        gemm_f16<1,3><<<dim3(49,1,BN),256,SMEMF16>>>(pw2h, ph1, py, nullptr, pxb, nullptr);
        chan_reduce<<<256,256>>>(rm, rv);

        // surprise chain fully fused
        surprise_fused<<<dim3(49,1,BN),256,SF_SMEM>>>(py, pdy, mk, sc);

        // backward through modifier
        gemm512b<<<dim3(49,1,BN),256,SMEM512>>>(pw2tb, pdy, pdg, ph1);
        dgn_rowreduce<<<32,256>>>();
        reduce_part<<<1,512>>>();

        gemm_nt_bf16<3,0><<<dim3(4,2,SPLITK),256>>>(pdy, ph1, nullptr, psplit1, 256,512);
        gemm_nt_bf16<0,1><<<dim3(2,4,SPLITK),256>>>(pdg, pxb, ph1,     psplit2, 512,256);
        update_fused<<<256,256>>>();
    }

    // gate
    gate_kernel<<<1,256>>>(gw1, gb1, gw2, gb2);

    // final forward (fused output)
    gemm512h<<<dim3(49,1,BN),256,SMEM512H>>>(pw1h, pxh, ph1);
    gn_reduce<<<1,128>>>();
    gemm_f16<5,0><<<dim3(49,1,BN),256,SMEMF16>>>(pw2h, ph1, (float*)d_out, x, nullptr, rscale);

    (void)in_sizes; (void)n_in; (void)out_size;
}